// round 9
// baseline (speedup 1.0000x reference)
#include <cuda_runtime.h>

typedef unsigned long long u64;
typedef unsigned int u32;
typedef unsigned short u16;

#define NT 256
#define ATOMS 64

// ---------------- smem map (bytes) ----------------
#define SM_X      0          // X[3][64][194] f32, X_i stride 49664
#define X_STR     194
#define SM_INVA   0          // gate alias: [2][64][264hw]
#define INVA_SIDE 33792
#define INVA_STR  264
#define SM_RED    69632      // 49152 B gate2 reduction
#define SM_EQA    148992     // [2][64][40hw]
#define EQA_SIDE  5120
#define SM_B      159232     // up to 34816 B
#define SM_CHI    194048     // 64*66*4
#define CHI_STR   66
#define SM_CS     210944     // 128 f32
#define SM_RSS    211456     // 512 f32
#define SM_BYTES  213504

__device__ u16 d_PfT_h[192 * 256], d_PfT_l[192 * 256];
__device__ u16 d_G1T_h[512 * 256], d_G1T_l[512 * 256];
__device__ u16 d_G2T_h[64 * 512],  d_G2T_l[64 * 512];
__device__ float d_B1f[512];

// ---------------- helpers ----------------
static __device__ __forceinline__ u32 smem_u32(const void* p) {
    u32 a;
    asm("{ .reg .u64 t; cvta.to.shared.u64 t, %1; cvt.u32.u64 %0, t; }" : "=r"(a) : "l"(p));
    return a;
}
static __device__ __forceinline__ void ldsm4(u32* r, u32 addr) {
    asm volatile("ldmatrix.sync.aligned.m8n8.x4.shared.b16 {%0,%1,%2,%3}, [%4];"
        : "=r"(r[0]), "=r"(r[1]), "=r"(r[2]), "=r"(r[3]) : "r"(addr));
}
static __device__ __forceinline__ void ldsm2(u32* r, u32 addr) {
    asm volatile("ldmatrix.sync.aligned.m8n8.x2.shared.b16 {%0,%1}, [%2];"
        : "=r"(r[0]), "=r"(r[1]) : "r"(addr));
}
static __device__ __forceinline__ void mma16816(float* d, const u32* a, const u32* b) {
    asm volatile(
        "mma.sync.aligned.m16n8k16.row.col.f32.bf16.bf16.f32 "
        "{%0,%1,%2,%3},{%4,%5,%6,%7},{%8,%9},{%0,%1,%2,%3};"
        : "+f"(d[0]), "+f"(d[1]), "+f"(d[2]), "+f"(d[3])
        : "r"(a[0]), "r"(a[1]), "r"(a[2]), "r"(a[3]), "r"(b[0]), "r"(b[1]));
}
static __device__ __forceinline__ void split1(float v, u16& h, u16& l) {
    u32 hp;
    asm("cvt.rn.bf16x2.f32 %0, %1, %2;" : "=r"(hp) : "f"(0.f), "f"(v));
    float lr = v - __uint_as_float(hp << 16);
    u32 lp;
    asm("cvt.rn.bf16x2.f32 %0, %1, %2;" : "=r"(lp) : "f"(0.f), "f"(lr));
    h = (u16)hp; l = (u16)lp;
}
// pack pair (a = element k, b = element k+1) into bf16x2 hi + lo
static __device__ __forceinline__ void splitpk(float a, float b, u32& h, u32& l) {
    u32 hp;
    asm("cvt.rn.bf16x2.f32 %0, %1, %2;" : "=r"(hp) : "f"(b), "f"(a));
    float ra = a - __uint_as_float(hp << 16);
    float rb = b - __uint_as_float(hp & 0xFFFF0000u);
    asm("cvt.rn.bf16x2.f32 %0, %1, %2;" : "=r"(l) : "f"(rb), "f"(ra));
    h = hp;
}
static __device__ __forceinline__ float silu(float x) { return x / (1.f + __expf(-x)); }
static __device__ __forceinline__ float sigm(float x) { return 1.f / (1.f + __expf(-x)); }

// ---------------- prep kernels ----------------
__global__ void prep_pf(const float* __restrict__ gam, const float* __restrict__ W0,
                        const float* __restrict__ W1, const float* __restrict__ W2,
                        const float* __restrict__ wc, const float* __restrict__ wd) {
    int n = blockIdx.x, m = threadIdx.x;      // n: 0..191 (role*64+u), m: 0..255
    int role = n >> 6, u = n & 63;
    float v;
    if (role == 0) v = W0[m * 64 + u];
    else {
        const float* Wx = (role == 1) ? W1 : W2;
        const float* wx = (role == 1) ? wc : wd;
        float s = 0.f;
        #pragma unroll 8
        for (int j = 0; j < 64; j++) s += Wx[m * 64 + j] * wx[u * 64 + j];
        v = s;
    }
    v *= gam[m] * 0.0625f;
    u16 h, l; split1(v, h, l);
    d_PfT_h[n * 256 + m] = h; d_PfT_l[n * 256 + m] = l;
}
__global__ void prep_g1(const float* __restrict__ gw1, const float* __restrict__ stdv) {
    int h = blockIdx.x, v = threadIdx.x;
    u16 a, b; split1(gw1[v * 512 + h] / stdv[v], a, b);
    d_G1T_h[h * 256 + v] = a; d_G1T_l[h * 256 + v] = b;
}
__global__ void prep_g2(const float* __restrict__ gw2) {
    int k = blockIdx.x, h = threadIdx.x;
    u16 a, b; split1(gw2[h * 64 + k], a, b);
    d_G2T_h[k * 512 + h] = a; d_G2T_l[k * 512 + h] = b;
}
__global__ void prep_b1(const float* __restrict__ gw1, const float* __restrict__ gb1,
                        const float* __restrict__ mean, const float* __restrict__ stdv) {
    int h = threadIdx.x;
    float s = gb1[h];
    for (int v = 0; v < 256; v++) s -= (mean[v] / stdv[v]) * gw1[v * 512 + h];
    d_B1f[h] = s;
}

// ---------------- fused main kernel ----------------
__global__ __launch_bounds__(NT)
void chiral_tc(const float* __restrict__ emb,
               const float* __restrict__ lnw, const float* __restrict__ lnb,
               const float* __restrict__ gb2, float* __restrict__ outp) {
    extern __shared__ char smc[];
    float* smf = (float*)smc;
    const u32 sb = smem_u32(smc);
    const int tid = threadIdx.x, lane = tid & 31, w = tid >> 5;
    const int l15 = lane & 15;
    const long abase = (long)blockIdx.x * ATOMS;

    // ldmatrix lane address components
    const int arow = (lane & 7) + ((lane >> 3) & 1) * 8;   // A x4 row
    const int akq  = (lane >> 4) * 8;                      // A x4 k sub-offset
    const int brow = l15 & 7;                              // B x2 row
    const int bkq  = ((l15 >> 3) & 1) * 8;                 // B x2 k sub-offset

    const int mw = w >> 2, uw = w & 3;   // eq warp tile: rows mw*32, cols uw*48
    float rloc = 0.f;

    // ============ eq GEMM: 3 sweeps over spatial dim i ============
    for (int i = 0; i < 3; i++) {
        float acc[2][6][4];
        #pragma unroll
        for (int mt = 0; mt < 2; mt++)
            #pragma unroll
            for (int nt = 0; nt < 6; nt++)
                #pragma unroll
                for (int e = 0; e < 4; e++) acc[mt][nt][e] = 0.f;

        for (int kc = 0; kc < 8; kc++) {
            __syncthreads();
            {   // stage A_i chunk [64 atoms][32 m] hi/lo
                int a = tid >> 2, q = tid & 3;
                const float* src = emb + (abase + a) * 1024 + 256 + (kc * 32 + q * 8) * 3 + i;
                #pragma unroll
                for (int j = 0; j < 8; j++) {
                    float f = __ldg(src + j * 3);
                    rloc += f * f;
                    u16 h, l; split1(f, h, l);
                    int m = q * 8 + j;
                    *(u16*)(smc + SM_EQA + (a * 40 + m) * 2) = h;
                    *(u16*)(smc + SM_EQA + EQA_SIDE + (a * 40 + m) * 2) = l;
                }
            }
            {   // stage B chunk [192 n][32 k] hi/lo  (192*16 u32 = 3072)
                #pragma unroll
                for (int rr = 0; rr < 12; rr++) {
                    int idx = tid + rr * 256;
                    int row = idx >> 4, c = idx & 15;
                    *(u32*)(smc + SM_B + row * 80 + c * 4) =
                        *(const u32*)(d_PfT_h + row * 256 + kc * 32 + c * 2);
                    *(u32*)(smc + SM_B + 15360 + row * 80 + c * 4) =
                        *(const u32*)(d_PfT_l + row * 256 + kc * 32 + c * 2);
                }
            }
            __syncthreads();
            #pragma unroll
            for (int ks = 0; ks < 2; ks++) {
                u32 A[2][2][4];
                #pragma unroll
                for (int mt = 0; mt < 2; mt++)
                    #pragma unroll
                    for (int s = 0; s < 2; s++)
                        ldsm4(A[mt][s], sb + SM_EQA + s * EQA_SIDE +
                              2 * ((mw * 32 + mt * 16 + arow) * 40 + ks * 16 + akq));
                #pragma unroll
                for (int nt = 0; nt < 6; nt++) {
                    u32 Bh[2], Bl[2];
                    u32 boff = 2 * ((uw * 48 + nt * 8 + brow) * 40 + ks * 16 + bkq);
                    ldsm2(Bh, sb + SM_B + boff);
                    ldsm2(Bl, sb + SM_B + 15360 + boff);
                    #pragma unroll
                    for (int mt = 0; mt < 2; mt++) {
                        mma16816(acc[mt][nt], A[mt][0], Bh);
                        mma16816(acc[mt][nt], A[mt][1], Bh);
                        mma16816(acc[mt][nt], A[mt][0], Bl);
                    }
                }
            }
        }
        // stash X_i to smem (f32)
        #pragma unroll
        for (int mt = 0; mt < 2; mt++)
            #pragma unroll
            for (int nt = 0; nt < 6; nt++) {
                int r0 = mw * 32 + mt * 16 + (lane >> 2);
                int c0 = uw * 48 + nt * 8 + (lane & 3) * 2;
                float* xp = smf + i * 12416;
                xp[r0 * X_STR + c0]       = acc[mt][nt][0];
                xp[r0 * X_STR + c0 + 1]   = acc[mt][nt][1];
                xp[(r0 + 8) * X_STR + c0]     = acc[mt][nt][2];
                xp[(r0 + 8) * X_STR + c0 + 1] = acc[mt][nt][3];
            }
    }
    __syncthreads();

    // ============ rms -> cs ============
    smf[(SM_RSS >> 2) + tid] = rloc;
    __syncthreads();
    if (tid < 64) {
        const float* rp = smf + (SM_RSS >> 2);
        float s = rp[tid * 4] + rp[tid * 4 + 1] + rp[tid * 4 + 2] + rp[tid * 4 + 3];
        float qr = rsqrtf(s * (1.f / 256.f) + 1e-6f);
        smf[(SM_CS >> 2) + tid] = qr * qr * qr * rsqrtf(24576.0f);
    }
    __syncthreads();

    // ============ chi = cs * det; LN stats ============
    {
        int a = tid >> 2, ug = tid & 3;
        float cs = smf[(SM_CS >> 2) + a];
        float ps = 0.f, pq = 0.f;
        #pragma unroll 4
        for (int uu = 0; uu < 16; uu++) {
            int u = ug * 16 + uu;
            const float* X0 = smf + 0 * 12416 + a * X_STR;
            const float* X1 = smf + 1 * 12416 + a * X_STR;
            const float* X2 = smf + 2 * 12416 + a * X_STR;
            float ax = X0[u],       bx = X0[u + 64],  cx = X0[u + 128];
            float ay = X1[u],       by = X1[u + 64],  cy = X1[u + 128];
            float az = X2[u],       bz = X2[u + 64],  cz = X2[u + 128];
            float det = ax * (by * cz - bz * cy) + ay * (bz * cx - bx * cz)
                      + az * (bx * cy - by * cx);
            float chi = cs * det;
            smf[(SM_CHI >> 2) + a * CHI_STR + u] = chi;
            ps += chi; pq += chi * chi;
        }
        smf[(SM_RSS >> 2) + tid] = ps;
        smf[(SM_RSS >> 2) + 256 + tid] = pq;
    }
    __syncthreads();
    if (tid < 64) {
        const float* rp = smf + (SM_RSS >> 2);
        float s = rp[tid * 4] + rp[tid * 4 + 1] + rp[tid * 4 + 2] + rp[tid * 4 + 3];
        float q = rp[256 + tid * 4] + rp[256 + tid * 4 + 1] + rp[256 + tid * 4 + 2] + rp[256 + tid * 4 + 3];
        float mu = s * (1.f / 64.f);
        float var = fmaxf(q * (1.f / 64.f) - mu * mu, 0.f);
        smf[(SM_CS >> 2) + tid] = mu;
        smf[(SM_CS >> 2) + 64 + tid] = rsqrtf(var + 1e-5f);
    }
    __syncthreads();
    {   // apply LN in-place
        int a = tid >> 2, ug = tid & 3;
        float mu = smf[(SM_CS >> 2) + a], is = smf[(SM_CS >> 2) + 64 + a];
        #pragma unroll 4
        for (int uu = 0; uu < 16; uu++) {
            int u = ug * 16 + uu;
            float c = smf[(SM_CHI >> 2) + a * CHI_STR + u];
            smf[(SM_CHI >> 2) + a * CHI_STR + u] =
                (c - mu) * is * __ldg(lnw + u) + __ldg(lnb + u);
        }
    }
    __syncthreads();   // X region now dead -> gate may reuse

    // ============ gate phase ============
    {   // stage inv A full [64][256] hi/lo
        int a = tid >> 2, q = tid & 3;
        const float4* src = (const float4*)(emb + (abase + a) * 1024 + q * 64);
        #pragma unroll
        for (int j = 0; j < 16; j++) {
            float4 v = __ldg(src + j);
            float vv[4] = {v.x, v.y, v.z, v.w};
            #pragma unroll
            for (int e = 0; e < 4; e++) {
                int k = q * 64 + j * 4 + e;
                u16 h, l; split1(vv[e], h, l);
                *(u16*)(smc + SM_INVA + (a * INVA_STR + k) * 2) = h;
                *(u16*)(smc + SM_INVA + INVA_SIDE + (a * INVA_STR + k) * 2) = l;
            }
        }
    }
    const int gmw = w >> 2, gnw = w & 3;   // rows gmw*32, h-cols gnw*32 (per hc)
    float g2acc[2][8][4];
    #pragma unroll
    for (int mt = 0; mt < 2; mt++)
        #pragma unroll
        for (int nt = 0; nt < 8; nt++)
            #pragma unroll
            for (int e = 0; e < 4; e++) g2acc[mt][nt][e] = 0.f;

    for (int hc = 0; hc < 4; hc++) {
        float g1acc[2][4][4];
        #pragma unroll
        for (int mt = 0; mt < 2; mt++)
            #pragma unroll
            for (int nt = 0; nt < 4; nt++)
                #pragma unroll
                for (int e = 0; e < 4; e++) g1acc[mt][nt][e] = 0.f;

        for (int kc = 0; kc < 8; kc++) {
            __syncthreads();
            {   // stage B1 chunk [128 h][32 k] hi/lo (128*16 u32 = 2048)
                #pragma unroll
                for (int rr = 0; rr < 8; rr++) {
                    int idx = tid + rr * 256;
                    int row = idx >> 4, c = idx & 15;
                    *(u32*)(smc + SM_B + row * 80 + c * 4) =
                        *(const u32*)(d_G1T_h + (hc * 128 + row) * 256 + kc * 32 + c * 2);
                    *(u32*)(smc + SM_B + 10240 + row * 80 + c * 4) =
                        *(const u32*)(d_G1T_l + (hc * 128 + row) * 256 + kc * 32 + c * 2);
                }
            }
            __syncthreads();
            #pragma unroll
            for (int ks = 0; ks < 2; ks++) {
                u32 A[2][2][4];
                #pragma unroll
                for (int mt = 0; mt < 2; mt++)
                    #pragma unroll
                    for (int s = 0; s < 2; s++)
                        ldsm4(A[mt][s], sb + SM_INVA + s * INVA_SIDE +
                              2 * ((gmw * 32 + mt * 16 + arow) * INVA_STR + kc * 32 + ks * 16 + akq));
                #pragma unroll
                for (int nt = 0; nt < 4; nt++) {
                    u32 Bh[2], Bl[2];
                    u32 boff = 2 * ((gnw * 32 + nt * 8 + brow) * 40 + ks * 16 + bkq);
                    ldsm2(Bh, sb + SM_B + boff);
                    ldsm2(Bl, sb + SM_B + 10240 + boff);
                    #pragma unroll
                    for (int mt = 0; mt < 2; mt++) {
                        mma16816(g1acc[mt][nt], A[mt][0], Bh);
                        mma16816(g1acc[mt][nt], A[mt][1], Bh);
                        mma16816(g1acc[mt][nt], A[mt][0], Bl);
                    }
                }
            }
        }
        // SiLU + re-split into gate2 A fragments (in registers)
        u32 a2h[2][2][4], a2l[2][2][4];
        #pragma unroll
        for (int mt = 0; mt < 2; mt++)
            #pragma unroll
            for (int kt = 0; kt < 2; kt++)
                #pragma unroll
                for (int half = 0; half < 2; half++) {
                    int nt = kt * 2 + half;
                    int hb = hc * 128 + gnw * 32 + nt * 8 + (lane & 3) * 2;
                    float b0 = __ldg(d_B1f + hb), b1 = __ldg(d_B1f + hb + 1);
                    float s0 = silu(g1acc[mt][nt][0] + b0);
                    float s1 = silu(g1acc[mt][nt][1] + b1);
                    float s2 = silu(g1acc[mt][nt][2] + b0);
                    float s3 = silu(g1acc[mt][nt][3] + b1);
                    splitpk(s0, s1, a2h[mt][kt][half * 2], a2l[mt][kt][half * 2]);
                    splitpk(s2, s3, a2h[mt][kt][half * 2 + 1], a2l[mt][kt][half * 2 + 1]);
                }
        __syncthreads();
        {   // stage B2 [64 n][128 h-slice] hi/lo (64*64 u32 = 4096)
            #pragma unroll
            for (int rr = 0; rr < 16; rr++) {
                int idx = tid + rr * 256;
                int row = idx >> 6, c = idx & 63;
                *(u32*)(smc + SM_B + row * 272 + c * 4) =
                    *(const u32*)(d_G2T_h + row * 512 + hc * 128 + c * 2);
                *(u32*)(smc + SM_B + 17408 + row * 272 + c * 4) =
                    *(const u32*)(d_G2T_l + row * 512 + hc * 128 + c * 2);
            }
        }
        __syncthreads();
        #pragma unroll
        for (int kt = 0; kt < 2; kt++)
            #pragma unroll
            for (int nt = 0; nt < 8; nt++) {
                u32 Bh[2], Bl[2];
                u32 boff = 2 * ((nt * 8 + brow) * 136 + gnw * 32 + kt * 16 + bkq);
                ldsm2(Bh, sb + SM_B + boff);
                ldsm2(Bl, sb + SM_B + 17408 + boff);
                #pragma unroll
                for (int mt = 0; mt < 2; mt++) {
                    mma16816(g2acc[mt][nt], a2h[mt][kt], Bh);
                    mma16816(g2acc[mt][nt], a2l[mt][kt], Bh);
                    mma16816(g2acc[mt][nt], a2h[mt][kt], Bl);
                }
            }
    }
    // cross-warp reduction over gnw, then epilogue
    __syncthreads();
    if (gnw != 0) {
        float* rp = smf + (SM_RED >> 2) + (((gnw - 1) * 2 + gmw) * 32 + lane) * 64;
        #pragma unroll
        for (int mt = 0; mt < 2; mt++)
            #pragma unroll
            for (int nt = 0; nt < 8; nt++)
                #pragma unroll
                for (int e = 0; e < 4; e++)
                    rp[mt * 32 + nt * 4 + e] = g2acc[mt][nt][e];
    }
    __syncthreads();
    if (gnw == 0) {
        #pragma unroll
        for (int p = 0; p < 3; p++) {
            const float* rp = smf + (SM_RED >> 2) + ((p * 2 + gmw) * 32 + lane) * 64;
            #pragma unroll
            for (int mt = 0; mt < 2; mt++)
                #pragma unroll
                for (int nt = 0; nt < 8; nt++)
                    #pragma unroll
                    for (int e = 0; e < 4; e++)
                        g2acc[mt][nt][e] += rp[mt * 32 + nt * 4 + e];
        }
        #pragma unroll
        for (int mt = 0; mt < 2; mt++)
            #pragma unroll
            for (int nt = 0; nt < 8; nt++) {
                int r0 = gmw * 32 + mt * 16 + (lane >> 2);
                int c0 = nt * 8 + (lane & 3) * 2;
                float b0 = __ldg(gb2 + c0), b1 = __ldg(gb2 + c0 + 1);
                float g0 = sigm(g2acc[mt][nt][0] + b0);
                float g1 = sigm(g2acc[mt][nt][1] + b1);
                float n0 = smf[(SM_CHI >> 2) + r0 * CHI_STR + c0];
                float n1 = smf[(SM_CHI >> 2) + r0 * CHI_STR + c0 + 1];
                *(float2*)(outp + (abase + r0) * 64 + c0) = make_float2(g0 * n0, g1 * n1);
                int r1 = r0 + 8;
                float g2 = sigm(g2acc[mt][nt][2] + b0);
                float g3 = sigm(g2acc[mt][nt][3] + b1);
                float n2 = smf[(SM_CHI >> 2) + r1 * CHI_STR + c0];
                float n3 = smf[(SM_CHI >> 2) + r1 * CHI_STR + c0 + 1];
                *(float2*)(outp + (abase + r1) * 64 + c0) = make_float2(g2 * n2, g3 * n3);
            }
    }
}

extern "C" void kernel_launch(void* const* d_in, const int* in_sizes, int n_in,
                              void* d_out, int out_size) {
    const float* emb  = (const float*)d_in[0];
    const float* mean = (const float*)d_in[1];
    const float* stdv = (const float*)d_in[2];
    const float* gam  = (const float*)d_in[3];
    const float* W0   = (const float*)d_in[4];
    const float* W1   = (const float*)d_in[5];
    const float* W2   = (const float*)d_in[6];
    const float* wc   = (const float*)d_in[7];
    const float* wd   = (const float*)d_in[8];
    const float* lnw  = (const float*)d_in[9];
    const float* lnb  = (const float*)d_in[10];
    const float* gw1  = (const float*)d_in[11];
    const float* gb1  = (const float*)d_in[12];
    const float* gw2  = (const float*)d_in[13];
    const float* gb2  = (const float*)d_in[14];
    float* out = (float*)d_out;

    prep_pf<<<192, 256>>>(gam, W0, W1, W2, wc, wd);
    prep_g1<<<512, 256>>>(gw1, stdv);
    prep_g2<<<64, 512>>>(gw2);
    prep_b1<<<1, 512>>>(gw1, gb1, mean, stdv);

    cudaFuncSetAttribute(chiral_tc, cudaFuncAttributeMaxDynamicSharedMemorySize, SM_BYTES);
    chiral_tc<<<131072 / ATOMS, NT, SM_BYTES>>>(emb, lnw, lnb, gb2, out);
}

// round 10
// speedup vs baseline: 1.4366x; 1.4366x over previous
#include <cuda_runtime.h>

typedef unsigned long long u64;
typedef unsigned int u32;
typedef unsigned short u16;

#define NT 256
#define ATOMS 64

// ---------------- smem map (bytes) ----------------
#define SM_X      0          // X[3][64][194] f32, X_i stride 49664 B
#define X_STR     194
#define SM_EQA    148992     // [3 dims][2 sides][64][40hw u16] = 6*5120
#define SM_B      179712     // eq B: hi +0, lo +15360 (30720 total)
#define SM_CHI    148992     // alias EQA (chi phase; EQA dead)
#define CHI_STR   66
#define SM_INVA   0          // gate alias of X: [2][64][264hw]
#define INVA_SIDE 33792
#define INVA_STR  264
#define SM_RED    69632      // 49152 B gate2 reduction (late)
#define SM_B2     69632      // alias RED (B2 used before RED)
#define SM_B1     165888     // 2 bufs * 20480 (hi +0, lo +10240 each)
#define SM_CS     210432     // 128 f32
#define SM_RSS    210944     // 512 f32
#define SM_BYTES  212992

__device__ u16 d_PfT_h[192 * 256], d_PfT_l[192 * 256];
__device__ u16 d_G1T_h[512 * 256], d_G1T_l[512 * 256];
__device__ u16 d_G2T_h[64 * 512],  d_G2T_l[64 * 512];
__device__ float d_B1f[512];

// ---------------- helpers ----------------
static __device__ __forceinline__ u32 smem_u32(const void* p) {
    u32 a;
    asm("{ .reg .u64 t; cvta.to.shared.u64 t, %1; cvt.u32.u64 %0, t; }" : "=r"(a) : "l"(p));
    return a;
}
static __device__ __forceinline__ void ldsm4(u32* r, u32 addr) {
    asm volatile("ldmatrix.sync.aligned.m8n8.x4.shared.b16 {%0,%1,%2,%3}, [%4];"
        : "=r"(r[0]), "=r"(r[1]), "=r"(r[2]), "=r"(r[3]) : "r"(addr));
}
static __device__ __forceinline__ void ldsm2(u32* r, u32 addr) {
    asm volatile("ldmatrix.sync.aligned.m8n8.x2.shared.b16 {%0,%1}, [%2];"
        : "=r"(r[0]), "=r"(r[1]) : "r"(addr));
}
static __device__ __forceinline__ void mma16816(float* d, const u32* a, const u32* b) {
    asm volatile(
        "mma.sync.aligned.m16n8k16.row.col.f32.bf16.bf16.f32 "
        "{%0,%1,%2,%3},{%4,%5,%6,%7},{%8,%9},{%0,%1,%2,%3};"
        : "+f"(d[0]), "+f"(d[1]), "+f"(d[2]), "+f"(d[3])
        : "r"(a[0]), "r"(a[1]), "r"(a[2]), "r"(a[3]), "r"(b[0]), "r"(b[1]));
}
static __device__ __forceinline__ void cpa16(u32 dst, const void* src) {
    asm volatile("cp.async.cg.shared.global [%0], [%1], 16;" :: "r"(dst), "l"(src));
}
#define CP_COMMIT() asm volatile("cp.async.commit_group;")
#define CP_WAIT0()  asm volatile("cp.async.wait_group 0;")
#define CP_WAIT1()  asm volatile("cp.async.wait_group 1;")

static __device__ __forceinline__ void split1(float v, u16& h, u16& l) {
    u32 hp;
    asm("cvt.rn.bf16x2.f32 %0, %1, %2;" : "=r"(hp) : "f"(0.f), "f"(v));
    float lr = v - __uint_as_float(hp << 16);
    u32 lp;
    asm("cvt.rn.bf16x2.f32 %0, %1, %2;" : "=r"(lp) : "f"(0.f), "f"(lr));
    h = (u16)hp; l = (u16)lp;
}
static __device__ __forceinline__ void splitpk(float a, float b, u32& h, u32& l) {
    u32 hp;
    asm("cvt.rn.bf16x2.f32 %0, %1, %2;" : "=r"(hp) : "f"(b), "f"(a));
    float ra = a - __uint_as_float(hp << 16);
    float rb = b - __uint_as_float(hp & 0xFFFF0000u);
    asm("cvt.rn.bf16x2.f32 %0, %1, %2;" : "=r"(l) : "f"(rb), "f"(ra));
    h = hp;
}
static __device__ __forceinline__ float silu(float x) { return x / (1.f + __expf(-x)); }
static __device__ __forceinline__ float sigm(float x) { return 1.f / (1.f + __expf(-x)); }

// ---------------- prep kernels ----------------
__global__ void prep_pf(const float* __restrict__ gam, const float* __restrict__ W0,
                        const float* __restrict__ W1, const float* __restrict__ W2,
                        const float* __restrict__ wc, const float* __restrict__ wd) {
    int n = blockIdx.x, m = threadIdx.x;
    int role = n >> 6, u = n & 63;
    float v;
    if (role == 0) v = W0[m * 64 + u];
    else {
        const float* Wx = (role == 1) ? W1 : W2;
        const float* wx = (role == 1) ? wc : wd;
        float s = 0.f;
        #pragma unroll 8
        for (int j = 0; j < 64; j++) s += Wx[m * 64 + j] * wx[u * 64 + j];
        v = s;
    }
    v *= gam[m] * 0.0625f;
    u16 h, l; split1(v, h, l);
    d_PfT_h[n * 256 + m] = h; d_PfT_l[n * 256 + m] = l;
}
__global__ void prep_g1(const float* __restrict__ gw1, const float* __restrict__ stdv) {
    int h = blockIdx.x, v = threadIdx.x;
    u16 a, b; split1(gw1[v * 512 + h] / stdv[v], a, b);
    d_G1T_h[h * 256 + v] = a; d_G1T_l[h * 256 + v] = b;
}
__global__ void prep_g2(const float* __restrict__ gw2) {
    int k = blockIdx.x, h = threadIdx.x;
    u16 a, b; split1(gw2[h * 64 + k], a, b);
    d_G2T_h[k * 512 + h] = a; d_G2T_l[k * 512 + h] = b;
}
__global__ void prep_b1(const float* __restrict__ gw1, const float* __restrict__ gb1,
                        const float* __restrict__ mean, const float* __restrict__ stdv) {
    __shared__ float red[256];
    int h = blockIdx.x, v = threadIdx.x;
    red[v] = (mean[v] / stdv[v]) * gw1[v * 512 + h];
    __syncthreads();
    #pragma unroll
    for (int s = 128; s > 0; s >>= 1) {
        if (v < s) red[v] += red[v + s];
        __syncthreads();
    }
    if (v == 0) d_B1f[h] = gb1[h] - red[0];
}

// ---------------- fused main kernel ----------------
__global__ __launch_bounds__(NT, 1)
void chiral_tc(const float* __restrict__ emb,
               const float* __restrict__ lnw, const float* __restrict__ lnb,
               const float* __restrict__ gb2, float* __restrict__ outp) {
    extern __shared__ char smc[];
    float* smf = (float*)smc;
    const u32 sb = smem_u32(smc);
    const int tid = threadIdx.x, lane = tid & 31, w = tid >> 5;
    const int l15 = lane & 15;
    const long abase = (long)blockIdx.x * ATOMS;

    const int arow = (lane & 7) + ((lane >> 3) & 1) * 8;
    const int akq  = (lane >> 4) * 8;
    const int brow = l15 & 7;
    const int bkq  = ((l15 >> 3) & 1) * 8;

    const int mw = w >> 2, uw = w & 3;
    const int a4 = tid >> 2, q4 = tid & 3;
    float rloc = 0.f;

    // ============ eq GEMM: single K sweep, 3 spatial dims in regs ============
    float acc[3][2][6][4];
    #pragma unroll
    for (int i = 0; i < 3; i++)
        #pragma unroll
        for (int mt = 0; mt < 2; mt++)
            #pragma unroll
            for (int nt = 0; nt < 6; nt++)
                #pragma unroll
                for (int e = 0; e < 4; e++) acc[i][mt][nt][e] = 0.f;

    for (int kc = 0; kc < 8; kc++) {
        // coalesced eq loads for this k-chunk (issued before barrier)
        float4 Areg[6];
        #pragma unroll
        for (int j = 0; j < 6; j++)
            Areg[j] = __ldg((const float4*)(emb + (abase + a4) * 1024) + 64 + kc * 24 + q4 * 6 + j);
        __syncthreads();
        // eq-B tile via cp.async (overlaps the A convert below)
        #pragma unroll
        for (int rr = 0; rr < 3; rr++) {
            int idx = tid + rr * 256;
            int row = idx >> 2, ch = idx & 3;
            cpa16(sb + SM_B + row * 80 + ch * 16, d_PfT_h + row * 256 + kc * 32 + ch * 8);
            cpa16(sb + SM_B + 15360 + row * 80 + ch * 16, d_PfT_l + row * 256 + kc * 32 + ch * 8);
        }
        CP_COMMIT();
        // convert + scatter A (m,i compile-time per element)
        #pragma unroll
        for (int j = 0; j < 6; j++) {
            float vv[4] = {Areg[j].x, Areg[j].y, Areg[j].z, Areg[j].w};
            #pragma unroll
            for (int e = 0; e < 4; e++) {
                float f = vv[e];
                rloc += f * f;
                const int je = j * 4 + e;
                const int i = je % 3;
                int m = q4 * 8 + je / 3;
                u16 h, l; split1(f, h, l);
                *(u16*)(smc + SM_EQA + (i * 2 + 0) * 5120 + (a4 * 40 + m) * 2) = h;
                *(u16*)(smc + SM_EQA + (i * 2 + 1) * 5120 + (a4 * 40 + m) * 2) = l;
            }
        }
        CP_WAIT0();
        __syncthreads();
        // MMA
        #pragma unroll
        for (int ks = 0; ks < 2; ks++) {
            u32 A[3][2][2][4];
            #pragma unroll
            for (int i = 0; i < 3; i++)
                #pragma unroll
                for (int mt = 0; mt < 2; mt++)
                    #pragma unroll
                    for (int s = 0; s < 2; s++)
                        ldsm4(A[i][mt][s], sb + SM_EQA + (i * 2 + s) * 5120 +
                              2 * ((mw * 32 + mt * 16 + arow) * 40 + ks * 16 + akq));
            #pragma unroll
            for (int nt = 0; nt < 6; nt++) {
                u32 Bh[2], Bl[2];
                u32 boff = 2 * ((uw * 48 + nt * 8 + brow) * 40 + ks * 16 + bkq);
                ldsm2(Bh, sb + SM_B + boff);
                ldsm2(Bl, sb + SM_B + 15360 + boff);
                #pragma unroll
                for (int i = 0; i < 3; i++)
                    #pragma unroll
                    for (int mt = 0; mt < 2; mt++) {
                        mma16816(acc[i][mt][nt], A[i][mt][0], Bh);
                        mma16816(acc[i][mt][nt], A[i][mt][1], Bh);
                        mma16816(acc[i][mt][nt], A[i][mt][0], Bl);
                    }
            }
        }
    }
    __syncthreads();
    // stash X (f32)
    #pragma unroll
    for (int i = 0; i < 3; i++)
        #pragma unroll
        for (int mt = 0; mt < 2; mt++)
            #pragma unroll
            for (int nt = 0; nt < 6; nt++) {
                int r0 = mw * 32 + mt * 16 + (lane >> 2);
                int c0 = uw * 48 + nt * 8 + (lane & 3) * 2;
                float* xp = smf + i * 12416;
                xp[r0 * X_STR + c0]           = acc[i][mt][nt][0];
                xp[r0 * X_STR + c0 + 1]       = acc[i][mt][nt][1];
                xp[(r0 + 8) * X_STR + c0]     = acc[i][mt][nt][2];
                xp[(r0 + 8) * X_STR + c0 + 1] = acc[i][mt][nt][3];
            }
    __syncthreads();

    // ============ rms -> cs ============
    smf[(SM_RSS >> 2) + tid] = rloc;
    __syncthreads();
    if (tid < 64) {
        const float* rp = smf + (SM_RSS >> 2);
        float s = rp[tid * 4] + rp[tid * 4 + 1] + rp[tid * 4 + 2] + rp[tid * 4 + 3];
        float qr = rsqrtf(s * (1.f / 256.f) + 1e-6f);
        smf[(SM_CS >> 2) + tid] = qr * qr * qr * rsqrtf(24576.0f);
    }
    __syncthreads();

    // ============ chi = cs * det; LN stats ============
    {
        int a = tid >> 2, ug = tid & 3;
        float cs = smf[(SM_CS >> 2) + a];
        float ps = 0.f, pq = 0.f;
        #pragma unroll 4
        for (int uu = 0; uu < 16; uu++) {
            int u = ug * 16 + uu;
            const float* X0 = smf + 0 * 12416 + a * X_STR;
            const float* X1 = smf + 1 * 12416 + a * X_STR;
            const float* X2 = smf + 2 * 12416 + a * X_STR;
            float ax = X0[u],       bx = X0[u + 64],  cx = X0[u + 128];
            float ay = X1[u],       by = X1[u + 64],  cy = X1[u + 128];
            float az = X2[u],       bz = X2[u + 64],  cz = X2[u + 128];
            float det = ax * (by * cz - bz * cy) + ay * (bz * cx - bx * cz)
                      + az * (bx * cy - by * cx);
            float chi = cs * det;
            smf[(SM_CHI >> 2) + a * CHI_STR + u] = chi;
            ps += chi; pq += chi * chi;
        }
        smf[(SM_RSS >> 2) + tid] = ps;
        smf[(SM_RSS >> 2) + 256 + tid] = pq;
    }
    __syncthreads();
    if (tid < 64) {
        const float* rp = smf + (SM_RSS >> 2);
        float s = rp[tid * 4] + rp[tid * 4 + 1] + rp[tid * 4 + 2] + rp[tid * 4 + 3];
        float q = rp[256 + tid * 4] + rp[256 + tid * 4 + 1] + rp[256 + tid * 4 + 2] + rp[256 + tid * 4 + 3];
        float mu = s * (1.f / 64.f);
        float var = fmaxf(q * (1.f / 64.f) - mu * mu, 0.f);
        smf[(SM_CS >> 2) + tid] = mu;
        smf[(SM_CS >> 2) + 64 + tid] = rsqrtf(var + 1e-5f);
    }
    __syncthreads();
    {   // apply LN in-place
        int a = tid >> 2, ug = tid & 3;
        float mu = smf[(SM_CS >> 2) + a], is = smf[(SM_CS >> 2) + 64 + a];
        #pragma unroll 4
        for (int uu = 0; uu < 16; uu++) {
            int u = ug * 16 + uu;
            float c = smf[(SM_CHI >> 2) + a * CHI_STR + u];
            smf[(SM_CHI >> 2) + a * CHI_STR + u] =
                (c - mu) * is * __ldg(lnw + u) + __ldg(lnb + u);
        }
    }
    __syncthreads();

    // ============ gate phase ============
    {   // stage inv A [64][256] hi/lo
        const float4* src = (const float4*)(emb + (abase + a4) * 1024 + q4 * 64);
        #pragma unroll
        for (int j = 0; j < 16; j++) {
            float4 v = __ldg(src + j);
            float vv[4] = {v.x, v.y, v.z, v.w};
            #pragma unroll
            for (int e = 0; e < 4; e++) {
                int k = q4 * 64 + j * 4 + e;
                u16 h, l; split1(vv[e], h, l);
                *(u16*)(smc + SM_INVA + (a4 * INVA_STR + k) * 2) = h;
                *(u16*)(smc + SM_INVA + INVA_SIDE + (a4 * INVA_STR + k) * 2) = l;
            }
        }
    }
    // prologue B1 copy for (hc=0,kc=0)
    {
        u32 bb = sb + SM_B1;
        #pragma unroll
        for (int rr = 0; rr < 2; rr++) {
            int idx = tid + rr * 256;
            int row = idx >> 2, ch = idx & 3;
            cpa16(bb + row * 80 + ch * 16, d_G1T_h + row * 256 + ch * 8);
            cpa16(bb + 10240 + row * 80 + ch * 16, d_G1T_l + row * 256 + ch * 8);
        }
        CP_COMMIT();
    }
    __syncthreads();   // INVA visible

    const int gmw = w >> 2, gnw = w & 3;
    float g2acc[2][8][4];
    #pragma unroll
    for (int mt = 0; mt < 2; mt++)
        #pragma unroll
        for (int nt = 0; nt < 8; nt++)
            #pragma unroll
            for (int e = 0; e < 4; e++) g2acc[mt][nt][e] = 0.f;

    for (int hc = 0; hc < 4; hc++) {
        float g1acc[2][4][4];
        #pragma unroll
        for (int mt = 0; mt < 2; mt++)
            #pragma unroll
            for (int nt = 0; nt < 4; nt++)
                #pragma unroll
                for (int e = 0; e < 4; e++) g1acc[mt][nt][e] = 0.f;

        for (int kc = 0; kc < 8; kc++) {
            int g = hc * 8 + kc;
            __syncthreads();   // MMA(g-1) done everywhere -> other buffer free
            if (g < 31) {      // prefetch next B1 chunk
                int gn = g + 1;
                int nhc = gn >> 3, nkc = gn & 7;
                u32 bb = sb + SM_B1 + (gn & 1) * 20480;
                #pragma unroll
                for (int rr = 0; rr < 2; rr++) {
                    int idx = tid + rr * 256;
                    int row = idx >> 2, ch = idx & 3;
                    cpa16(bb + row * 80 + ch * 16,
                          d_G1T_h + (nhc * 128 + row) * 256 + nkc * 32 + ch * 8);
                    cpa16(bb + 10240 + row * 80 + ch * 16,
                          d_G1T_l + (nhc * 128 + row) * 256 + nkc * 32 + ch * 8);
                }
                CP_COMMIT();
                CP_WAIT1();
            } else {
                CP_WAIT0();
            }
            __syncthreads();   // current buffer visible to all
            u32 bb = sb + SM_B1 + (g & 1) * 20480;
            #pragma unroll
            for (int ks = 0; ks < 2; ks++) {
                u32 A[2][2][4];
                #pragma unroll
                for (int mt = 0; mt < 2; mt++)
                    #pragma unroll
                    for (int s = 0; s < 2; s++)
                        ldsm4(A[mt][s], sb + SM_INVA + s * INVA_SIDE +
                              2 * ((gmw * 32 + mt * 16 + arow) * INVA_STR + kc * 32 + ks * 16 + akq));
                #pragma unroll
                for (int nt = 0; nt < 4; nt++) {
                    u32 Bh[2], Bl[2];
                    u32 boff = 2 * ((gnw * 32 + nt * 8 + brow) * 40 + ks * 16 + bkq);
                    ldsm2(Bh, bb + boff);
                    ldsm2(Bl, bb + 10240 + boff);
                    #pragma unroll
                    for (int mt = 0; mt < 2; mt++) {
                        mma16816(g1acc[mt][nt], A[mt][0], Bh);
                        mma16816(g1acc[mt][nt], A[mt][1], Bh);
                        mma16816(g1acc[mt][nt], A[mt][0], Bl);
                    }
                }
            }
        }
        // SiLU + re-split into gate2 A fragments
        u32 a2h[2][2][4], a2l[2][2][4];
        #pragma unroll
        for (int mt = 0; mt < 2; mt++)
            #pragma unroll
            for (int kt = 0; kt < 2; kt++)
                #pragma unroll
                for (int half = 0; half < 2; half++) {
                    int nt = kt * 2 + half;
                    int hb = hc * 128 + gnw * 32 + nt * 8 + (lane & 3) * 2;
                    float b0 = __ldg(d_B1f + hb), b1 = __ldg(d_B1f + hb + 1);
                    float s0 = silu(g1acc[mt][nt][0] + b0);
                    float s1 = silu(g1acc[mt][nt][1] + b1);
                    float s2 = silu(g1acc[mt][nt][2] + b0);
                    float s3 = silu(g1acc[mt][nt][3] + b1);
                    splitpk(s0, s1, a2h[mt][kt][half * 2], a2l[mt][kt][half * 2]);
                    splitpk(s2, s3, a2h[mt][kt][half * 2 + 1], a2l[mt][kt][half * 2 + 1]);
                }
        // B2 stage (RED alias region) via cp.async
        __syncthreads();   // previous hc's gate2 MMA done with B2
        #pragma unroll
        for (int rr = 0; rr < 4; rr++) {
            int idx = tid + rr * 256;
            int row = idx >> 4, ch = idx & 15;
            cpa16(sb + SM_B2 + row * 272 + ch * 16, d_G2T_h + row * 512 + hc * 128 + ch * 8);
            cpa16(sb + SM_B2 + 17408 + row * 272 + ch * 16, d_G2T_l + row * 512 + hc * 128 + ch * 8);
        }
        CP_COMMIT();
        CP_WAIT0();
        __syncthreads();
        #pragma unroll
        for (int kt = 0; kt < 2; kt++)
            #pragma unroll
            for (int nt = 0; nt < 8; nt++) {
                u32 Bh[2], Bl[2];
                u32 boff = 2 * ((nt * 8 + brow) * 136 + gnw * 32 + kt * 16 + bkq);
                ldsm2(Bh, sb + SM_B2 + boff);
                ldsm2(Bl, sb + SM_B2 + 17408 + boff);
                #pragma unroll
                for (int mt = 0; mt < 2; mt++) {
                    mma16816(g2acc[mt][nt], a2h[mt][kt], Bh);
                    mma16816(g2acc[mt][nt], a2l[mt][kt], Bh);
                    mma16816(g2acc[mt][nt], a2h[mt][kt], Bl);
                }
            }
    }
    // cross-warp reduction over gnw, then epilogue
    __syncthreads();
    if (gnw != 0) {
        float* rp = smf + (SM_RED >> 2) + (((gnw - 1) * 2 + gmw) * 32 + lane) * 64;
        #pragma unroll
        for (int mt = 0; mt < 2; mt++)
            #pragma unroll
            for (int nt = 0; nt < 8; nt++)
                #pragma unroll
                for (int e = 0; e < 4; e++)
                    rp[mt * 32 + nt * 4 + e] = g2acc[mt][nt][e];
    }
    __syncthreads();
    if (gnw == 0) {
        #pragma unroll
        for (int p = 0; p < 3; p++) {
            const float* rp = smf + (SM_RED >> 2) + ((p * 2 + gmw) * 32 + lane) * 64;
            #pragma unroll
            for (int mt = 0; mt < 2; mt++)
                #pragma unroll
                for (int nt = 0; nt < 8; nt++)
                    #pragma unroll
                    for (int e = 0; e < 4; e++)
                        g2acc[mt][nt][e] += rp[mt * 32 + nt * 4 + e];
        }
        #pragma unroll
        for (int mt = 0; mt < 2; mt++)
            #pragma unroll
            for (int nt = 0; nt < 8; nt++) {
                int r0 = gmw * 32 + mt * 16 + (lane >> 2);
                int c0 = nt * 8 + (lane & 3) * 2;
                float b0 = __ldg(gb2 + c0), b1 = __ldg(gb2 + c0 + 1);
                float g0 = sigm(g2acc[mt][nt][0] + b0);
                float g1 = sigm(g2acc[mt][nt][1] + b1);
                float n0 = smf[(SM_CHI >> 2) + r0 * CHI_STR + c0];
                float n1 = smf[(SM_CHI >> 2) + r0 * CHI_STR + c0 + 1];
                *(float2*)(outp + (abase + r0) * 64 + c0) = make_float2(g0 * n0, g1 * n1);
                int r1 = r0 + 8;
                float g2 = sigm(g2acc[mt][nt][2] + b0);
                float g3 = sigm(g2acc[mt][nt][3] + b1);
                float n2 = smf[(SM_CHI >> 2) + r1 * CHI_STR + c0];
                float n3 = smf[(SM_CHI >> 2) + r1 * CHI_STR + c0 + 1];
                *(float2*)(outp + (abase + r1) * 64 + c0) = make_float2(g2 * n2, g3 * n3);
            }
    }
}

extern "C" void kernel_launch(void* const* d_in, const int* in_sizes, int n_in,
                              void* d_out, int out_size) {
    const float* emb  = (const float*)d_in[0];
    const float* mean = (const float*)d_in[1];
    const float* stdv = (const float*)d_in[2];
    const float* gam  = (const float*)d_in[3];
    const float* W0   = (const float*)d_in[4];
    const float* W1   = (const float*)d_in[5];
    const float* W2   = (const float*)d_in[6];
    const float* wc   = (const float*)d_in[7];
    const float* wd   = (const float*)d_in[8];
    const float* lnw  = (const float*)d_in[9];
    const float* lnb  = (const float*)d_in[10];
    const float* gw1  = (const float*)d_in[11];
    const float* gb1  = (const float*)d_in[12];
    const float* gw2  = (const float*)d_in[13];
    const float* gb2  = (const float*)d_in[14];
    float* out = (float*)d_out;

    prep_pf<<<192, 256>>>(gam, W0, W1, W2, wc, wd);
    prep_g1<<<512, 256>>>(gw1, stdv);
    prep_g2<<<64, 512>>>(gw2);
    prep_b1<<<512, 256>>>(gw1, gb1, mean, stdv);

    cudaFuncSetAttribute(chiral_tc, cudaFuncAttributeMaxDynamicSharedMemorySize, SM_BYTES);
    chiral_tc<<<131072 / ATOMS, NT, SM_BYTES>>>(emb, lnw, lnb, gb2, out);
}

// round 11
// speedup vs baseline: 1.5166x; 1.0557x over previous
#include <cuda_runtime.h>

typedef unsigned long long u64;
typedef unsigned int u32;
typedef unsigned short u16;

#define NT 256
#define ATOMS 64

// ---------------- smem map (bytes) ----------------
#define SM_EQA    0          // [3 dims][2 sides][64][40hw u16] = 6*5120 = 30720
#define SM_B      30720      // eq B: hi +0, lo +15360 (30720 total)
#define SM_INVA   0          // gate alias: [2][64][264hw]
#define INVA_SIDE 33792
#define INVA_STR  264
#define SM_B1     67584      // 2 bufs * 20480 (hi +0, lo +10240 each)
#define SM_RED    108544     // 49152 B gate2 reduction (late)
#define SM_B2     108544     // alias RED (B2 used before RED)
#define SM_CHI    157696     // 64*66*4 = 16896
#define CHI_STR   66
#define SM_CS     174592     // 128 f32
#define SM_RSS    175104     // 512 f32
#define SM_BYTES  177152

__device__ u16 d_PfT_h[192 * 256], d_PfT_l[192 * 256];
__device__ u16 d_G1T_h[512 * 256], d_G1T_l[512 * 256];
__device__ u16 d_G2T_h[64 * 512],  d_G2T_l[64 * 512];
__device__ float d_B1f[512];

// ---------------- helpers ----------------
static __device__ __forceinline__ u32 smem_u32(const void* p) {
    u32 a;
    asm("{ .reg .u64 t; cvta.to.shared.u64 t, %1; cvt.u32.u64 %0, t; }" : "=r"(a) : "l"(p));
    return a;
}
static __device__ __forceinline__ void ldsm4(u32* r, u32 addr) {
    asm volatile("ldmatrix.sync.aligned.m8n8.x4.shared.b16 {%0,%1,%2,%3}, [%4];"
        : "=r"(r[0]), "=r"(r[1]), "=r"(r[2]), "=r"(r[3]) : "r"(addr));
}
static __device__ __forceinline__ void ldsm2(u32* r, u32 addr) {
    asm volatile("ldmatrix.sync.aligned.m8n8.x2.shared.b16 {%0,%1}, [%2];"
        : "=r"(r[0]), "=r"(r[1]) : "r"(addr));
}
static __device__ __forceinline__ void mma16816(float* d, const u32* a, const u32* b) {
    asm volatile(
        "mma.sync.aligned.m16n8k16.row.col.f32.bf16.bf16.f32 "
        "{%0,%1,%2,%3},{%4,%5,%6,%7},{%8,%9},{%0,%1,%2,%3};"
        : "+f"(d[0]), "+f"(d[1]), "+f"(d[2]), "+f"(d[3])
        : "r"(a[0]), "r"(a[1]), "r"(a[2]), "r"(a[3]), "r"(b[0]), "r"(b[1]));
}
static __device__ __forceinline__ void cpa16(u32 dst, const void* src) {
    asm volatile("cp.async.cg.shared.global [%0], [%1], 16;" :: "r"(dst), "l"(src));
}
#define CP_COMMIT() asm volatile("cp.async.commit_group;")
#define CP_WAIT0()  asm volatile("cp.async.wait_group 0;")
#define CP_WAIT1()  asm volatile("cp.async.wait_group 1;")

static __device__ __forceinline__ void split1(float v, u16& h, u16& l) {
    u32 hp;
    asm("cvt.rn.bf16x2.f32 %0, %1, %2;" : "=r"(hp) : "f"(0.f), "f"(v));
    float lr = v - __uint_as_float(hp << 16);
    u32 lp;
    asm("cvt.rn.bf16x2.f32 %0, %1, %2;" : "=r"(lp) : "f"(0.f), "f"(lr));
    h = (u16)hp; l = (u16)lp;
}
static __device__ __forceinline__ void splitpk(float a, float b, u32& h, u32& l) {
    u32 hp;
    asm("cvt.rn.bf16x2.f32 %0, %1, %2;" : "=r"(hp) : "f"(b), "f"(a));
    float ra = a - __uint_as_float(hp << 16);
    float rb = b - __uint_as_float(hp & 0xFFFF0000u);
    asm("cvt.rn.bf16x2.f32 %0, %1, %2;" : "=r"(l) : "f"(rb), "f"(ra));
    h = hp;
}
static __device__ __forceinline__ float silu(float x) { return x / (1.f + __expf(-x)); }
static __device__ __forceinline__ float sigm(float x) { return 1.f / (1.f + __expf(-x)); }

// ---------------- prep kernels ----------------
__global__ void prep_pf(const float* __restrict__ gam, const float* __restrict__ W0,
                        const float* __restrict__ W1, const float* __restrict__ W2,
                        const float* __restrict__ wc, const float* __restrict__ wd) {
    int n = blockIdx.x, m = threadIdx.x;
    int role = n >> 6, u = n & 63;
    float v;
    if (role == 0) v = W0[m * 64 + u];
    else {
        const float* Wx = (role == 1) ? W1 : W2;
        const float* wx = (role == 1) ? wc : wd;
        float s = 0.f;
        #pragma unroll 8
        for (int j = 0; j < 64; j++) s += Wx[m * 64 + j] * wx[u * 64 + j];
        v = s;
    }
    v *= gam[m] * 0.0625f;
    u16 h, l; split1(v, h, l);
    d_PfT_h[n * 256 + m] = h; d_PfT_l[n * 256 + m] = l;
}
__global__ void prep_g1(const float* __restrict__ gw1, const float* __restrict__ stdv) {
    int h = blockIdx.x, v = threadIdx.x;
    u16 a, b; split1(gw1[v * 512 + h] / stdv[v], a, b);
    d_G1T_h[h * 256 + v] = a; d_G1T_l[h * 256 + v] = b;
}
__global__ void prep_g2(const float* __restrict__ gw2) {
    int k = blockIdx.x, h = threadIdx.x;
    u16 a, b; split1(gw2[h * 64 + k], a, b);
    d_G2T_h[k * 512 + h] = a; d_G2T_l[k * 512 + h] = b;
}
__global__ void prep_b1(const float* __restrict__ gw1, const float* __restrict__ gb1,
                        const float* __restrict__ mean, const float* __restrict__ stdv) {
    __shared__ float red[256];
    int h = blockIdx.x, v = threadIdx.x;
    red[v] = (mean[v] / stdv[v]) * gw1[v * 512 + h];
    __syncthreads();
    #pragma unroll
    for (int s = 128; s > 0; s >>= 1) {
        if (v < s) red[v] += red[v + s];
        __syncthreads();
    }
    if (v == 0) d_B1f[h] = gb1[h] - red[0];
}

// ---------------- fused main kernel ----------------
__global__ __launch_bounds__(NT, 1)
void chiral_tc(const float* __restrict__ emb,
               const float* __restrict__ lnw, const float* __restrict__ lnb,
               const float* __restrict__ gb2, float* __restrict__ outp) {
    extern __shared__ char smc[];
    float* smf = (float*)smc;
    const u32 sb = smem_u32(smc);
    const int tid = threadIdx.x, lane = tid & 31, w = tid >> 5;
    const int l15 = lane & 15;
    const long abase = (long)blockIdx.x * ATOMS;

    const int arow = (lane & 7) + ((lane >> 3) & 1) * 8;
    const int akq  = (lane >> 4) * 8;
    const int brow = l15 & 7;
    const int bkq  = ((l15 >> 3) & 1) * 8;

    const int mw = w >> 2, uw = w & 3;
    const int a4 = tid >> 2, q4 = tid & 3;
    float rloc = 0.f;

    // ============ eq GEMM: single K sweep, 3 spatial dims in regs ============
    // warp n-tiles: nt -> n = (nt>>1)*64 + uw*16 + (nt&1)*8  (same 16 u across 3 roles)
    float acc[3][2][6][4];
    #pragma unroll
    for (int i = 0; i < 3; i++)
        #pragma unroll
        for (int mt = 0; mt < 2; mt++)
            #pragma unroll
            for (int nt = 0; nt < 6; nt++)
                #pragma unroll
                for (int e = 0; e < 4; e++) acc[i][mt][nt][e] = 0.f;

    for (int kc = 0; kc < 8; kc++) {
        float4 Areg[6];
        #pragma unroll
        for (int j = 0; j < 6; j++)
            Areg[j] = __ldg((const float4*)(emb + (abase + a4) * 1024) + 64 + kc * 24 + q4 * 6 + j);
        __syncthreads();
        #pragma unroll
        for (int rr = 0; rr < 3; rr++) {
            int idx = tid + rr * 256;
            int row = idx >> 2, ch = idx & 3;
            cpa16(sb + SM_B + row * 80 + ch * 16, d_PfT_h + row * 256 + kc * 32 + ch * 8);
            cpa16(sb + SM_B + 15360 + row * 80 + ch * 16, d_PfT_l + row * 256 + kc * 32 + ch * 8);
        }
        CP_COMMIT();
        #pragma unroll
        for (int j = 0; j < 6; j++) {
            float vv[4] = {Areg[j].x, Areg[j].y, Areg[j].z, Areg[j].w};
            #pragma unroll
            for (int e = 0; e < 4; e++) {
                float f = vv[e];
                rloc += f * f;
                const int je = j * 4 + e;
                const int i = je % 3;
                int m = q4 * 8 + je / 3;
                u16 h, l; split1(f, h, l);
                *(u16*)(smc + SM_EQA + (i * 2 + 0) * 5120 + (a4 * 40 + m) * 2) = h;
                *(u16*)(smc + SM_EQA + (i * 2 + 1) * 5120 + (a4 * 40 + m) * 2) = l;
            }
        }
        CP_WAIT0();
        __syncthreads();
        #pragma unroll
        for (int ks = 0; ks < 2; ks++) {
            u32 A[3][2][2][4];
            #pragma unroll
            for (int i = 0; i < 3; i++)
                #pragma unroll
                for (int mt = 0; mt < 2; mt++)
                    #pragma unroll
                    for (int s = 0; s < 2; s++)
                        ldsm4(A[i][mt][s], sb + SM_EQA + (i * 2 + s) * 5120 +
                              2 * ((mw * 32 + mt * 16 + arow) * 40 + ks * 16 + akq));
            #pragma unroll
            for (int nt = 0; nt < 6; nt++) {
                u32 Bh[2], Bl[2];
                int nbase = (nt >> 1) * 64 + uw * 16 + (nt & 1) * 8;
                u32 boff = 2 * ((nbase + brow) * 40 + ks * 16 + bkq);
                ldsm2(Bh, sb + SM_B + boff);
                ldsm2(Bl, sb + SM_B + 15360 + boff);
                #pragma unroll
                for (int i = 0; i < 3; i++)
                    #pragma unroll
                    for (int mt = 0; mt < 2; mt++) {
                        mma16816(acc[i][mt][nt], A[i][mt][0], Bh);
                        mma16816(acc[i][mt][nt], A[i][mt][1], Bh);
                        mma16816(acc[i][mt][nt], A[i][mt][0], Bl);
                    }
            }
        }
    }
    __syncthreads();

    // ============ rms -> cs ============
    smf[(SM_RSS >> 2) + tid] = rloc;
    __syncthreads();
    if (tid < 64) {
        const float* rp = smf + (SM_RSS >> 2);
        float s = rp[tid * 4] + rp[tid * 4 + 1] + rp[tid * 4 + 2] + rp[tid * 4 + 3];
        float qr = rsqrtf(s * (1.f / 256.f) + 1e-6f);
        smf[(SM_CS >> 2) + tid] = qr * qr * qr * rsqrtf(24576.0f);
    }
    __syncthreads();

    // ============ det in registers -> chi to smem ============
    {
        #pragma unroll
        for (int mt = 0; mt < 2; mt++)
            #pragma unroll
            for (int eh = 0; eh < 2; eh++) {          // e>>1 : row +0 / +8
                int r = mw * 32 + mt * 16 + eh * 8 + (lane >> 2);
                float cs = smf[(SM_CS >> 2) + r];
                #pragma unroll
                for (int half = 0; half < 2; half++)
                    #pragma unroll
                    for (int el = 0; el < 2; el++) {  // e&1 : col +0 / +1
                        int e = eh * 2 + el;
                        int u = uw * 16 + half * 8 + (lane & 3) * 2 + el;
                        float ax = acc[0][mt][half][e],     bx = acc[0][mt][2 + half][e], cx = acc[0][mt][4 + half][e];
                        float ay = acc[1][mt][half][e],     by = acc[1][mt][2 + half][e], cy = acc[1][mt][4 + half][e];
                        float az = acc[2][mt][half][e],     bz = acc[2][mt][2 + half][e], cz = acc[2][mt][4 + half][e];
                        float det = ax * (by * cz - bz * cy) + ay * (bz * cx - bx * cz)
                                  + az * (bx * cy - by * cx);
                        smf[(SM_CHI >> 2) + r * CHI_STR + u] = cs * det;
                    }
            }
    }
    __syncthreads();

    // ============ LN stats ============
    {
        int a = tid >> 2, ug = tid & 3;
        float ps = 0.f, pq = 0.f;
        #pragma unroll 4
        for (int uu = 0; uu < 16; uu++) {
            float c = smf[(SM_CHI >> 2) + a * CHI_STR + ug * 16 + uu];
            ps += c; pq += c * c;
        }
        smf[(SM_RSS >> 2) + tid] = ps;
        smf[(SM_RSS >> 2) + 256 + tid] = pq;
    }
    __syncthreads();
    if (tid < 64) {
        const float* rp = smf + (SM_RSS >> 2);
        float s = rp[tid * 4] + rp[tid * 4 + 1] + rp[tid * 4 + 2] + rp[tid * 4 + 3];
        float q = rp[256 + tid * 4] + rp[256 + tid * 4 + 1] + rp[256 + tid * 4 + 2] + rp[256 + tid * 4 + 3];
        float mu = s * (1.f / 64.f);
        float var = fmaxf(q * (1.f / 64.f) - mu * mu, 0.f);
        smf[(SM_CS >> 2) + tid] = mu;
        smf[(SM_CS >> 2) + 64 + tid] = rsqrtf(var + 1e-5f);
    }
    __syncthreads();
    {   // apply LN in-place
        int a = tid >> 2, ug = tid & 3;
        float mu = smf[(SM_CS >> 2) + a], is = smf[(SM_CS >> 2) + 64 + a];
        #pragma unroll 4
        for (int uu = 0; uu < 16; uu++) {
            int u = ug * 16 + uu;
            float c = smf[(SM_CHI >> 2) + a * CHI_STR + u];
            smf[(SM_CHI >> 2) + a * CHI_STR + u] =
                (c - mu) * is * __ldg(lnw + u) + __ldg(lnb + u);
        }
    }
    __syncthreads();

    // ============ gate phase ============
    {   // stage inv A [64][256] hi/lo
        const float4* src = (const float4*)(emb + (abase + a4) * 1024 + q4 * 64);
        #pragma unroll
        for (int j = 0; j < 16; j++) {
            float4 v = __ldg(src + j);
            float vv[4] = {v.x, v.y, v.z, v.w};
            #pragma unroll
            for (int e = 0; e < 4; e++) {
                int k = q4 * 64 + j * 4 + e;
                u16 h, l; split1(vv[e], h, l);
                *(u16*)(smc + SM_INVA + (a4 * INVA_STR + k) * 2) = h;
                *(u16*)(smc + SM_INVA + INVA_SIDE + (a4 * INVA_STR + k) * 2) = l;
            }
        }
    }
    // prologue B1 copy for (hc=0,kc=0)
    {
        u32 bb = sb + SM_B1;
        #pragma unroll
        for (int rr = 0; rr < 2; rr++) {
            int idx = tid + rr * 256;
            int row = idx >> 2, ch = idx & 3;
            cpa16(bb + row * 80 + ch * 16, d_G1T_h + row * 256 + ch * 8);
            cpa16(bb + 10240 + row * 80 + ch * 16, d_G1T_l + row * 256 + ch * 8);
        }
        CP_COMMIT();
    }
    __syncthreads();

    const int gmw = w >> 2, gnw = w & 3;
    float g2acc[2][8][4];
    #pragma unroll
    for (int mt = 0; mt < 2; mt++)
        #pragma unroll
        for (int nt = 0; nt < 8; nt++)
            #pragma unroll
            for (int e = 0; e < 4; e++) g2acc[mt][nt][e] = 0.f;

    for (int hc = 0; hc < 4; hc++) {
        float g1acc[2][4][4];
        #pragma unroll
        for (int mt = 0; mt < 2; mt++)
            #pragma unroll
            for (int nt = 0; nt < 4; nt++)
                #pragma unroll
                for (int e = 0; e < 4; e++) g1acc[mt][nt][e] = 0.f;

        for (int kc = 0; kc < 8; kc++) {
            int g = hc * 8 + kc;
            __syncthreads();
            if (g < 31) {
                int gn = g + 1;
                int nhc = gn >> 3, nkc = gn & 7;
                u32 bb = sb + SM_B1 + (gn & 1) * 20480;
                #pragma unroll
                for (int rr = 0; rr < 2; rr++) {
                    int idx = tid + rr * 256;
                    int row = idx >> 2, ch = idx & 3;
                    cpa16(bb + row * 80 + ch * 16,
                          d_G1T_h + (nhc * 128 + row) * 256 + nkc * 32 + ch * 8);
                    cpa16(bb + 10240 + row * 80 + ch * 16,
                          d_G1T_l + (nhc * 128 + row) * 256 + nkc * 32 + ch * 8);
                }
                CP_COMMIT();
                CP_WAIT1();
            } else {
                CP_WAIT0();
            }
            __syncthreads();
            u32 bb = sb + SM_B1 + (g & 1) * 20480;
            #pragma unroll
            for (int ks = 0; ks < 2; ks++) {
                u32 A[2][2][4];
                #pragma unroll
                for (int mt = 0; mt < 2; mt++)
                    #pragma unroll
                    for (int s = 0; s < 2; s++)
                        ldsm4(A[mt][s], sb + SM_INVA + s * INVA_SIDE +
                              2 * ((gmw * 32 + mt * 16 + arow) * INVA_STR + kc * 32 + ks * 16 + akq));
                #pragma unroll
                for (int nt = 0; nt < 4; nt++) {
                    u32 Bh[2], Bl[2];
                    u32 boff = 2 * ((gnw * 32 + nt * 8 + brow) * 40 + ks * 16 + bkq);
                    ldsm2(Bh, bb + boff);
                    ldsm2(Bl, bb + 10240 + boff);
                    #pragma unroll
                    for (int mt = 0; mt < 2; mt++) {
                        mma16816(g1acc[mt][nt], A[mt][0], Bh);
                        mma16816(g1acc[mt][nt], A[mt][1], Bh);
                        mma16816(g1acc[mt][nt], A[mt][0], Bl);
                    }
                }
            }
        }
        // SiLU + re-split into gate2 A fragments
        u32 a2h[2][2][4], a2l[2][2][4];
        #pragma unroll
        for (int mt = 0; mt < 2; mt++)
            #pragma unroll
            for (int kt = 0; kt < 2; kt++)
                #pragma unroll
                for (int half = 0; half < 2; half++) {
                    int nt = kt * 2 + half;
                    int hb = hc * 128 + gnw * 32 + nt * 8 + (lane & 3) * 2;
                    float b0 = __ldg(d_B1f + hb), b1 = __ldg(d_B1f + hb + 1);
                    float s0 = silu(g1acc[mt][nt][0] + b0);
                    float s1 = silu(g1acc[mt][nt][1] + b1);
                    float s2 = silu(g1acc[mt][nt][2] + b0);
                    float s3 = silu(g1acc[mt][nt][3] + b1);
                    splitpk(s0, s1, a2h[mt][kt][half * 2], a2l[mt][kt][half * 2]);
                    splitpk(s2, s3, a2h[mt][kt][half * 2 + 1], a2l[mt][kt][half * 2 + 1]);
                }
        __syncthreads();
        #pragma unroll
        for (int rr = 0; rr < 4; rr++) {
            int idx = tid + rr * 256;
            int row = idx >> 4, ch = idx & 15;
            cpa16(sb + SM_B2 + row * 272 + ch * 16, d_G2T_h + row * 512 + hc * 128 + ch * 8);
            cpa16(sb + SM_B2 + 17408 + row * 272 + ch * 16, d_G2T_l + row * 512 + hc * 128 + ch * 8);
        }
        CP_COMMIT();
        CP_WAIT0();
        __syncthreads();
        #pragma unroll
        for (int kt = 0; kt < 2; kt++)
            #pragma unroll
            for (int nt = 0; nt < 8; nt++) {
                u32 Bh[2], Bl[2];
                u32 boff = 2 * ((nt * 8 + brow) * 136 + gnw * 32 + kt * 16 + bkq);
                ldsm2(Bh, sb + SM_B2 + boff);
                ldsm2(Bl, sb + SM_B2 + 17408 + boff);
                #pragma unroll
                for (int mt = 0; mt < 2; mt++) {
                    mma16816(g2acc[mt][nt], a2h[mt][kt], Bh);
                    mma16816(g2acc[mt][nt], a2l[mt][kt], Bh);
                    mma16816(g2acc[mt][nt], a2h[mt][kt], Bl);
                }
            }
    }
    // cross-warp reduction over gnw, then epilogue
    __syncthreads();
    if (gnw != 0) {
        float* rp = smf + (SM_RED >> 2) + (((gnw - 1) * 2 + gmw) * 32 + lane) * 64;
        #pragma unroll
        for (int mt = 0; mt < 2; mt++)
            #pragma unroll
            for (int nt = 0; nt < 8; nt++)
                #pragma unroll
                for (int e = 0; e < 4; e++)
                    rp[mt * 32 + nt * 4 + e] = g2acc[mt][nt][e];
    }
    __syncthreads();
    if (gnw == 0) {
        #pragma unroll
        for (int p = 0; p < 3; p++) {
            const float* rp = smf + (SM_RED >> 2) + ((p * 2 + gmw) * 32 + lane) * 64;
            #pragma unroll
            for (int mt = 0; mt < 2; mt++)
                #pragma unroll
                for (int nt = 0; nt < 8; nt++)
                    #pragma unroll
                    for (int e = 0; e < 4; e++)
                        g2acc[mt][nt][e] += rp[mt * 32 + nt * 4 + e];
        }
        #pragma unroll
        for (int mt = 0; mt < 2; mt++)
            #pragma unroll
            for (int nt = 0; nt < 8; nt++) {
                int r0 = gmw * 32 + mt * 16 + (lane >> 2);
                int c0 = nt * 8 + (lane & 3) * 2;
                float b0 = __ldg(gb2 + c0), b1 = __ldg(gb2 + c0 + 1);
                float g0 = sigm(g2acc[mt][nt][0] + b0);
                float g1 = sigm(g2acc[mt][nt][1] + b1);
                float n0 = smf[(SM_CHI >> 2) + r0 * CHI_STR + c0];
                float n1 = smf[(SM_CHI >> 2) + r0 * CHI_STR + c0 + 1];
                *(float2*)(outp + (abase + r0) * 64 + c0) = make_float2(g0 * n0, g1 * n1);
                int r1 = r0 + 8;
                float g2 = sigm(g2acc[mt][nt][2] + b0);
                float g3 = sigm(g2acc[mt][nt][3] + b1);
                float n2 = smf[(SM_CHI >> 2) + r1 * CHI_STR + c0];
                float n3 = smf[(SM_CHI >> 2) + r1 * CHI_STR + c0 + 1];
                *(float2*)(outp + (abase + r1) * 64 + c0) = make_float2(g2 * n2, g3 * n3);
            }
    }
}

extern "C" void kernel_launch(void* const* d_in, const int* in_sizes, int n_in,
                              void* d_out, int out_size) {
    const float* emb  = (const float*)d_in[0];
    const float* mean = (const float*)d_in[1];
    const float* stdv = (const float*)d_in[2];
    const float* gam  = (const float*)d_in[3];
    const float* W0   = (const float*)d_in[4];
    const float* W1   = (const float*)d_in[5];
    const float* W2   = (const float*)d_in[6];
    const float* wc   = (const float*)d_in[7];
    const float* wd   = (const float*)d_in[8];
    const float* lnw  = (const float*)d_in[9];
    const float* lnb  = (const float*)d_in[10];
    const float* gw1  = (const float*)d_in[11];
    const float* gb1  = (const float*)d_in[12];
    const float* gw2  = (const float*)d_in[13];
    const float* gb2  = (const float*)d_in[14];
    float* out = (float*)d_out;

    prep_pf<<<192, 256>>>(gam, W0, W1, W2, wc, wd);
    prep_g1<<<512, 256>>>(gw1, stdv);
    prep_g2<<<64, 512>>>(gw2);
    prep_b1<<<512, 256>>>(gw1, gb1, mean, stdv);

    cudaFuncSetAttribute(chiral_tc, cudaFuncAttributeMaxDynamicSharedMemorySize, SM_BYTES);
    chiral_tc<<<131072 / ATOMS, NT, SM_BYTES>>>(emb, lnw, lnb, gb2, out);
}

// round 12
// speedup vs baseline: 1.5753x; 1.0387x over previous
#include <cuda_runtime.h>

typedef unsigned long long u64;
typedef unsigned int u32;
typedef unsigned short u16;

#define NT 256
#define ATOMS 64

// ---------------- smem map (bytes) ----------------
#define SM_EQA    0          // [3 dims][2 sides][64][40hw u16] = 6*5120 = 30720
#define SM_B      30720      // eq B: hi +0, lo +15360 (30720 total)
#define SM_INVA   0          // gate alias: [2][64][264hw]
#define INVA_SIDE 33792
#define INVA_STR  264
#define SM_B1     67584      // 2 bufs * 20480 (hi +0, lo +10240 each)
#define SM_RED    108544     // 49152 B gate2 reduction (late)
#define SM_B2     108544     // alias RED (B2 used before RED)
#define SM_CHI    157696     // 64*66*4 = 16896
#define CHI_STR   66
#define SM_CS     174592     // 128 f32
#define SM_RSS    175104     // 512 f32
#define SM_BYTES  177152

__device__ u16 d_PfT_h[192 * 256], d_PfT_l[192 * 256];
__device__ u16 d_G1T_h[512 * 256], d_G1T_l[512 * 256];
__device__ u16 d_G2T_h[64 * 512],  d_G2T_l[64 * 512];
__device__ float d_B1f[512];

// ---------------- helpers ----------------
static __device__ __forceinline__ u32 smem_u32(const void* p) {
    u32 a;
    asm("{ .reg .u64 t; cvta.to.shared.u64 t, %1; cvt.u32.u64 %0, t; }" : "=r"(a) : "l"(p));
    return a;
}
static __device__ __forceinline__ void ldsm4(u32* r, u32 addr) {
    asm volatile("ldmatrix.sync.aligned.m8n8.x4.shared.b16 {%0,%1,%2,%3}, [%4];"
        : "=r"(r[0]), "=r"(r[1]), "=r"(r[2]), "=r"(r[3]) : "r"(addr));
}
static __device__ __forceinline__ void ldsm2(u32* r, u32 addr) {
    asm volatile("ldmatrix.sync.aligned.m8n8.x2.shared.b16 {%0,%1}, [%2];"
        : "=r"(r[0]), "=r"(r[1]) : "r"(addr));
}
static __device__ __forceinline__ void mma16816(float* d, const u32* a, const u32* b) {
    asm volatile(
        "mma.sync.aligned.m16n8k16.row.col.f32.bf16.bf16.f32 "
        "{%0,%1,%2,%3},{%4,%5,%6,%7},{%8,%9},{%0,%1,%2,%3};"
        : "+f"(d[0]), "+f"(d[1]), "+f"(d[2]), "+f"(d[3])
        : "r"(a[0]), "r"(a[1]), "r"(a[2]), "r"(a[3]), "r"(b[0]), "r"(b[1]));
}
static __device__ __forceinline__ void cpa16(u32 dst, const void* src) {
    asm volatile("cp.async.cg.shared.global [%0], [%1], 16;" :: "r"(dst), "l"(src));
}
#define CP_COMMIT() asm volatile("cp.async.commit_group;")
#define CP_WAIT0()  asm volatile("cp.async.wait_group 0;")

static __device__ __forceinline__ void split1(float v, u16& h, u16& l) {
    u32 hp;
    asm("cvt.rn.bf16x2.f32 %0, %1, %2;" : "=r"(hp) : "f"(0.f), "f"(v));
    float lr = v - __uint_as_float(hp << 16);
    u32 lp;
    asm("cvt.rn.bf16x2.f32 %0, %1, %2;" : "=r"(lp) : "f"(0.f), "f"(lr));
    h = (u16)hp; l = (u16)lp;
}
static __device__ __forceinline__ void splitpk(float a, float b, u32& h, u32& l) {
    u32 hp;
    asm("cvt.rn.bf16x2.f32 %0, %1, %2;" : "=r"(hp) : "f"(b), "f"(a));
    float ra = a - __uint_as_float(hp << 16);
    float rb = b - __uint_as_float(hp & 0xFFFF0000u);
    asm("cvt.rn.bf16x2.f32 %0, %1, %2;" : "=r"(l) : "f"(rb), "f"(ra));
    h = hp;
}
static __device__ __forceinline__ float silu(float x) { return x / (1.f + __expf(-x)); }
static __device__ __forceinline__ float sigm(float x) { return 1.f / (1.f + __expf(-x)); }

// ---------------- prep kernels ----------------
__global__ void prep_pf(const float* __restrict__ gam, const float* __restrict__ W0,
                        const float* __restrict__ W1, const float* __restrict__ W2,
                        const float* __restrict__ wc, const float* __restrict__ wd) {
    int n = blockIdx.x, m = threadIdx.x;
    int role = n >> 6, u = n & 63;
    float v;
    if (role == 0) v = W0[m * 64 + u];
    else {
        const float* Wx = (role == 1) ? W1 : W2;
        const float* wx = (role == 1) ? wc : wd;
        float s = 0.f;
        #pragma unroll 8
        for (int j = 0; j < 64; j++) s += Wx[m * 64 + j] * wx[u * 64 + j];
        v = s;
    }
    v *= gam[m] * 0.0625f;
    u16 h, l; split1(v, h, l);
    d_PfT_h[n * 256 + m] = h; d_PfT_l[n * 256 + m] = l;
}
__global__ void prep_g1(const float* __restrict__ gw1, const float* __restrict__ stdv) {
    int h = blockIdx.x, v = threadIdx.x;
    u16 a, b; split1(gw1[v * 512 + h] / stdv[v], a, b);
    d_G1T_h[h * 256 + v] = a; d_G1T_l[h * 256 + v] = b;
}
__global__ void prep_g2(const float* __restrict__ gw2) {
    int k = blockIdx.x, h = threadIdx.x;
    u16 a, b; split1(gw2[h * 64 + k], a, b);
    d_G2T_h[k * 512 + h] = a; d_G2T_l[k * 512 + h] = b;
}
__global__ void prep_b1(const float* __restrict__ gw1, const float* __restrict__ gb1,
                        const float* __restrict__ mean, const float* __restrict__ stdv) {
    __shared__ float red[256];
    int h = blockIdx.x, v = threadIdx.x;
    red[v] = (mean[v] / stdv[v]) * gw1[v * 512 + h];
    __syncthreads();
    #pragma unroll
    for (int s = 128; s > 0; s >>= 1) {
        if (v < s) red[v] += red[v + s];
        __syncthreads();
    }
    if (v == 0) d_B1f[h] = gb1[h] - red[0];
}

// ---------------- fused main kernel ----------------
__global__ __launch_bounds__(NT, 1)
void chiral_tc(const float* __restrict__ emb,
               const float* __restrict__ lnw, const float* __restrict__ lnb,
               const float* __restrict__ gb2, float* __restrict__ outp) {
    extern __shared__ char smc[];
    float* smf = (float*)smc;
    const u32 sb = smem_u32(smc);
    const int tid = threadIdx.x, lane = tid & 31, w = tid >> 5;
    const int l15 = lane & 15;
    const long abase = (long)blockIdx.x * ATOMS;

    const int arow = (lane & 7) + ((lane >> 3) & 1) * 8;
    const int akq  = (lane >> 4) * 8;
    const int brow = l15 & 7;
    const int bkq  = ((l15 >> 3) & 1) * 8;

    const int mw = w >> 2, uw = w & 3;
    const int a4 = tid >> 2, q4 = tid & 3;
    float rloc = 0.f;

    // ============ eq GEMM: single K sweep, 3 spatial dims in regs ============
    float acc[3][2][6][4];
    #pragma unroll
    for (int i = 0; i < 3; i++)
        #pragma unroll
        for (int mt = 0; mt < 2; mt++)
            #pragma unroll
            for (int nt = 0; nt < 6; nt++)
                #pragma unroll
                for (int e = 0; e < 4; e++) acc[i][mt][nt][e] = 0.f;

    for (int kc = 0; kc < 8; kc++) {
        float4 Areg[6];
        #pragma unroll
        for (int j = 0; j < 6; j++)
            Areg[j] = __ldg((const float4*)(emb + (abase + a4) * 1024) + 64 + kc * 24 + q4 * 6 + j);
        __syncthreads();
        #pragma unroll
        for (int rr = 0; rr < 3; rr++) {
            int idx = tid + rr * 256;
            int row = idx >> 2, ch = idx & 3;
            cpa16(sb + SM_B + row * 80 + ch * 16, d_PfT_h + row * 256 + kc * 32 + ch * 8);
            cpa16(sb + SM_B + 15360 + row * 80 + ch * 16, d_PfT_l + row * 256 + kc * 32 + ch * 8);
        }
        CP_COMMIT();
        #pragma unroll
        for (int j = 0; j < 6; j++) {
            float vv[4] = {Areg[j].x, Areg[j].y, Areg[j].z, Areg[j].w};
            #pragma unroll
            for (int e = 0; e < 4; e++) {
                float f = vv[e];
                rloc += f * f;
                const int je = j * 4 + e;
                const int i = je % 3;
                int m = q4 * 8 + je / 3;
                u16 h, l; split1(f, h, l);
                *(u16*)(smc + SM_EQA + (i * 2 + 0) * 5120 + (a4 * 40 + m) * 2) = h;
                *(u16*)(smc + SM_EQA + (i * 2 + 1) * 5120 + (a4 * 40 + m) * 2) = l;
            }
        }
        CP_WAIT0();
        __syncthreads();
        #pragma unroll
        for (int ks = 0; ks < 2; ks++) {
            u32 A[3][2][2][4];
            #pragma unroll
            for (int i = 0; i < 3; i++)
                #pragma unroll
                for (int mt = 0; mt < 2; mt++)
                    #pragma unroll
                    for (int s = 0; s < 2; s++)
                        ldsm4(A[i][mt][s], sb + SM_EQA + (i * 2 + s) * 5120 +
                              2 * ((mw * 32 + mt * 16 + arow) * 40 + ks * 16 + akq));
            #pragma unroll
            for (int nt = 0; nt < 6; nt++) {
                u32 Bh[2], Bl[2];
                int nbase = (nt >> 1) * 64 + uw * 16 + (nt & 1) * 8;
                u32 boff = 2 * ((nbase + brow) * 40 + ks * 16 + bkq);
                ldsm2(Bh, sb + SM_B + boff);
                ldsm2(Bl, sb + SM_B + 15360 + boff);
                #pragma unroll
                for (int i = 0; i < 3; i++)
                    #pragma unroll
                    for (int mt = 0; mt < 2; mt++) {
                        mma16816(acc[i][mt][nt], A[i][mt][0], Bh);
                        mma16816(acc[i][mt][nt], A[i][mt][1], Bh);
                        mma16816(acc[i][mt][nt], A[i][mt][0], Bl);
                    }
            }
        }
    }
    __syncthreads();

    // ============ rms -> cs ============
    smf[(SM_RSS >> 2) + tid] = rloc;
    __syncthreads();
    if (tid < 64) {
        const float* rp = smf + (SM_RSS >> 2);
        float s = rp[tid * 4] + rp[tid * 4 + 1] + rp[tid * 4 + 2] + rp[tid * 4 + 3];
        float qr = rsqrtf(s * (1.f / 256.f) + 1e-6f);
        smf[(SM_CS >> 2) + tid] = qr * qr * qr * rsqrtf(24576.0f);
    }
    __syncthreads();

    // ============ det in registers -> raw chi to smem ============
    {
        #pragma unroll
        for (int mt = 0; mt < 2; mt++)
            #pragma unroll
            for (int eh = 0; eh < 2; eh++) {
                int r = mw * 32 + mt * 16 + eh * 8 + (lane >> 2);
                float cs = smf[(SM_CS >> 2) + r];
                #pragma unroll
                for (int half = 0; half < 2; half++)
                    #pragma unroll
                    for (int el = 0; el < 2; el++) {
                        int e = eh * 2 + el;
                        int u = uw * 16 + half * 8 + (lane & 3) * 2 + el;
                        float ax = acc[0][mt][half][e],     bx = acc[0][mt][2 + half][e], cx = acc[0][mt][4 + half][e];
                        float ay = acc[1][mt][half][e],     by = acc[1][mt][2 + half][e], cy = acc[1][mt][4 + half][e];
                        float az = acc[2][mt][half][e],     bz = acc[2][mt][2 + half][e], cz = acc[2][mt][4 + half][e];
                        float det = ax * (by * cz - bz * cy) + ay * (bz * cx - bx * cz)
                                  + az * (bx * cy - by * cx);
                        smf[(SM_CHI >> 2) + r * CHI_STR + u] = cs * det;
                    }
            }
    }
    __syncthreads();

    // ============ LN stats (mu, inv-sigma only; apply deferred to epilogue) ============
    {
        int a = tid >> 2, ug = tid & 3;
        float ps = 0.f, pq = 0.f;
        #pragma unroll 4
        for (int uu = 0; uu < 16; uu++) {
            float c = smf[(SM_CHI >> 2) + a * CHI_STR + ug * 16 + uu];
            ps += c; pq += c * c;
        }
        smf[(SM_RSS >> 2) + tid] = ps;
        smf[(SM_RSS >> 2) + 256 + tid] = pq;
    }
    __syncthreads();
    if (tid < 64) {
        const float* rp = smf + (SM_RSS >> 2);
        float s = rp[tid * 4] + rp[tid * 4 + 1] + rp[tid * 4 + 2] + rp[tid * 4 + 3];
        float q = rp[256 + tid * 4] + rp[256 + tid * 4 + 1] + rp[256 + tid * 4 + 2] + rp[256 + tid * 4 + 3];
        float mu = s * (1.f / 64.f);
        float var = fmaxf(q * (1.f / 64.f) - mu * mu, 0.f);
        smf[(SM_CS >> 2) + tid] = mu;
        smf[(SM_CS >> 2) + 64 + tid] = rsqrtf(var + 1e-5f);
    }

    // ============ gate phase ============
    {   // stage inv A [64][256] hi/lo (disjoint from CS/RSS; no barrier needed first)
        const float4* src = (const float4*)(emb + (abase + a4) * 1024 + q4 * 64);
        #pragma unroll
        for (int j = 0; j < 16; j++) {
            float4 v = __ldg(src + j);
            float vv[4] = {v.x, v.y, v.z, v.w};
            #pragma unroll
            for (int e = 0; e < 4; e++) {
                int k = q4 * 64 + j * 4 + e;
                u16 h, l; split1(vv[e], h, l);
                *(u16*)(smc + SM_INVA + (a4 * INVA_STR + k) * 2) = h;
                *(u16*)(smc + SM_INVA + INVA_SIDE + (a4 * INVA_STR + k) * 2) = l;
            }
        }
    }
    // prologue B1 copy for (hc=0,kc=0)
    {
        u32 bb = sb + SM_B1;
        #pragma unroll
        for (int rr = 0; rr < 2; rr++) {
            int idx = tid + rr * 256;
            int row = idx >> 2, ch = idx & 3;
            cpa16(bb + row * 80 + ch * 16, d_G1T_h + row * 256 + ch * 8);
            cpa16(bb + 10240 + row * 80 + ch * 16, d_G1T_l + row * 256 + ch * 8);
        }
        CP_COMMIT();
    }

    const int gmw = w >> 2, gnw = w & 3;
    float g2acc[2][8][4];
    #pragma unroll
    for (int mt = 0; mt < 2; mt++)
        #pragma unroll
        for (int nt = 0; nt < 8; nt++)
            #pragma unroll
            for (int e = 0; e < 4; e++) g2acc[mt][nt][e] = 0.f;

    for (int hc = 0; hc < 4; hc++) {
        float g1acc[2][4][4];
        #pragma unroll
        for (int mt = 0; mt < 2; mt++)
            #pragma unroll
            for (int nt = 0; nt < 4; nt++)
                #pragma unroll
                for (int e = 0; e < 4; e++) g1acc[mt][nt][e] = 0.f;

        for (int kc = 0; kc < 8; kc++) {
            int g = hc * 8 + kc;
            CP_WAIT0();        // B1(g) complete (committed previously)
            __syncthreads();   // visibility of buf g; all readers of buf (g+1)&1 done
            bool did = false;
            if (g < 31) {      // prefetch next B1 chunk into the now-free buffer
                int gn = g + 1;
                int nhc = gn >> 3, nkc = gn & 7;
                u32 bb = sb + SM_B1 + (gn & 1) * 20480;
                #pragma unroll
                for (int rr = 0; rr < 2; rr++) {
                    int idx = tid + rr * 256;
                    int row = idx >> 2, ch = idx & 3;
                    cpa16(bb + row * 80 + ch * 16,
                          d_G1T_h + (nhc * 128 + row) * 256 + nkc * 32 + ch * 8);
                    cpa16(bb + 10240 + row * 80 + ch * 16,
                          d_G1T_l + (nhc * 128 + row) * 256 + nkc * 32 + ch * 8);
                }
                did = true;
            }
            if (kc == 7) {     // prefetch B2(hc): all warps past gate2(hc-1) here
                #pragma unroll
                for (int rr = 0; rr < 4; rr++) {
                    int idx = tid + rr * 256;
                    int row = idx >> 4, ch = idx & 15;
                    cpa16(sb + SM_B2 + row * 272 + ch * 16,
                          d_G2T_h + row * 512 + hc * 128 + ch * 8);
                    cpa16(sb + SM_B2 + 17408 + row * 272 + ch * 16,
                          d_G2T_l + row * 512 + hc * 128 + ch * 8);
                }
                did = true;
            }
            if (did) CP_COMMIT();
            u32 bb = sb + SM_B1 + (g & 1) * 20480;
            #pragma unroll
            for (int ks = 0; ks < 2; ks++) {
                u32 A[2][2][4];
                #pragma unroll
                for (int mt = 0; mt < 2; mt++)
                    #pragma unroll
                    for (int s = 0; s < 2; s++)
                        ldsm4(A[mt][s], sb + SM_INVA + s * INVA_SIDE +
                              2 * ((gmw * 32 + mt * 16 + arow) * INVA_STR + kc * 32 + ks * 16 + akq));
                #pragma unroll
                for (int nt = 0; nt < 4; nt++) {
                    u32 Bh[2], Bl[2];
                    u32 boff = 2 * ((gnw * 32 + nt * 8 + brow) * 40 + ks * 16 + bkq);
                    ldsm2(Bh, bb + boff);
                    ldsm2(Bl, bb + 10240 + boff);
                    #pragma unroll
                    for (int mt = 0; mt < 2; mt++) {
                        mma16816(g1acc[mt][nt], A[mt][0], Bh);
                        mma16816(g1acc[mt][nt], A[mt][1], Bh);
                        mma16816(g1acc[mt][nt], A[mt][0], Bl);
                    }
                }
            }
        }
        // SiLU + re-split into gate2 A fragments (covers B2 copy latency)
        u32 a2h[2][2][4], a2l[2][2][4];
        #pragma unroll
        for (int mt = 0; mt < 2; mt++)
            #pragma unroll
            for (int kt = 0; kt < 2; kt++)
                #pragma unroll
                for (int half = 0; half < 2; half++) {
                    int nt = kt * 2 + half;
                    int hb = hc * 128 + gnw * 32 + nt * 8 + (lane & 3) * 2;
                    float b0 = __ldg(d_B1f + hb), b1 = __ldg(d_B1f + hb + 1);
                    float s0 = silu(g1acc[mt][nt][0] + b0);
                    float s1 = silu(g1acc[mt][nt][1] + b1);
                    float s2 = silu(g1acc[mt][nt][2] + b0);
                    float s3 = silu(g1acc[mt][nt][3] + b1);
                    splitpk(s0, s1, a2h[mt][kt][half * 2], a2l[mt][kt][half * 2]);
                    splitpk(s2, s3, a2h[mt][kt][half * 2 + 1], a2l[mt][kt][half * 2 + 1]);
                }
        CP_WAIT0();        // B2(hc) (and any in-flight B1) complete
        __syncthreads();   // B2 visible to all warps
        #pragma unroll
        for (int kt = 0; kt < 2; kt++)
            #pragma unroll
            for (int nt = 0; nt < 8; nt++) {
                u32 Bh[2], Bl[2];
                u32 boff = 2 * ((nt * 8 + brow) * 136 + gnw * 32 + kt * 16 + bkq);
                ldsm2(Bh, sb + SM_B2 + boff);
                ldsm2(Bl, sb + SM_B2 + 17408 + boff);
                #pragma unroll
                for (int mt = 0; mt < 2; mt++) {
                    mma16816(g2acc[mt][nt], a2h[mt][kt], Bh);
                    mma16816(g2acc[mt][nt], a2l[mt][kt], Bh);
                    mma16816(g2acc[mt][nt], a2h[mt][kt], Bl);
                }
            }
    }
    // cross-warp reduction over gnw, then epilogue (LN applied here)
    __syncthreads();
    if (gnw != 0) {
        float* rp = smf + (SM_RED >> 2) + (((gnw - 1) * 2 + gmw) * 32 + lane) * 64;
        #pragma unroll
        for (int mt = 0; mt < 2; mt++)
            #pragma unroll
            for (int nt = 0; nt < 8; nt++)
                #pragma unroll
                for (int e = 0; e < 4; e++)
                    rp[mt * 32 + nt * 4 + e] = g2acc[mt][nt][e];
    }
    __syncthreads();
    if (gnw == 0) {
        #pragma unroll
        for (int p = 0; p < 3; p++) {
            const float* rp = smf + (SM_RED >> 2) + ((p * 2 + gmw) * 32 + lane) * 64;
            #pragma unroll
            for (int mt = 0; mt < 2; mt++)
                #pragma unroll
                for (int nt = 0; nt < 8; nt++)
                    #pragma unroll
                    for (int e = 0; e < 4; e++)
                        g2acc[mt][nt][e] += rp[mt * 32 + nt * 4 + e];
        }
        #pragma unroll
        for (int mt = 0; mt < 2; mt++)
            #pragma unroll
            for (int nt = 0; nt < 8; nt++) {
                int r0 = gmw * 32 + mt * 16 + (lane >> 2);
                int c0 = nt * 8 + (lane & 3) * 2;
                float b0 = __ldg(gb2 + c0), b1 = __ldg(gb2 + c0 + 1);
                float w0 = __ldg(lnw + c0), w1 = __ldg(lnw + c0 + 1);
                float z0 = __ldg(lnb + c0), z1 = __ldg(lnb + c0 + 1);
                float mu0 = smf[(SM_CS >> 2) + r0], is0 = smf[(SM_CS >> 2) + 64 + r0];
                float g0 = sigm(g2acc[mt][nt][0] + b0);
                float g1 = sigm(g2acc[mt][nt][1] + b1);
                float n0 = (smf[(SM_CHI >> 2) + r0 * CHI_STR + c0]     - mu0) * is0 * w0 + z0;
                float n1 = (smf[(SM_CHI >> 2) + r0 * CHI_STR + c0 + 1] - mu0) * is0 * w1 + z1;
                *(float2*)(outp + (abase + r0) * 64 + c0) = make_float2(g0 * n0, g1 * n1);
                int r1 = r0 + 8;
                float mu1 = smf[(SM_CS >> 2) + r1], is1 = smf[(SM_CS >> 2) + 64 + r1];
                float g2 = sigm(g2acc[mt][nt][2] + b0);
                float g3 = sigm(g2acc[mt][nt][3] + b1);
                float n2 = (smf[(SM_CHI >> 2) + r1 * CHI_STR + c0]     - mu1) * is1 * w0 + z0;
                float n3 = (smf[(SM_CHI >> 2) + r1 * CHI_STR + c0 + 1] - mu1) * is1 * w1 + z1;
                *(float2*)(outp + (abase + r1) * 64 + c0) = make_float2(g2 * n2, g3 * n3);
            }
    }
}

extern "C" void kernel_launch(void* const* d_in, const int* in_sizes, int n_in,
                              void* d_out, int out_size) {
    const float* emb  = (const float*)d_in[0];
    const float* mean = (const float*)d_in[1];
    const float* stdv = (const float*)d_in[2];
    const float* gam  = (const float*)d_in[3];
    const float* W0   = (const float*)d_in[4];
    const float* W1   = (const float*)d_in[5];
    const float* W2   = (const float*)d_in[6];
    const float* wc   = (const float*)d_in[7];
    const float* wd   = (const float*)d_in[8];
    const float* lnw  = (const float*)d_in[9];
    const float* lnb  = (const float*)d_in[10];
    const float* gw1  = (const float*)d_in[11];
    const float* gb1  = (const float*)d_in[12];
    const float* gw2  = (const float*)d_in[13];
    const float* gb2  = (const float*)d_in[14];
    float* out = (float*)d_out;

    prep_pf<<<192, 256>>>(gam, W0, W1, W2, wc, wd);
    prep_g1<<<512, 256>>>(gw1, stdv);
    prep_g2<<<64, 512>>>(gw2);
    prep_b1<<<512, 256>>>(gw1, gb1, mean, stdv);

    cudaFuncSetAttribute(chiral_tc, cudaFuncAttributeMaxDynamicSharedMemorySize, SM_BYTES);
    chiral_tc<<<131072 / ATOMS, NT, SM_BYTES>>>(emb, lnw, lnb, gb2, out);
}

// round 13
// speedup vs baseline: 1.9042x; 1.2088x over previous
#include <cuda_runtime.h>
#include <cuda_fp16.h>

typedef unsigned long long u64;
typedef unsigned int u32;
typedef unsigned short u16;

#define NT 256
#define ATOMS 64

// ---------------- smem map (bytes) ----------------
#define SM_EQA    0          // [3 dims][2 sides][64][40hw u16] = 6*5120 = 30720
#define SM_B      30720      // eq B hi: 192 rows * 80 = 15360
#define SM_INVA   0          // gate alias: [2][64][264hw]
#define INVA_SIDE 33792
#define INVA_STR  264
#define SM_B1     67584      // 2 bufs * 10240 (hi only)
#define SM_RED    88064      // 49152 B gate2 reduction (late)
#define SM_B2     88064      // alias RED (B2 used before RED): 64*272 = 17408
#define SM_CHI    137216     // 64*66*4 = 16896
#define CHI_STR   66
#define SM_CS     154112     // 128 f32
#define SM_RSS    154624     // 512 f32
#define SM_BYTES  156672

__device__ u16 d_PfT_h[192 * 256];
__device__ u16 d_G1T_h[512 * 256];
__device__ u16 d_G2T_h[64 * 512];
__device__ float d_B1f[512];

// ---------------- helpers ----------------
static __device__ __forceinline__ u32 smem_u32(const void* p) {
    u32 a;
    asm("{ .reg .u64 t; cvta.to.shared.u64 t, %1; cvt.u32.u64 %0, t; }" : "=r"(a) : "l"(p));
    return a;
}
static __device__ __forceinline__ void ldsm4(u32* r, u32 addr) {
    asm volatile("ldmatrix.sync.aligned.m8n8.x4.shared.b16 {%0,%1,%2,%3}, [%4];"
        : "=r"(r[0]), "=r"(r[1]), "=r"(r[2]), "=r"(r[3]) : "r"(addr));
}
static __device__ __forceinline__ void ldsm2(u32* r, u32 addr) {
    asm volatile("ldmatrix.sync.aligned.m8n8.x2.shared.b16 {%0,%1}, [%2];"
        : "=r"(r[0]), "=r"(r[1]) : "r"(addr));
}
static __device__ __forceinline__ void mma16816(float* d, const u32* a, const u32* b) {
    asm volatile(
        "mma.sync.aligned.m16n8k16.row.col.f32.f16.f16.f32 "
        "{%0,%1,%2,%3},{%4,%5,%6,%7},{%8,%9},{%0,%1,%2,%3};"
        : "+f"(d[0]), "+f"(d[1]), "+f"(d[2]), "+f"(d[3])
        : "r"(a[0]), "r"(a[1]), "r"(a[2]), "r"(a[3]), "r"(b[0]), "r"(b[1]));
}
static __device__ __forceinline__ void cpa16(u32 dst, const void* src) {
    asm volatile("cp.async.cg.shared.global [%0], [%1], 16;" :: "r"(dst), "l"(src));
}
#define CP_COMMIT() asm volatile("cp.async.commit_group;")
#define CP_WAIT0()  asm volatile("cp.async.wait_group 0;")

// fp16 2-term split: A data kept to ~22 bits (hi+lo); weights hi-only (11 bits)
static __device__ __forceinline__ void split1(float v, u16& h, u16& l) {
    __half hh = __float2half_rn(v);
    float lr = v - __half2float(hh);
    __half ll = __float2half_rn(lr);
    h = __half_as_ushort(hh); l = __half_as_ushort(ll);
}
static __device__ __forceinline__ u16 cvt1(float v) {
    return __half_as_ushort(__float2half_rn(v));
}
static __device__ __forceinline__ void splitpk(float a, float b, u32& h, u32& l) {
    __half2 hp = __floats2half2_rn(a, b);          // low = a (elem k), high = b (elem k+1)
    float ra = a - __low2float(hp);
    float rb = b - __high2float(hp);
    __half2 lp = __floats2half2_rn(ra, rb);
    h = *(u32*)&hp; l = *(u32*)&lp;
}
static __device__ __forceinline__ float silu(float x) { return x / (1.f + __expf(-x)); }
static __device__ __forceinline__ float sigm(float x) { return 1.f / (1.f + __expf(-x)); }

// ---------------- prep kernels ----------------
__global__ void prep_pf(const float* __restrict__ gam, const float* __restrict__ W0,
                        const float* __restrict__ W1, const float* __restrict__ W2,
                        const float* __restrict__ wc, const float* __restrict__ wd) {
    int n = blockIdx.x, m = threadIdx.x;
    int role = n >> 6, u = n & 63;
    float v;
    if (role == 0) v = W0[m * 64 + u];
    else {
        const float* Wx = (role == 1) ? W1 : W2;
        const float* wx = (role == 1) ? wc : wd;
        float s = 0.f;
        #pragma unroll 8
        for (int j = 0; j < 64; j++) s += Wx[m * 64 + j] * wx[u * 64 + j];
        v = s;
    }
    d_PfT_h[n * 256 + m] = cvt1(v * gam[m] * 0.0625f);
}
__global__ void prep_g1(const float* __restrict__ gw1, const float* __restrict__ stdv) {
    int h = blockIdx.x, v = threadIdx.x;
    d_G1T_h[h * 256 + v] = cvt1(gw1[v * 512 + h] / stdv[v]);
}
__global__ void prep_g2(const float* __restrict__ gw2) {
    int k = blockIdx.x, h = threadIdx.x;
    d_G2T_h[k * 512 + h] = cvt1(gw2[h * 64 + k]);
}
__global__ void prep_b1(const float* __restrict__ gw1, const float* __restrict__ gb1,
                        const float* __restrict__ mean, const float* __restrict__ stdv) {
    __shared__ float red[256];
    int h = blockIdx.x, v = threadIdx.x;
    red[v] = (mean[v] / stdv[v]) * gw1[v * 512 + h];
    __syncthreads();
    #pragma unroll
    for (int s = 128; s > 0; s >>= 1) {
        if (v < s) red[v] += red[v + s];
        __syncthreads();
    }
    if (v == 0) d_B1f[h] = gb1[h] - red[0];
}

// ---------------- fused main kernel ----------------
__global__ __launch_bounds__(NT, 1)
void chiral_tc(const float* __restrict__ emb,
               const float* __restrict__ lnw, const float* __restrict__ lnb,
               const float* __restrict__ gb2, float* __restrict__ outp) {
    extern __shared__ char smc[];
    float* smf = (float*)smc;
    const u32 sb = smem_u32(smc);
    const int tid = threadIdx.x, lane = tid & 31, w = tid >> 5;
    const int l15 = lane & 15;
    const long abase = (long)blockIdx.x * ATOMS;

    const int arow = (lane & 7) + ((lane >> 3) & 1) * 8;
    const int akq  = (lane >> 4) * 8;
    const int brow = l15 & 7;
    const int bkq  = ((l15 >> 3) & 1) * 8;

    const int mw = w >> 2, uw = w & 3;
    const int a4 = tid >> 2, q4 = tid & 3;
    float rloc = 0.f;

    // ============ eq GEMM: single K sweep, 3 spatial dims in regs ============
    float acc[3][2][6][4];
    #pragma unroll
    for (int i = 0; i < 3; i++)
        #pragma unroll
        for (int mt = 0; mt < 2; mt++)
            #pragma unroll
            for (int nt = 0; nt < 6; nt++)
                #pragma unroll
                for (int e = 0; e < 4; e++) acc[i][mt][nt][e] = 0.f;

    for (int kc = 0; kc < 8; kc++) {
        float4 Areg[6];
        #pragma unroll
        for (int j = 0; j < 6; j++)
            Areg[j] = __ldg((const float4*)(emb + (abase + a4) * 1024) + 64 + kc * 24 + q4 * 6 + j);
        __syncthreads();
        // eq-B hi tile: 192 rows x 32 k x 2B = 768 cp.async of 16B
        #pragma unroll
        for (int rr = 0; rr < 3; rr++) {
            int idx = tid + rr * 256;
            int row = idx >> 2, ch = idx & 3;
            cpa16(sb + SM_B + row * 80 + ch * 16, d_PfT_h + row * 256 + kc * 32 + ch * 8);
        }
        CP_COMMIT();
        #pragma unroll
        for (int j = 0; j < 6; j++) {
            float vv[4] = {Areg[j].x, Areg[j].y, Areg[j].z, Areg[j].w};
            #pragma unroll
            for (int e = 0; e < 4; e++) {
                float f = vv[e];
                rloc += f * f;
                const int je = j * 4 + e;
                const int i = je % 3;
                int m = q4 * 8 + je / 3;
                u16 h, l; split1(f, h, l);
                *(u16*)(smc + SM_EQA + (i * 2 + 0) * 5120 + (a4 * 40 + m) * 2) = h;
                *(u16*)(smc + SM_EQA + (i * 2 + 1) * 5120 + (a4 * 40 + m) * 2) = l;
            }
        }
        CP_WAIT0();
        __syncthreads();
        #pragma unroll
        for (int ks = 0; ks < 2; ks++) {
            u32 A[3][2][2][4];
            #pragma unroll
            for (int i = 0; i < 3; i++)
                #pragma unroll
                for (int mt = 0; mt < 2; mt++)
                    #pragma unroll
                    for (int s = 0; s < 2; s++)
                        ldsm4(A[i][mt][s], sb + SM_EQA + (i * 2 + s) * 5120 +
                              2 * ((mw * 32 + mt * 16 + arow) * 40 + ks * 16 + akq));
            #pragma unroll
            for (int nt = 0; nt < 6; nt++) {
                u32 Bh[2];
                int nbase = (nt >> 1) * 64 + uw * 16 + (nt & 1) * 8;
                u32 boff = 2 * ((nbase + brow) * 40 + ks * 16 + bkq);
                ldsm2(Bh, sb + SM_B + boff);
                #pragma unroll
                for (int i = 0; i < 3; i++)
                    #pragma unroll
                    for (int mt = 0; mt < 2; mt++) {
                        mma16816(acc[i][mt][nt], A[i][mt][0], Bh);
                        mma16816(acc[i][mt][nt], A[i][mt][1], Bh);
                    }
            }
        }
    }
    __syncthreads();

    // ============ rms -> cs ============
    smf[(SM_RSS >> 2) + tid] = rloc;
    __syncthreads();
    if (tid < 64) {
        const float* rp = smf + (SM_RSS >> 2);
        float s = rp[tid * 4] + rp[tid * 4 + 1] + rp[tid * 4 + 2] + rp[tid * 4 + 3];
        float qr = rsqrtf(s * (1.f / 256.f) + 1e-6f);
        smf[(SM_CS >> 2) + tid] = qr * qr * qr * rsqrtf(24576.0f);
    }
    __syncthreads();

    // ============ det in registers -> raw chi to smem ============
    {
        #pragma unroll
        for (int mt = 0; mt < 2; mt++)
            #pragma unroll
            for (int eh = 0; eh < 2; eh++) {
                int r = mw * 32 + mt * 16 + eh * 8 + (lane >> 2);
                float cs = smf[(SM_CS >> 2) + r];
                #pragma unroll
                for (int half = 0; half < 2; half++)
                    #pragma unroll
                    for (int el = 0; el < 2; el++) {
                        int e = eh * 2 + el;
                        int u = uw * 16 + half * 8 + (lane & 3) * 2 + el;
                        float ax = acc[0][mt][half][e],     bx = acc[0][mt][2 + half][e], cx = acc[0][mt][4 + half][e];
                        float ay = acc[1][mt][half][e],     by = acc[1][mt][2 + half][e], cy = acc[1][mt][4 + half][e];
                        float az = acc[2][mt][half][e],     bz = acc[2][mt][2 + half][e], cz = acc[2][mt][4 + half][e];
                        float det = ax * (by * cz - bz * cy) + ay * (bz * cx - bx * cz)
                                  + az * (bx * cy - by * cx);
                        smf[(SM_CHI >> 2) + r * CHI_STR + u] = cs * det;
                    }
            }
    }
    __syncthreads();

    // ============ LN stats (mu, inv-sigma only; apply deferred to epilogue) ============
    {
        int a = tid >> 2, ug = tid & 3;
        float ps = 0.f, pq = 0.f;
        #pragma unroll 4
        for (int uu = 0; uu < 16; uu++) {
            float c = smf[(SM_CHI >> 2) + a * CHI_STR + ug * 16 + uu];
            ps += c; pq += c * c;
        }
        smf[(SM_RSS >> 2) + tid] = ps;
        smf[(SM_RSS >> 2) + 256 + tid] = pq;
    }
    __syncthreads();
    if (tid < 64) {
        const float* rp = smf + (SM_RSS >> 2);
        float s = rp[tid * 4] + rp[tid * 4 + 1] + rp[tid * 4 + 2] + rp[tid * 4 + 3];
        float q = rp[256 + tid * 4] + rp[256 + tid * 4 + 1] + rp[256 + tid * 4 + 2] + rp[256 + tid * 4 + 3];
        float mu = s * (1.f / 64.f);
        float var = fmaxf(q * (1.f / 64.f) - mu * mu, 0.f);
        smf[(SM_CS >> 2) + tid] = mu;
        smf[(SM_CS >> 2) + 64 + tid] = rsqrtf(var + 1e-5f);
    }

    // ============ gate phase ============
    {   // stage inv A [64][256] hi/lo
        const float4* src = (const float4*)(emb + (abase + a4) * 1024 + q4 * 64);
        #pragma unroll
        for (int j = 0; j < 16; j++) {
            float4 v = __ldg(src + j);
            float vv[4] = {v.x, v.y, v.z, v.w};
            #pragma unroll
            for (int e = 0; e < 4; e++) {
                int k = q4 * 64 + j * 4 + e;
                u16 h, l; split1(vv[e], h, l);
                *(u16*)(smc + SM_INVA + (a4 * INVA_STR + k) * 2) = h;
                *(u16*)(smc + SM_INVA + INVA_SIDE + (a4 * INVA_STR + k) * 2) = l;
            }
        }
    }
    // prologue B1 copy for (hc=0,kc=0): 128 rows x 32 k x 2B = 512 cp.async
    {
        u32 bb = sb + SM_B1;
        #pragma unroll
        for (int rr = 0; rr < 2; rr++) {
            int idx = tid + rr * 256;
            int row = idx >> 2, ch = idx & 3;
            cpa16(bb + row * 80 + ch * 16, d_G1T_h + row * 256 + ch * 8);
        }
        CP_COMMIT();
    }

    const int gmw = w >> 2, gnw = w & 3;
    float g2acc[2][8][4];
    #pragma unroll
    for (int mt = 0; mt < 2; mt++)
        #pragma unroll
        for (int nt = 0; nt < 8; nt++)
            #pragma unroll
            for (int e = 0; e < 4; e++) g2acc[mt][nt][e] = 0.f;

    for (int hc = 0; hc < 4; hc++) {
        float g1acc[2][4][4];
        #pragma unroll
        for (int mt = 0; mt < 2; mt++)
            #pragma unroll
            for (int nt = 0; nt < 4; nt++)
                #pragma unroll
                for (int e = 0; e < 4; e++) g1acc[mt][nt][e] = 0.f;

        for (int kc = 0; kc < 8; kc++) {
            int g = hc * 8 + kc;
            CP_WAIT0();
            __syncthreads();
            bool did = false;
            if (g < 31) {
                int gn = g + 1;
                int nhc = gn >> 3, nkc = gn & 7;
                u32 bb = sb + SM_B1 + (gn & 1) * 10240;
                #pragma unroll
                for (int rr = 0; rr < 2; rr++) {
                    int idx = tid + rr * 256;
                    int row = idx >> 2, ch = idx & 3;
                    cpa16(bb + row * 80 + ch * 16,
                          d_G1T_h + (nhc * 128 + row) * 256 + nkc * 32 + ch * 8);
                }
                did = true;
            }
            if (kc == 7) {   // prefetch B2(hc): 64 rows x 128 h x 2B = 1024 cp.async
                #pragma unroll
                for (int rr = 0; rr < 4; rr++) {
                    int idx = tid + rr * 256;
                    int row = idx >> 4, ch = idx & 15;
                    cpa16(sb + SM_B2 + row * 272 + ch * 16,
                          d_G2T_h + row * 512 + hc * 128 + ch * 8);
                }
                did = true;
            }
            if (did) CP_COMMIT();
            u32 bb = sb + SM_B1 + (g & 1) * 10240;
            #pragma unroll
            for (int ks = 0; ks < 2; ks++) {
                u32 A[2][2][4];
                #pragma unroll
                for (int mt = 0; mt < 2; mt++)
                    #pragma unroll
                    for (int s = 0; s < 2; s++)
                        ldsm4(A[mt][s], sb + SM_INVA + s * INVA_SIDE +
                              2 * ((gmw * 32 + mt * 16 + arow) * INVA_STR + kc * 32 + ks * 16 + akq));
                #pragma unroll
                for (int nt = 0; nt < 4; nt++) {
                    u32 Bh[2];
                    u32 boff = 2 * ((gnw * 32 + nt * 8 + brow) * 40 + ks * 16 + bkq);
                    ldsm2(Bh, bb + boff);
                    #pragma unroll
                    for (int mt = 0; mt < 2; mt++) {
                        mma16816(g1acc[mt][nt], A[mt][0], Bh);
                        mma16816(g1acc[mt][nt], A[mt][1], Bh);
                    }
                }
            }
        }
        // SiLU + re-split into gate2 A fragments (covers B2 copy latency)
        u32 a2h[2][2][4], a2l[2][2][4];
        #pragma unroll
        for (int mt = 0; mt < 2; mt++)
            #pragma unroll
            for (int kt = 0; kt < 2; kt++)
                #pragma unroll
                for (int half = 0; half < 2; half++) {
                    int nt = kt * 2 + half;
                    int hb = hc * 128 + gnw * 32 + nt * 8 + (lane & 3) * 2;
                    float b0 = __ldg(d_B1f + hb), b1 = __ldg(d_B1f + hb + 1);
                    float s0 = silu(g1acc[mt][nt][0] + b0);
                    float s1 = silu(g1acc[mt][nt][1] + b1);
                    float s2 = silu(g1acc[mt][nt][2] + b0);
                    float s3 = silu(g1acc[mt][nt][3] + b1);
                    splitpk(s0, s1, a2h[mt][kt][half * 2], a2l[mt][kt][half * 2]);
                    splitpk(s2, s3, a2h[mt][kt][half * 2 + 1], a2l[mt][kt][half * 2 + 1]);
                }
        CP_WAIT0();
        __syncthreads();
        #pragma unroll
        for (int kt = 0; kt < 2; kt++)
            #pragma unroll
            for (int nt = 0; nt < 8; nt++) {
                u32 Bh[2];
                u32 boff = 2 * ((nt * 8 + brow) * 136 + gnw * 32 + kt * 16 + bkq);
                ldsm2(Bh, sb + SM_B2 + boff);
                #pragma unroll
                for (int mt = 0; mt < 2; mt++) {
                    mma16816(g2acc[mt][nt], a2h[mt][kt], Bh);
                    mma16816(g2acc[mt][nt], a2l[mt][kt], Bh);
                }
            }
    }
    // cross-warp reduction over gnw, then epilogue (LN applied here)
    __syncthreads();
    if (gnw != 0) {
        float* rp = smf + (SM_RED >> 2) + (((gnw - 1) * 2 + gmw) * 32 + lane) * 64;
        #pragma unroll
        for (int mt = 0; mt < 2; mt++)
            #pragma unroll
            for (int nt = 0; nt < 8; nt++)
                #pragma unroll
                for (int e = 0; e < 4; e++)
                    rp[mt * 32 + nt * 4 + e] = g2acc[mt][nt][e];
    }
    __syncthreads();
    if (gnw == 0) {
        #pragma unroll
        for (int p = 0; p < 3; p++) {
            const float* rp = smf + (SM_RED >> 2) + ((p * 2 + gmw) * 32 + lane) * 64;
            #pragma unroll
            for (int mt = 0; mt < 2; mt++)
                #pragma unroll
                for (int nt = 0; nt < 8; nt++)
                    #pragma unroll
                    for (int e = 0; e < 4; e++)
                        g2acc[mt][nt][e] += rp[mt * 32 + nt * 4 + e];
        }
        #pragma unroll
        for (int mt = 0; mt < 2; mt++)
            #pragma unroll
            for (int nt = 0; nt < 8; nt++) {
                int r0 = gmw * 32 + mt * 16 + (lane >> 2);
                int c0 = nt * 8 + (lane & 3) * 2;
                float b0 = __ldg(gb2 + c0), b1 = __ldg(gb2 + c0 + 1);
                float w0 = __ldg(lnw + c0), w1 = __ldg(lnw + c0 + 1);
                float z0 = __ldg(lnb + c0), z1 = __ldg(lnb + c0 + 1);
                float mu0 = smf[(SM_CS >> 2) + r0], is0 = smf[(SM_CS >> 2) + 64 + r0];
                float g0 = sigm(g2acc[mt][nt][0] + b0);
                float g1 = sigm(g2acc[mt][nt][1] + b1);
                float n0 = (smf[(SM_CHI >> 2) + r0 * CHI_STR + c0]     - mu0) * is0 * w0 + z0;
                float n1 = (smf[(SM_CHI >> 2) + r0 * CHI_STR + c0 + 1] - mu0) * is0 * w1 + z1;
                *(float2*)(outp + (abase + r0) * 64 + c0) = make_float2(g0 * n0, g1 * n1);
                int r1 = r0 + 8;
                float mu1 = smf[(SM_CS >> 2) + r1], is1 = smf[(SM_CS >> 2) + 64 + r1];
                float g2 = sigm(g2acc[mt][nt][2] + b0);
                float g3 = sigm(g2acc[mt][nt][3] + b1);
                float n2 = (smf[(SM_CHI >> 2) + r1 * CHI_STR + c0]     - mu1) * is1 * w0 + z0;
                float n3 = (smf[(SM_CHI >> 2) + r1 * CHI_STR + c0 + 1] - mu1) * is1 * w1 + z1;
                *(float2*)(outp + (abase + r1) * 64 + c0) = make_float2(g2 * n2, g3 * n3);
            }
    }
}

extern "C" void kernel_launch(void* const* d_in, const int* in_sizes, int n_in,
                              void* d_out, int out_size) {
    const float* emb  = (const float*)d_in[0];
    const float* mean = (const float*)d_in[1];
    const float* stdv = (const float*)d_in[2];
    const float* gam  = (const float*)d_in[3];
    const float* W0   = (const float*)d_in[4];
    const float* W1   = (const float*)d_in[5];
    const float* W2   = (const float*)d_in[6];
    const float* wc   = (const float*)d_in[7];
    const float* wd   = (const float*)d_in[8];
    const float* lnw  = (const float*)d_in[9];
    const float* lnb  = (const float*)d_in[10];
    const float* gw1  = (const float*)d_in[11];
    const float* gb1  = (const float*)d_in[12];
    const float* gw2  = (const float*)d_in[13];
    const float* gb2  = (const float*)d_in[14];
    float* out = (float*)d_out;

    prep_pf<<<192, 256>>>(gam, W0, W1, W2, wc, wd);
    prep_g1<<<512, 256>>>(gw1, stdv);
    prep_g2<<<64, 512>>>(gw2);
    prep_b1<<<512, 256>>>(gw1, gb1, mean, stdv);

    cudaFuncSetAttribute(chiral_tc, cudaFuncAttributeMaxDynamicSharedMemorySize, SM_BYTES);
    chiral_tc<<<131072 / ATOMS, NT, SM_BYTES>>>(emb, lnw, lnb, gb2, out);
}

// round 14
// speedup vs baseline: 2.1599x; 1.1343x over previous
#include <cuda_runtime.h>
#include <cuda_fp16.h>

typedef unsigned long long u64;
typedef unsigned int u32;
typedef unsigned short u16;

#define NT 256
#define ATOMS 64

// ---------------- smem map (bytes) ----------------
#define SM_EQA    0          // [3 dims][2 sides][64][40hw u16] = 6*5120 = 30720
#define SM_B      30720      // eq B hi: 192 rows * 80 = 15360 -> eq window [0,46080)
#define SM_INVA   0          // gate alias: [64][264hw] u16 hi only = 33792
#define INVA_STR  264
#define SM_B1     46080      // 2 bufs * 10240 (hi only) -> [46080,66560)
#define SM_RED    66560      // 49152 gate2 reduction -> [66560,115712)
#define SM_B2     66560      // alias RED (B2 used before RED): 64*272 = 17408
#define SM_CHI    115712     // 64*66*4 = 16896
#define CHI_STR   66
#define SM_CS     132608     // 128 f32
#define SM_RSS    133120     // 512 f32
#define SM_BYTES  135168

__device__ u16 d_PfT_h[192 * 256];
__device__ u16 d_G1T_h[512 * 256];
__device__ u16 d_G2T_h[64 * 512];
__device__ float d_B1f[512];

// ---------------- helpers ----------------
static __device__ __forceinline__ u32 smem_u32(const void* p) {
    u32 a;
    asm("{ .reg .u64 t; cvta.to.shared.u64 t, %1; cvt.u32.u64 %0, t; }" : "=r"(a) : "l"(p));
    return a;
}
static __device__ __forceinline__ void ldsm4(u32* r, u32 addr) {
    asm volatile("ldmatrix.sync.aligned.m8n8.x4.shared.b16 {%0,%1,%2,%3}, [%4];"
        : "=r"(r[0]), "=r"(r[1]), "=r"(r[2]), "=r"(r[3]) : "r"(addr));
}
static __device__ __forceinline__ void ldsm2(u32* r, u32 addr) {
    asm volatile("ldmatrix.sync.aligned.m8n8.x2.shared.b16 {%0,%1}, [%2];"
        : "=r"(r[0]), "=r"(r[1]) : "r"(addr));
}
static __device__ __forceinline__ void mma16816(float* d, const u32* a, const u32* b) {
    asm volatile(
        "mma.sync.aligned.m16n8k16.row.col.f32.f16.f16.f32 "
        "{%0,%1,%2,%3},{%4,%5,%6,%7},{%8,%9},{%0,%1,%2,%3};"
        : "+f"(d[0]), "+f"(d[1]), "+f"(d[2]), "+f"(d[3])
        : "r"(a[0]), "r"(a[1]), "r"(a[2]), "r"(a[3]), "r"(b[0]), "r"(b[1]));
}
static __device__ __forceinline__ void cpa16(u32 dst, const void* src) {
    asm volatile("cp.async.cg.shared.global [%0], [%1], 16;" :: "r"(dst), "l"(src));
}
#define CP_COMMIT() asm volatile("cp.async.commit_group;")
#define CP_WAIT0()  asm volatile("cp.async.wait_group 0;")

static __device__ __forceinline__ u16 cvt1(float v) {
    return __half_as_ushort(__float2half_rn(v));
}
// split pair (v0 = elem k, v1 = elem k+1) into packed half2 hi + lo
static __device__ __forceinline__ void split2pk(float v0, float v1, u32& h, u32& l) {
    __half2 h2 = __floats2half2_rn(v0, v1);
    float r0 = v0 - __low2float(h2);
    float r1 = v1 - __high2float(h2);
    __half2 l2 = __floats2half2_rn(r0, r1);
    h = *(u32*)&h2; l = *(u32*)&l2;
}
static __device__ __forceinline__ u32 pk2h(float v0, float v1) {
    __half2 h2 = __floats2half2_rn(v0, v1);
    return *(u32*)&h2;
}
static __device__ __forceinline__ float silu(float x) { return x / (1.f + __expf(-x)); }
static __device__ __forceinline__ float sigm(float x) { return 1.f / (1.f + __expf(-x)); }

// ---------------- prep kernels ----------------
__global__ void prep_pf(const float* __restrict__ gam, const float* __restrict__ W0,
                        const float* __restrict__ W1, const float* __restrict__ W2,
                        const float* __restrict__ wc, const float* __restrict__ wd) {
    int n = blockIdx.x, m = threadIdx.x;
    int role = n >> 6, u = n & 63;
    float v;
    if (role == 0) v = W0[m * 64 + u];
    else {
        const float* Wx = (role == 1) ? W1 : W2;
        const float* wx = (role == 1) ? wc : wd;
        float s = 0.f;
        #pragma unroll 8
        for (int j = 0; j < 64; j++) s += Wx[m * 64 + j] * wx[u * 64 + j];
        v = s;
    }
    d_PfT_h[n * 256 + m] = cvt1(v * gam[m] * 0.0625f);
}
__global__ void prep_g1(const float* __restrict__ gw1, const float* __restrict__ stdv) {
    int h = blockIdx.x, v = threadIdx.x;
    d_G1T_h[h * 256 + v] = cvt1(gw1[v * 512 + h] / stdv[v]);
}
__global__ void prep_g2(const float* __restrict__ gw2) {
    int k = blockIdx.x, h = threadIdx.x;
    d_G2T_h[k * 512 + h] = cvt1(gw2[h * 64 + k]);
}
__global__ void prep_b1(const float* __restrict__ gw1, const float* __restrict__ gb1,
                        const float* __restrict__ mean, const float* __restrict__ stdv) {
    __shared__ float red[256];
    int h = blockIdx.x, v = threadIdx.x;
    red[v] = (mean[v] / stdv[v]) * gw1[v * 512 + h];
    __syncthreads();
    #pragma unroll
    for (int s = 128; s > 0; s >>= 1) {
        if (v < s) red[v] += red[v + s];
        __syncthreads();
    }
    if (v == 0) d_B1f[h] = gb1[h] - red[0];
}

// ---------------- fused main kernel ----------------
__global__ __launch_bounds__(NT, 1)
void chiral_tc(const float* __restrict__ emb,
               const float* __restrict__ lnw, const float* __restrict__ lnb,
               const float* __restrict__ gb2, float* __restrict__ outp) {
    extern __shared__ char smc[];
    float* smf = (float*)smc;
    const u32 sb = smem_u32(smc);
    const int tid = threadIdx.x, lane = tid & 31, w = tid >> 5;
    const int l15 = lane & 15;
    const long abase = (long)blockIdx.x * ATOMS;

    const int arow = (lane & 7) + ((lane >> 3) & 1) * 8;
    const int akq  = (lane >> 4) * 8;
    const int brow = l15 & 7;
    const int bkq  = ((l15 >> 3) & 1) * 8;

    const int mw = w >> 2, uw = w & 3;
    const int a4 = tid >> 2, q4 = tid & 3;
    float rloc = 0.f;

    // ============ eq GEMM: single K sweep, 3 spatial dims in regs ============
    float acc[3][2][6][4];
    #pragma unroll
    for (int i = 0; i < 3; i++)
        #pragma unroll
        for (int mt = 0; mt < 2; mt++)
            #pragma unroll
            for (int nt = 0; nt < 6; nt++)
                #pragma unroll
                for (int e = 0; e < 4; e++) acc[i][mt][nt][e] = 0.f;

    for (int kc = 0; kc < 8; kc++) {
        float4 Areg[6];
        #pragma unroll
        for (int j = 0; j < 6; j++)
            Areg[j] = __ldg((const float4*)(emb + (abase + a4) * 1024) + 64 + kc * 24 + q4 * 6 + j);
        __syncthreads();
        // eq-B hi tile: 192 rows x 32 k x 2B
        #pragma unroll
        for (int rr = 0; rr < 3; rr++) {
            int idx = tid + rr * 256;
            int row = idx >> 2, ch = idx & 3;
            cpa16(sb + SM_B + row * 80 + ch * 16, d_PfT_h + row * 256 + kc * 32 + ch * 8);
        }
        CP_COMMIT();
        // gather per-dim values, then vectorized split + 16B stores
        {
            float val[3][8];
            #pragma unroll
            for (int j = 0; j < 6; j++) {
                float vv[4] = {Areg[j].x, Areg[j].y, Areg[j].z, Areg[j].w};
                #pragma unroll
                for (int e = 0; e < 4; e++) {
                    const int je = j * 4 + e;
                    val[je % 3][je / 3] = vv[e];
                    rloc += vv[e] * vv[e];
                }
            }
            const u32 off = (u32)(a4 * 40 + q4 * 8) * 2;
            #pragma unroll
            for (int i = 0; i < 3; i++) {
                u32 hp[4], lp[4];
                #pragma unroll
                for (int p = 0; p < 4; p++)
                    split2pk(val[i][2 * p], val[i][2 * p + 1], hp[p], lp[p]);
                *(uint4*)(smc + SM_EQA + (i * 2 + 0) * 5120 + off) = make_uint4(hp[0], hp[1], hp[2], hp[3]);
                *(uint4*)(smc + SM_EQA + (i * 2 + 1) * 5120 + off) = make_uint4(lp[0], lp[1], lp[2], lp[3]);
            }
        }
        CP_WAIT0();
        __syncthreads();
        #pragma unroll
        for (int ks = 0; ks < 2; ks++) {
            u32 A[3][2][2][4];
            #pragma unroll
            for (int i = 0; i < 3; i++)
                #pragma unroll
                for (int mt = 0; mt < 2; mt++)
                    #pragma unroll
                    for (int s = 0; s < 2; s++)
                        ldsm4(A[i][mt][s], sb + SM_EQA + (i * 2 + s) * 5120 +
                              2 * ((mw * 32 + mt * 16 + arow) * 40 + ks * 16 + akq));
            #pragma unroll
            for (int nt = 0; nt < 6; nt++) {
                u32 Bh[2];
                int nbase = (nt >> 1) * 64 + uw * 16 + (nt & 1) * 8;
                u32 boff = 2 * ((nbase + brow) * 40 + ks * 16 + bkq);
                ldsm2(Bh, sb + SM_B + boff);
                #pragma unroll
                for (int i = 0; i < 3; i++)
                    #pragma unroll
                    for (int mt = 0; mt < 2; mt++) {
                        mma16816(acc[i][mt][nt], A[i][mt][0], Bh);
                        mma16816(acc[i][mt][nt], A[i][mt][1], Bh);
                    }
            }
        }
    }
    __syncthreads();

    // ============ rms -> cs ============
    smf[(SM_RSS >> 2) + tid] = rloc;
    __syncthreads();
    if (tid < 64) {
        const float* rp = smf + (SM_RSS >> 2);
        float s = rp[tid * 4] + rp[tid * 4 + 1] + rp[tid * 4 + 2] + rp[tid * 4 + 3];
        float qr = rsqrtf(s * (1.f / 256.f) + 1e-6f);
        smf[(SM_CS >> 2) + tid] = qr * qr * qr * rsqrtf(24576.0f);
    }
    __syncthreads();

    // ============ det in registers -> raw chi to smem ============
    {
        #pragma unroll
        for (int mt = 0; mt < 2; mt++)
            #pragma unroll
            for (int eh = 0; eh < 2; eh++) {
                int r = mw * 32 + mt * 16 + eh * 8 + (lane >> 2);
                float cs = smf[(SM_CS >> 2) + r];
                #pragma unroll
                for (int half = 0; half < 2; half++)
                    #pragma unroll
                    for (int el = 0; el < 2; el++) {
                        int e = eh * 2 + el;
                        int u = uw * 16 + half * 8 + (lane & 3) * 2 + el;
                        float ax = acc[0][mt][half][e],     bx = acc[0][mt][2 + half][e], cx = acc[0][mt][4 + half][e];
                        float ay = acc[1][mt][half][e],     by = acc[1][mt][2 + half][e], cy = acc[1][mt][4 + half][e];
                        float az = acc[2][mt][half][e],     bz = acc[2][mt][2 + half][e], cz = acc[2][mt][4 + half][e];
                        float det = ax * (by * cz - bz * cy) + ay * (bz * cx - bx * cz)
                                  + az * (bx * cy - by * cx);
                        smf[(SM_CHI >> 2) + r * CHI_STR + u] = cs * det;
                    }
            }
    }
    __syncthreads();

    // ============ LN stats (apply deferred to epilogue) ============
    {
        int a = tid >> 2, ug = tid & 3;
        float ps = 0.f, pq = 0.f;
        #pragma unroll 4
        for (int uu = 0; uu < 16; uu++) {
            float c = smf[(SM_CHI >> 2) + a * CHI_STR + ug * 16 + uu];
            ps += c; pq += c * c;
        }
        smf[(SM_RSS >> 2) + tid] = ps;
        smf[(SM_RSS >> 2) + 256 + tid] = pq;
    }
    __syncthreads();
    if (tid < 64) {
        const float* rp = smf + (SM_RSS >> 2);
        float s = rp[tid * 4] + rp[tid * 4 + 1] + rp[tid * 4 + 2] + rp[tid * 4 + 3];
        float q = rp[256 + tid * 4] + rp[256 + tid * 4 + 1] + rp[256 + tid * 4 + 2] + rp[256 + tid * 4 + 3];
        float mu = s * (1.f / 64.f);
        float var = fmaxf(q * (1.f / 64.f) - mu * mu, 0.f);
        smf[(SM_CS >> 2) + tid] = mu;
        smf[(SM_CS >> 2) + 64 + tid] = rsqrtf(var + 1e-5f);
    }

    // ============ gate phase ============
    {   // stage inv A [64][256] hi only, vectorized 16B stores
        const float4* src = (const float4*)(emb + (abase + a4) * 1024 + q4 * 64);
        #pragma unroll
        for (int jj = 0; jj < 8; jj++) {
            float4 v0 = __ldg(src + 2 * jj), v1 = __ldg(src + 2 * jj + 1);
            u32 hp0 = pk2h(v0.x, v0.y), hp1 = pk2h(v0.z, v0.w);
            u32 hp2 = pk2h(v1.x, v1.y), hp3 = pk2h(v1.z, v1.w);
            *(uint4*)(smc + SM_INVA + (u32)(a4 * INVA_STR + q4 * 64 + jj * 8) * 2) =
                make_uint4(hp0, hp1, hp2, hp3);
        }
    }
    // prologue B1 copy for (hc=0,kc=0)
    {
        u32 bb = sb + SM_B1;
        #pragma unroll
        for (int rr = 0; rr < 2; rr++) {
            int idx = tid + rr * 256;
            int row = idx >> 2, ch = idx & 3;
            cpa16(bb + row * 80 + ch * 16, d_G1T_h + row * 256 + ch * 8);
        }
        CP_COMMIT();
    }

    const int gmw = w >> 2, gnw = w & 3;
    float g2acc[2][8][4];
    #pragma unroll
    for (int mt = 0; mt < 2; mt++)
        #pragma unroll
        for (int nt = 0; nt < 8; nt++)
            #pragma unroll
            for (int e = 0; e < 4; e++) g2acc[mt][nt][e] = 0.f;

    for (int hc = 0; hc < 4; hc++) {
        float g1acc[2][4][4];
        #pragma unroll
        for (int mt = 0; mt < 2; mt++)
            #pragma unroll
            for (int nt = 0; nt < 4; nt++)
                #pragma unroll
                for (int e = 0; e < 4; e++) g1acc[mt][nt][e] = 0.f;

        for (int kc = 0; kc < 8; kc++) {
            int g = hc * 8 + kc;
            CP_WAIT0();
            __syncthreads();
            bool did = false;
            if (g < 31) {
                int gn = g + 1;
                int nhc = gn >> 3, nkc = gn & 7;
                u32 bb = sb + SM_B1 + (gn & 1) * 10240;
                #pragma unroll
                for (int rr = 0; rr < 2; rr++) {
                    int idx = tid + rr * 256;
                    int row = idx >> 2, ch = idx & 3;
                    cpa16(bb + row * 80 + ch * 16,
                          d_G1T_h + (nhc * 128 + row) * 256 + nkc * 32 + ch * 8);
                }
                did = true;
            }
            if (kc == 7) {
                #pragma unroll
                for (int rr = 0; rr < 4; rr++) {
                    int idx = tid + rr * 256;
                    int row = idx >> 4, ch = idx & 15;
                    cpa16(sb + SM_B2 + row * 272 + ch * 16,
                          d_G2T_h + row * 512 + hc * 128 + ch * 8);
                }
                did = true;
            }
            if (did) CP_COMMIT();
            u32 bb = sb + SM_B1 + (g & 1) * 10240;
            #pragma unroll
            for (int ks = 0; ks < 2; ks++) {
                u32 A[2][4];
                #pragma unroll
                for (int mt = 0; mt < 2; mt++)
                    ldsm4(A[mt], sb + SM_INVA +
                          2 * ((gmw * 32 + mt * 16 + arow) * INVA_STR + kc * 32 + ks * 16 + akq));
                #pragma unroll
                for (int nt = 0; nt < 4; nt++) {
                    u32 Bh[2];
                    u32 boff = 2 * ((gnw * 32 + nt * 8 + brow) * 40 + ks * 16 + bkq);
                    ldsm2(Bh, bb + boff);
                    #pragma unroll
                    for (int mt = 0; mt < 2; mt++)
                        mma16816(g1acc[mt][nt], A[mt], Bh);
                }
            }
        }
        // SiLU -> fp16 gate2 A fragments (covers B2 copy latency)
        u32 a2h[2][2][4];
        #pragma unroll
        for (int mt = 0; mt < 2; mt++)
            #pragma unroll
            for (int kt = 0; kt < 2; kt++)
                #pragma unroll
                for (int half = 0; half < 2; half++) {
                    int nt = kt * 2 + half;
                    int hb = hc * 128 + gnw * 32 + nt * 8 + (lane & 3) * 2;
                    float b0 = __ldg(d_B1f + hb), b1 = __ldg(d_B1f + hb + 1);
                    float s0 = silu(g1acc[mt][nt][0] + b0);
                    float s1 = silu(g1acc[mt][nt][1] + b1);
                    float s2 = silu(g1acc[mt][nt][2] + b0);
                    float s3 = silu(g1acc[mt][nt][3] + b1);
                    a2h[mt][kt][half * 2]     = pk2h(s0, s1);
                    a2h[mt][kt][half * 2 + 1] = pk2h(s2, s3);
                }
        CP_WAIT0();
        __syncthreads();
        #pragma unroll
        for (int kt = 0; kt < 2; kt++)
            #pragma unroll
            for (int nt = 0; nt < 8; nt++) {
                u32 Bh[2];
                u32 boff = 2 * ((nt * 8 + brow) * 136 + gnw * 32 + kt * 16 + bkq);
                ldsm2(Bh, sb + SM_B2 + boff);
                #pragma unroll
                for (int mt = 0; mt < 2; mt++)
                    mma16816(g2acc[mt][nt], a2h[mt][kt], Bh);
            }
    }
    // cross-warp reduction over gnw, then epilogue (LN applied here)
    __syncthreads();
    if (gnw != 0) {
        float* rp = smf + (SM_RED >> 2) + (((gnw - 1) * 2 + gmw) * 32 + lane) * 64;
        #pragma unroll
        for (int mt = 0; mt < 2; mt++)
            #pragma unroll
            for (int nt = 0; nt < 8; nt++)
                #pragma unroll
                for (int e = 0; e < 4; e++)
                    rp[mt * 32 + nt * 4 + e] = g2acc[mt][nt][e];
    }
    __syncthreads();
    if (gnw == 0) {
        #pragma unroll
        for (int p = 0; p < 3; p++) {
            const float* rp = smf + (SM_RED >> 2) + ((p * 2 + gmw) * 32 + lane) * 64;
            #pragma unroll
            for (int mt = 0; mt < 2; mt++)
                #pragma unroll
                for (int nt = 0; nt < 8; nt++)
                    #pragma unroll
                    for (int e = 0; e < 4; e++)
                        g2acc[mt][nt][e] += rp[mt * 32 + nt * 4 + e];
        }
        #pragma unroll
        for (int mt = 0; mt < 2; mt++)
            #pragma unroll
            for (int nt = 0; nt < 8; nt++) {
                int r0 = gmw * 32 + mt * 16 + (lane >> 2);
                int c0 = nt * 8 + (lane & 3) * 2;
                float b0 = __ldg(gb2 + c0), b1 = __ldg(gb2 + c0 + 1);
                float w0 = __ldg(lnw + c0), w1 = __ldg(lnw + c0 + 1);
                float z0 = __ldg(lnb + c0), z1 = __ldg(lnb + c0 + 1);
                float mu0 = smf[(SM_CS >> 2) + r0], is0 = smf[(SM_CS >> 2) + 64 + r0];
                float g0 = sigm(g2acc[mt][nt][0] + b0);
                float g1 = sigm(g2acc[mt][nt][1] + b1);
                float n0 = (smf[(SM_CHI >> 2) + r0 * CHI_STR + c0]     - mu0) * is0 * w0 + z0;
                float n1 = (smf[(SM_CHI >> 2) + r0 * CHI_STR + c0 + 1] - mu0) * is0 * w1 + z1;
                *(float2*)(outp + (abase + r0) * 64 + c0) = make_float2(g0 * n0, g1 * n1);
                int r1 = r0 + 8;
                float mu1 = smf[(SM_CS >> 2) + r1], is1 = smf[(SM_CS >> 2) + 64 + r1];
                float g2 = sigm(g2acc[mt][nt][2] + b0);
                float g3 = sigm(g2acc[mt][nt][3] + b1);
                float n2 = (smf[(SM_CHI >> 2) + r1 * CHI_STR + c0]     - mu1) * is1 * w0 + z0;
                float n3 = (smf[(SM_CHI >> 2) + r1 * CHI_STR + c0 + 1] - mu1) * is1 * w1 + z1;
                *(float2*)(outp + (abase + r1) * 64 + c0) = make_float2(g2 * n2, g3 * n3);
            }
    }
}

extern "C" void kernel_launch(void* const* d_in, const int* in_sizes, int n_in,
                              void* d_out, int out_size) {
    const float* emb  = (const float*)d_in[0];
    const float* mean = (const float*)d_in[1];
    const float* stdv = (const float*)d_in[2];
    const float* gam  = (const float*)d_in[3];
    const float* W0   = (const float*)d_in[4];
    const float* W1   = (const float*)d_in[5];
    const float* W2   = (const float*)d_in[6];
    const float* wc   = (const float*)d_in[7];
    const float* wd   = (const float*)d_in[8];
    const float* lnw  = (const float*)d_in[9];
    const float* lnb  = (const float*)d_in[10];
    const float* gw1  = (const float*)d_in[11];
    const float* gb1  = (const float*)d_in[12];
    const float* gw2  = (const float*)d_in[13];
    const float* gb2  = (const float*)d_in[14];
    float* out = (float*)d_out;

    prep_pf<<<192, 256>>>(gam, W0, W1, W2, wc, wd);
    prep_g1<<<512, 256>>>(gw1, stdv);
    prep_g2<<<64, 512>>>(gw2);
    prep_b1<<<512, 256>>>(gw1, gb1, mean, stdv);

    cudaFuncSetAttribute(chiral_tc, cudaFuncAttributeMaxDynamicSharedMemorySize, SM_BYTES);
    chiral_tc<<<131072 / ATOMS, NT, SM_BYTES>>>(emb, lnw, lnb, gb2, out);
}

// round 15
// speedup vs baseline: 2.5134x; 1.1637x over previous
#include <cuda_runtime.h>
#include <cuda_fp16.h>

typedef unsigned long long u64;
typedef unsigned int u32;
typedef unsigned short u16;

#define NT 256
#define ATOMS 32

// ---------------- smem map (bytes) ----------------
#define SM_EQA    0          // [3 dims][2 sides][32][40hw u16] = 6*2560 = 15360
#define SM_B      15360      // eq B hi: 192 rows * 80 = 15360 -> eq window [0,30720)
#define SM_INVA   0          // gate alias: [32][264hw] u16 hi = 16896
#define INVA_STR  264
#define SM_B1     30720      // 2 bufs * 10240 -> [30720,51200)
#define SM_RED    51200      // 24576 gate2 reduction -> [51200,75776)
#define SM_B2     51200      // alias RED: 64*272 = 17408
#define SM_CHI    75776      // 32*66*4 = 8448
#define CHI_STR   66
#define SM_CS     84224      // 128 f32
#define SM_RSS    84736      // 512 f32
#define SM_BYTES  86784

__device__ u16 d_PfT_h[192 * 256];
__device__ u16 d_G1T_h[512 * 256];
__device__ u16 d_G2T_h[64 * 512];
__device__ float d_B1f[512];

// ---------------- helpers ----------------
static __device__ __forceinline__ u32 smem_u32(const void* p) {
    u32 a;
    asm("{ .reg .u64 t; cvta.to.shared.u64 t, %1; cvt.u32.u64 %0, t; }" : "=r"(a) : "l"(p));
    return a;
}
static __device__ __forceinline__ void ldsm4(u32* r, u32 addr) {
    asm volatile("ldmatrix.sync.aligned.m8n8.x4.shared.b16 {%0,%1,%2,%3}, [%4];"
        : "=r"(r[0]), "=r"(r[1]), "=r"(r[2]), "=r"(r[3]) : "r"(addr));
}
static __device__ __forceinline__ void ldsm2(u32* r, u32 addr) {
    asm volatile("ldmatrix.sync.aligned.m8n8.x2.shared.b16 {%0,%1}, [%2];"
        : "=r"(r[0]), "=r"(r[1]) : "r"(addr));
}
static __device__ __forceinline__ void mma16816(float* d, const u32* a, const u32* b) {
    asm volatile(
        "mma.sync.aligned.m16n8k16.row.col.f32.f16.f16.f32 "
        "{%0,%1,%2,%3},{%4,%5,%6,%7},{%8,%9},{%0,%1,%2,%3};"
        : "+f"(d[0]), "+f"(d[1]), "+f"(d[2]), "+f"(d[3])
        : "r"(a[0]), "r"(a[1]), "r"(a[2]), "r"(a[3]), "r"(b[0]), "r"(b[1]));
}
static __device__ __forceinline__ void cpa16(u32 dst, const void* src) {
    asm volatile("cp.async.cg.shared.global [%0], [%1], 16;" :: "r"(dst), "l"(src));
}
#define CP_COMMIT() asm volatile("cp.async.commit_group;")
#define CP_WAIT0()  asm volatile("cp.async.wait_group 0;")

static __device__ __forceinline__ u16 cvt1(float v) {
    return __half_as_ushort(__float2half_rn(v));
}
static __device__ __forceinline__ void split2pk(float v0, float v1, u32& h, u32& l) {
    __half2 h2 = __floats2half2_rn(v0, v1);
    float r0 = v0 - __low2float(h2);
    float r1 = v1 - __high2float(h2);
    __half2 l2 = __floats2half2_rn(r0, r1);
    h = *(u32*)&h2; l = *(u32*)&l2;
}
static __device__ __forceinline__ u32 pk2h(float v0, float v1) {
    __half2 h2 = __floats2half2_rn(v0, v1);
    return *(u32*)&h2;
}
static __device__ __forceinline__ float silu(float x) { return x / (1.f + __expf(-x)); }
static __device__ __forceinline__ float sigm(float x) { return 1.f / (1.f + __expf(-x)); }

// ---------------- prep kernels ----------------
__global__ void prep_pf(const float* __restrict__ gam, const float* __restrict__ W0,
                        const float* __restrict__ W1, const float* __restrict__ W2,
                        const float* __restrict__ wc, const float* __restrict__ wd) {
    int n = blockIdx.x, m = threadIdx.x;
    int role = n >> 6, u = n & 63;
    float v;
    if (role == 0) v = W0[m * 64 + u];
    else {
        const float* Wx = (role == 1) ? W1 : W2;
        const float* wx = (role == 1) ? wc : wd;
        float s = 0.f;
        #pragma unroll 8
        for (int j = 0; j < 64; j++) s += Wx[m * 64 + j] * wx[u * 64 + j];
        v = s;
    }
    d_PfT_h[n * 256 + m] = cvt1(v * gam[m] * 0.0625f);
}
__global__ void prep_g1(const float* __restrict__ gw1, const float* __restrict__ stdv) {
    int h = blockIdx.x, v = threadIdx.x;
    d_G1T_h[h * 256 + v] = cvt1(gw1[v * 512 + h] / stdv[v]);
}
__global__ void prep_g2(const float* __restrict__ gw2) {
    int k = blockIdx.x, h = threadIdx.x;
    d_G2T_h[k * 512 + h] = cvt1(gw2[h * 64 + k]);
}
__global__ void prep_b1(const float* __restrict__ gw1, const float* __restrict__ gb1,
                        const float* __restrict__ mean, const float* __restrict__ stdv) {
    __shared__ float red[256];
    int h = blockIdx.x, v = threadIdx.x;
    red[v] = (mean[v] / stdv[v]) * gw1[v * 512 + h];
    __syncthreads();
    #pragma unroll
    for (int s = 128; s > 0; s >>= 1) {
        if (v < s) red[v] += red[v + s];
        __syncthreads();
    }
    if (v == 0) d_B1f[h] = gb1[h] - red[0];
}

// ---------------- fused main kernel ----------------
__global__ __launch_bounds__(NT, 2)
void chiral_tc(const float* __restrict__ emb,
               const float* __restrict__ lnw, const float* __restrict__ lnb,
               const float* __restrict__ gb2, float* __restrict__ outp) {
    extern __shared__ char smc[];
    float* smf = (float*)smc;
    const u32 sb = smem_u32(smc);
    const int tid = threadIdx.x, lane = tid & 31, w = tid >> 5;
    const int l15 = lane & 15;
    const long abase = (long)blockIdx.x * ATOMS;

    const int arow = (lane & 7) + ((lane >> 3) & 1) * 8;
    const int akq  = (lane >> 4) * 8;
    const int brow = l15 & 7;
    const int bkq  = ((l15 >> 3) & 1) * 8;

    const int mw = w >> 2, uw = w & 3;     // row block mw*16; u block uw*16
    const int a8 = tid >> 3, q8 = tid & 7; // staging: 8 threads per atom
    float rloc = 0.f;

    // ============ eq GEMM: single K sweep, 3 spatial dims in regs ============
    float acc[3][6][4];
    #pragma unroll
    for (int i = 0; i < 3; i++)
        #pragma unroll
        for (int nt = 0; nt < 6; nt++)
            #pragma unroll
            for (int e = 0; e < 4; e++) acc[i][nt][e] = 0.f;

    for (int kc = 0; kc < 8; kc++) {
        // 3 float4 per thread = 12 floats = 4 m x 3 dims
        float4 Areg[3];
        #pragma unroll
        for (int j = 0; j < 3; j++)
            Areg[j] = __ldg((const float4*)(emb + (abase + a8) * 1024) + 64 + kc * 24 + q8 * 3 + j);
        __syncthreads();
        // eq-B hi tile: 192 rows x 32 k x 2B
        #pragma unroll
        for (int rr = 0; rr < 3; rr++) {
            int idx = tid + rr * 256;
            int row = idx >> 2, ch = idx & 3;
            cpa16(sb + SM_B + row * 80 + ch * 16, d_PfT_h + row * 256 + kc * 32 + ch * 8);
        }
        CP_COMMIT();
        // gather per-dim values, split, 8B stores
        {
            float val[3][4];
            #pragma unroll
            for (int j = 0; j < 3; j++) {
                float vv[4] = {Areg[j].x, Areg[j].y, Areg[j].z, Areg[j].w};
                #pragma unroll
                for (int e = 0; e < 4; e++) {
                    const int je = j * 4 + e;
                    val[je % 3][je / 3] = vv[e];
                    rloc += vv[e] * vv[e];
                }
            }
            const u32 off = (u32)(a8 * 40 + q8 * 4) * 2;
            #pragma unroll
            for (int i = 0; i < 3; i++) {
                u32 hp[2], lp[2];
                split2pk(val[i][0], val[i][1], hp[0], lp[0]);
                split2pk(val[i][2], val[i][3], hp[1], lp[1]);
                *(uint2*)(smc + SM_EQA + (i * 2 + 0) * 2560 + off) = make_uint2(hp[0], hp[1]);
                *(uint2*)(smc + SM_EQA + (i * 2 + 1) * 2560 + off) = make_uint2(lp[0], lp[1]);
            }
        }
        CP_WAIT0();
        __syncthreads();
        #pragma unroll
        for (int ks = 0; ks < 2; ks++) {
            u32 A[3][2][4];
            #pragma unroll
            for (int i = 0; i < 3; i++)
                #pragma unroll
                for (int s = 0; s < 2; s++)
                    ldsm4(A[i][s], sb + SM_EQA + (i * 2 + s) * 2560 +
                          2 * ((mw * 16 + arow) * 40 + ks * 16 + akq));
            #pragma unroll
            for (int nt = 0; nt < 6; nt++) {
                u32 Bh[2];
                int nbase = (nt >> 1) * 64 + uw * 16 + (nt & 1) * 8;
                u32 boff = 2 * ((nbase + brow) * 40 + ks * 16 + bkq);
                ldsm2(Bh, sb + SM_B + boff);
                #pragma unroll
                for (int i = 0; i < 3; i++) {
                    mma16816(acc[i][nt], A[i][0], Bh);
                    mma16816(acc[i][nt], A[i][1], Bh);
                }
            }
        }
    }
    __syncthreads();

    // ============ rms -> cs ============
    smf[(SM_RSS >> 2) + tid] = rloc;
    __syncthreads();
    if (tid < 32) {
        const float* rp = smf + (SM_RSS >> 2);
        float s = 0.f;
        #pragma unroll
        for (int j = 0; j < 8; j++) s += rp[tid * 8 + j];
        float qr = rsqrtf(s * (1.f / 256.f) + 1e-6f);
        smf[(SM_CS >> 2) + tid] = qr * qr * qr * rsqrtf(24576.0f);
    }
    __syncthreads();

    // ============ det in registers -> raw chi to smem ============
    {
        #pragma unroll
        for (int eh = 0; eh < 2; eh++) {
            int r = mw * 16 + eh * 8 + (lane >> 2);
            float cs = smf[(SM_CS >> 2) + r];
            #pragma unroll
            for (int half = 0; half < 2; half++)
                #pragma unroll
                for (int el = 0; el < 2; el++) {
                    int e = eh * 2 + el;
                    int u = uw * 16 + half * 8 + (lane & 3) * 2 + el;
                    float ax = acc[0][half][e],     bx = acc[0][2 + half][e], cx = acc[0][4 + half][e];
                    float ay = acc[1][half][e],     by = acc[1][2 + half][e], cy = acc[1][4 + half][e];
                    float az = acc[2][half][e],     bz = acc[2][2 + half][e], cz = acc[2][4 + half][e];
                    float det = ax * (by * cz - bz * cy) + ay * (bz * cx - bx * cz)
                              + az * (bx * cy - by * cx);
                    smf[(SM_CHI >> 2) + r * CHI_STR + u] = cs * det;
                }
        }
    }
    __syncthreads();

    // ============ LN stats (apply deferred to epilogue) ============
    {
        int a = tid >> 3, ug = tid & 7;
        float ps = 0.f, pq = 0.f;
        #pragma unroll
        for (int uu = 0; uu < 8; uu++) {
            float c = smf[(SM_CHI >> 2) + a * CHI_STR + ug * 8 + uu];
            ps += c; pq += c * c;
        }
        smf[(SM_RSS >> 2) + tid] = ps;
        smf[(SM_RSS >> 2) + 256 + tid] = pq;
    }
    __syncthreads();
    if (tid < 32) {
        const float* rp = smf + (SM_RSS >> 2);
        float s = 0.f, q = 0.f;
        #pragma unroll
        for (int j = 0; j < 8; j++) { s += rp[tid * 8 + j]; q += rp[256 + tid * 8 + j]; }
        float mu = s * (1.f / 64.f);
        float var = fmaxf(q * (1.f / 64.f) - mu * mu, 0.f);
        smf[(SM_CS >> 2) + tid] = mu;
        smf[(SM_CS >> 2) + 64 + tid] = rsqrtf(var + 1e-5f);
    }

    // ============ gate phase ============
    {   // stage inv A [32][256] hi only: 8 float4/thread -> 4 uint4 stores
        const float4* src = (const float4*)(emb + (abase + a8) * 1024 + q8 * 32);
        #pragma unroll
        for (int jj = 0; jj < 4; jj++) {
            float4 v0 = __ldg(src + 2 * jj), v1 = __ldg(src + 2 * jj + 1);
            u32 hp0 = pk2h(v0.x, v0.y), hp1 = pk2h(v0.z, v0.w);
            u32 hp2 = pk2h(v1.x, v1.y), hp3 = pk2h(v1.z, v1.w);
            *(uint4*)(smc + SM_INVA + (u32)(a8 * INVA_STR + q8 * 32 + jj * 8) * 2) =
                make_uint4(hp0, hp1, hp2, hp3);
        }
    }
    // prologue B1 copy for (hc=0,kc=0)
    {
        u32 bb = sb + SM_B1;
        #pragma unroll
        for (int rr = 0; rr < 2; rr++) {
            int idx = tid + rr * 256;
            int row = idx >> 2, ch = idx & 3;
            cpa16(bb + row * 80 + ch * 16, d_G1T_h + row * 256 + ch * 8);
        }
        CP_COMMIT();
    }

    const int gmw = w >> 2, gnw = w & 3;
    float g2acc[8][4];
    #pragma unroll
    for (int nt = 0; nt < 8; nt++)
        #pragma unroll
        for (int e = 0; e < 4; e++) g2acc[nt][e] = 0.f;

    for (int hc = 0; hc < 4; hc++) {
        float g1acc[4][4];
        #pragma unroll
        for (int nt = 0; nt < 4; nt++)
            #pragma unroll
            for (int e = 0; e < 4; e++) g1acc[nt][e] = 0.f;

        for (int kc = 0; kc < 8; kc++) {
            int g = hc * 8 + kc;
            CP_WAIT0();
            __syncthreads();
            bool did = false;
            if (g < 31) {
                int gn = g + 1;
                int nhc = gn >> 3, nkc = gn & 7;
                u32 bb = sb + SM_B1 + (gn & 1) * 10240;
                #pragma unroll
                for (int rr = 0; rr < 2; rr++) {
                    int idx = tid + rr * 256;
                    int row = idx >> 2, ch = idx & 3;
                    cpa16(bb + row * 80 + ch * 16,
                          d_G1T_h + (nhc * 128 + row) * 256 + nkc * 32 + ch * 8);
                }
                did = true;
            }
            if (kc == 7) {
                #pragma unroll
                for (int rr = 0; rr < 4; rr++) {
                    int idx = tid + rr * 256;
                    int row = idx >> 4, ch = idx & 15;
                    cpa16(sb + SM_B2 + row * 272 + ch * 16,
                          d_G2T_h + row * 512 + hc * 128 + ch * 8);
                }
                did = true;
            }
            if (did) CP_COMMIT();
            u32 bb = sb + SM_B1 + (g & 1) * 10240;
            #pragma unroll
            for (int ks = 0; ks < 2; ks++) {
                u32 A[4];
                ldsm4(A, sb + SM_INVA +
                      2 * ((gmw * 16 + arow) * INVA_STR + kc * 32 + ks * 16 + akq));
                #pragma unroll
                for (int nt = 0; nt < 4; nt++) {
                    u32 Bh[2];
                    u32 boff = 2 * ((gnw * 32 + nt * 8 + brow) * 40 + ks * 16 + bkq);
                    ldsm2(Bh, bb + boff);
                    mma16816(g1acc[nt], A, Bh);
                }
            }
        }
        // SiLU -> fp16 gate2 A fragments (covers B2 copy latency)
        u32 a2h[2][4];
        #pragma unroll
        for (int kt = 0; kt < 2; kt++)
            #pragma unroll
            for (int half = 0; half < 2; half++) {
                int nt = kt * 2 + half;
                int hb = hc * 128 + gnw * 32 + nt * 8 + (lane & 3) * 2;
                float b0 = __ldg(d_B1f + hb), b1 = __ldg(d_B1f + hb + 1);
                float s0 = silu(g1acc[nt][0] + b0);
                float s1 = silu(g1acc[nt][1] + b1);
                float s2 = silu(g1acc[nt][2] + b0);
                float s3 = silu(g1acc[nt][3] + b1);
                a2h[kt][half * 2]     = pk2h(s0, s1);
                a2h[kt][half * 2 + 1] = pk2h(s2, s3);
            }
        CP_WAIT0();
        __syncthreads();
        #pragma unroll
        for (int kt = 0; kt < 2; kt++)
            #pragma unroll
            for (int nt = 0; nt < 8; nt++) {
                u32 Bh[2];
                u32 boff = 2 * ((nt * 8 + brow) * 136 + gnw * 32 + kt * 16 + bkq);
                ldsm2(Bh, sb + SM_B2 + boff);
                mma16816(g2acc[nt], a2h[kt], Bh);
            }
    }
    // cross-warp reduction over gnw, then epilogue (LN applied here)
    __syncthreads();
    if (gnw != 0) {
        float* rp = smf + (SM_RED >> 2) + (((gnw - 1) * 2 + gmw) * 32 + lane) * 32;
        #pragma unroll
        for (int nt = 0; nt < 8; nt++)
            #pragma unroll
            for (int e = 0; e < 4; e++)
                rp[nt * 4 + e] = g2acc[nt][e];
    }
    __syncthreads();
    if (gnw == 0) {
        #pragma unroll
        for (int p = 0; p < 3; p++) {
            const float* rp = smf + (SM_RED >> 2) + ((p * 2 + gmw) * 32 + lane) * 32;
            #pragma unroll
            for (int nt = 0; nt < 8; nt++)
                #pragma unroll
                for (int e = 0; e < 4; e++)
                    g2acc[nt][e] += rp[nt * 4 + e];
        }
        #pragma unroll
        for (int nt = 0; nt < 8; nt++) {
            int r0 = gmw * 16 + (lane >> 2);
            int c0 = nt * 8 + (lane & 3) * 2;
            float b0 = __ldg(gb2 + c0), b1 = __ldg(gb2 + c0 + 1);
            float w0 = __ldg(lnw + c0), w1 = __ldg(lnw + c0 + 1);
            float z0 = __ldg(lnb + c0), z1 = __ldg(lnb + c0 + 1);
            float mu0 = smf[(SM_CS >> 2) + r0], is0 = smf[(SM_CS >> 2) + 64 + r0];
            float g0 = sigm(g2acc[nt][0] + b0);
            float g1 = sigm(g2acc[nt][1] + b1);
            float n0 = (smf[(SM_CHI >> 2) + r0 * CHI_STR + c0]     - mu0) * is0 * w0 + z0;
            float n1 = (smf[(SM_CHI >> 2) + r0 * CHI_STR + c0 + 1] - mu0) * is0 * w1 + z1;
            *(float2*)(outp + (abase + r0) * 64 + c0) = make_float2(g0 * n0, g1 * n1);
            int r1 = r0 + 8;
            float mu1 = smf[(SM_CS >> 2) + r1], is1 = smf[(SM_CS >> 2) + 64 + r1];
            float g2 = sigm(g2acc[nt][2] + b0);
            float g3 = sigm(g2acc[nt][3] + b1);
            float n2 = (smf[(SM_CHI >> 2) + r1 * CHI_STR + c0]     - mu1) * is1 * w0 + z0;
            float n3 = (smf[(SM_CHI >> 2) + r1 * CHI_STR + c0 + 1] - mu1) * is1 * w1 + z1;
            *(float2*)(outp + (abase + r1) * 64 + c0) = make_float2(g2 * n2, g3 * n3);
        }
    }
}

extern "C" void kernel_launch(void* const* d_in, const int* in_sizes, int n_in,
                              void* d_out, int out_size) {
    const float* emb  = (const float*)d_in[0];
    const float* mean = (const float*)d_in[1];
    const float* stdv = (const float*)d_in[2];
    const float* gam  = (const float*)d_in[3];
    const float* W0   = (const float*)d_in[4];
    const float* W1   = (const float*)d_in[5];
    const float* W2   = (const float*)d_in[6];
    const float* wc   = (const float*)d_in[7];
    const float* wd   = (const float*)d_in[8];
    const float* lnw  = (const float*)d_in[9];
    const float* lnb  = (const float*)d_in[10];
    const float* gw1  = (const float*)d_in[11];
    const float* gb1  = (const float*)d_in[12];
    const float* gw2  = (const float*)d_in[13];
    const float* gb2  = (const float*)d_in[14];
    float* out = (float*)d_out;

    prep_pf<<<192, 256>>>(gam, W0, W1, W2, wc, wd);
    prep_g1<<<512, 256>>>(gw1, stdv);
    prep_g2<<<64, 512>>>(gw2);
    prep_b1<<<512, 256>>>(gw1, gb1, mean, stdv);

    cudaFuncSetAttribute(chiral_tc, cudaFuncAttributeMaxDynamicSharedMemorySize, SM_BYTES);
    chiral_tc<<<131072 / ATOMS, NT, SM_BYTES>>>(emb, lnw, lnb, gb2, out);
}

// round 16
// speedup vs baseline: 2.9162x; 1.1602x over previous
#include <cuda_runtime.h>
#include <cuda_fp16.h>

typedef unsigned long long u64;
typedef unsigned int u32;
typedef unsigned short u16;

#define NT 256
#define ATOMS 32

// ---------------- smem map (bytes) ----------------
#define SM_EQA    0          // [3 dims][32][40hw u16] hi only = 3*2560 = 7680
#define SM_B      7680       // eq B hi: 192 rows * 80 = 15360 -> eq window [0,23040)
#define SM_INVA   0          // gate alias: [32][264hw] u16 hi = 16896
#define INVA_STR  264
#define SM_B1     23040      // 2 bufs * 18432 (128 rows x 144B) -> [23040,59904)
#define SM_RED    59904      // 24576 gate2 reduction
#define SM_B2     59904      // alias RED: 64*272 = 17408
#define SM_CHI    84480      // 32*66*4 = 8448
#define CHI_STR   66
#define SM_CS     92928      // 128 f32
#define SM_RSS    93440      // 512 f32
#define SM_BYTES  95488

__device__ u16 d_PfT_h[192 * 256];
__device__ u16 d_G1T_h[512 * 256];
__device__ u16 d_G2T_h[64 * 512];
__device__ float d_B1f[512];

// ---------------- helpers ----------------
static __device__ __forceinline__ u32 smem_u32(const void* p) {
    u32 a;
    asm("{ .reg .u64 t; cvta.to.shared.u64 t, %1; cvt.u32.u64 %0, t; }" : "=r"(a) : "l"(p));
    return a;
}
static __device__ __forceinline__ void ldsm4(u32* r, u32 addr) {
    asm volatile("ldmatrix.sync.aligned.m8n8.x4.shared.b16 {%0,%1,%2,%3}, [%4];"
        : "=r"(r[0]), "=r"(r[1]), "=r"(r[2]), "=r"(r[3]) : "r"(addr));
}
static __device__ __forceinline__ void ldsm2(u32* r, u32 addr) {
    asm volatile("ldmatrix.sync.aligned.m8n8.x2.shared.b16 {%0,%1}, [%2];"
        : "=r"(r[0]), "=r"(r[1]) : "r"(addr));
}
static __device__ __forceinline__ void mma16816(float* d, const u32* a, const u32* b) {
    asm volatile(
        "mma.sync.aligned.m16n8k16.row.col.f32.f16.f16.f32 "
        "{%0,%1,%2,%3},{%4,%5,%6,%7},{%8,%9},{%0,%1,%2,%3};"
        : "+f"(d[0]), "+f"(d[1]), "+f"(d[2]), "+f"(d[3])
        : "r"(a[0]), "r"(a[1]), "r"(a[2]), "r"(a[3]), "r"(b[0]), "r"(b[1]));
}
static __device__ __forceinline__ void cpa16(u32 dst, const void* src) {
    asm volatile("cp.async.cg.shared.global [%0], [%1], 16;" :: "r"(dst), "l"(src));
}
#define CP_COMMIT() asm volatile("cp.async.commit_group;")
#define CP_WAIT0()  asm volatile("cp.async.wait_group 0;")

static __device__ __forceinline__ u16 cvt1(float v) {
    return __half_as_ushort(__float2half_rn(v));
}
static __device__ __forceinline__ u32 pk2h(float v0, float v1) {
    __half2 h2 = __floats2half2_rn(v0, v1);
    return *(u32*)&h2;
}
static __device__ __forceinline__ float silu(float x) { return x / (1.f + __expf(-x)); }
static __device__ __forceinline__ float sigm(float x) { return 1.f / (1.f + __expf(-x)); }

// ---------------- prep kernels ----------------
__global__ void prep_pf(const float* __restrict__ gam, const float* __restrict__ W0,
                        const float* __restrict__ W1, const float* __restrict__ W2,
                        const float* __restrict__ wc, const float* __restrict__ wd) {
    int n = blockIdx.x, m = threadIdx.x;
    int role = n >> 6, u = n & 63;
    float v;
    if (role == 0) v = W0[m * 64 + u];
    else {
        const float* Wx = (role == 1) ? W1 : W2;
        const float* wx = (role == 1) ? wc : wd;
        float s = 0.f;
        #pragma unroll 8
        for (int j = 0; j < 64; j++) s += Wx[m * 64 + j] * wx[u * 64 + j];
        v = s;
    }
    d_PfT_h[n * 256 + m] = cvt1(v * gam[m] * 0.0625f);
}
__global__ void prep_g1(const float* __restrict__ gw1, const float* __restrict__ stdv) {
    int h = blockIdx.x, v = threadIdx.x;
    d_G1T_h[h * 256 + v] = cvt1(gw1[v * 512 + h] / stdv[v]);
}
__global__ void prep_g2(const float* __restrict__ gw2) {
    int k = blockIdx.x, h = threadIdx.x;
    d_G2T_h[k * 512 + h] = cvt1(gw2[h * 64 + k]);
}
__global__ void prep_b1(const float* __restrict__ gw1, const float* __restrict__ gb1,
                        const float* __restrict__ mean, const float* __restrict__ stdv) {
    __shared__ float red[256];
    int h = blockIdx.x, v = threadIdx.x;
    red[v] = (mean[v] / stdv[v]) * gw1[v * 512 + h];
    __syncthreads();
    #pragma unroll
    for (int s = 128; s > 0; s >>= 1) {
        if (v < s) red[v] += red[v + s];
        __syncthreads();
    }
    if (v == 0) d_B1f[h] = gb1[h] - red[0];
}

// ---------------- fused main kernel ----------------
__global__ __launch_bounds__(NT, 2)
void chiral_tc(const float* __restrict__ emb,
               const float* __restrict__ lnw, const float* __restrict__ lnb,
               const float* __restrict__ gb2, float* __restrict__ outp) {
    extern __shared__ char smc[];
    float* smf = (float*)smc;
    const u32 sb = smem_u32(smc);
    const int tid = threadIdx.x, lane = tid & 31, w = tid >> 5;
    const int l15 = lane & 15;
    const long abase = (long)blockIdx.x * ATOMS;

    const int arow = (lane & 7) + ((lane >> 3) & 1) * 8;
    const int akq  = (lane >> 4) * 8;
    const int brow = l15 & 7;
    const int bkq  = ((l15 >> 3) & 1) * 8;

    const int mw = w >> 2, uw = w & 3;     // row block mw*16; u block uw*16
    const int a8 = tid >> 3, q8 = tid & 7; // staging: 8 threads per atom
    float rloc = 0.f;

    // ============ eq GEMM: single K sweep, fp16 A (hi only) ============
    float acc[3][6][4];
    #pragma unroll
    for (int i = 0; i < 3; i++)
        #pragma unroll
        for (int nt = 0; nt < 6; nt++)
            #pragma unroll
            for (int e = 0; e < 4; e++) acc[i][nt][e] = 0.f;

    for (int kc = 0; kc < 8; kc++) {
        float4 Areg[3];
        #pragma unroll
        for (int j = 0; j < 3; j++)
            Areg[j] = __ldg((const float4*)(emb + (abase + a8) * 1024) + 64 + kc * 24 + q8 * 3 + j);
        __syncthreads();
        // eq-B hi tile: 192 rows x 32 k x 2B
        #pragma unroll
        for (int rr = 0; rr < 3; rr++) {
            int idx = tid + rr * 256;
            int row = idx >> 2, ch = idx & 3;
            cpa16(sb + SM_B + row * 80 + ch * 16, d_PfT_h + row * 256 + kc * 32 + ch * 8);
        }
        CP_COMMIT();
        // gather per-dim values, cvt to fp16 hi, 8B stores
        {
            float val[3][4];
            #pragma unroll
            for (int j = 0; j < 3; j++) {
                float vv[4] = {Areg[j].x, Areg[j].y, Areg[j].z, Areg[j].w};
                #pragma unroll
                for (int e = 0; e < 4; e++) {
                    const int je = j * 4 + e;
                    val[je % 3][je / 3] = vv[e];
                    rloc += vv[e] * vv[e];
                }
            }
            const u32 off = (u32)(a8 * 40 + q8 * 4) * 2;
            #pragma unroll
            for (int i = 0; i < 3; i++) {
                u32 h0 = pk2h(val[i][0], val[i][1]);
                u32 h1 = pk2h(val[i][2], val[i][3]);
                *(uint2*)(smc + SM_EQA + i * 2560 + off) = make_uint2(h0, h1);
            }
        }
        CP_WAIT0();
        __syncthreads();
        #pragma unroll
        for (int ks = 0; ks < 2; ks++) {
            u32 A[3][4];
            #pragma unroll
            for (int i = 0; i < 3; i++)
                ldsm4(A[i], sb + SM_EQA + i * 2560 +
                      2 * ((mw * 16 + arow) * 40 + ks * 16 + akq));
            #pragma unroll
            for (int nt = 0; nt < 6; nt++) {
                u32 Bh[2];
                int nbase = (nt >> 1) * 64 + uw * 16 + (nt & 1) * 8;
                u32 boff = 2 * ((nbase + brow) * 40 + ks * 16 + bkq);
                ldsm2(Bh, sb + SM_B + boff);
                #pragma unroll
                for (int i = 0; i < 3; i++)
                    mma16816(acc[i][nt], A[i], Bh);
            }
        }
    }
    __syncthreads();

    // ============ rms -> cs ============
    smf[(SM_RSS >> 2) + tid] = rloc;
    __syncthreads();
    if (tid < 32) {
        const float* rp = smf + (SM_RSS >> 2);
        float s = 0.f;
        #pragma unroll
        for (int j = 0; j < 8; j++) s += rp[tid * 8 + j];
        float qr = rsqrtf(s * (1.f / 256.f) + 1e-6f);
        smf[(SM_CS >> 2) + tid] = qr * qr * qr * rsqrtf(24576.0f);
    }
    __syncthreads();

    // ============ det in registers -> raw chi to smem ============
    {
        #pragma unroll
        for (int eh = 0; eh < 2; eh++) {
            int r = mw * 16 + eh * 8 + (lane >> 2);
            float cs = smf[(SM_CS >> 2) + r];
            #pragma unroll
            for (int half = 0; half < 2; half++)
                #pragma unroll
                for (int el = 0; el < 2; el++) {
                    int e = eh * 2 + el;
                    int u = uw * 16 + half * 8 + (lane & 3) * 2 + el;
                    float ax = acc[0][half][e],     bx = acc[0][2 + half][e], cx = acc[0][4 + half][e];
                    float ay = acc[1][half][e],     by = acc[1][2 + half][e], cy = acc[1][4 + half][e];
                    float az = acc[2][half][e],     bz = acc[2][2 + half][e], cz = acc[2][4 + half][e];
                    float det = ax * (by * cz - bz * cy) + ay * (bz * cx - bx * cz)
                              + az * (bx * cy - by * cx);
                    smf[(SM_CHI >> 2) + r * CHI_STR + u] = cs * det;
                }
        }
    }
    __syncthreads();

    // ============ LN stats (apply deferred to epilogue) ============
    {
        int a = tid >> 3, ug = tid & 7;
        float ps = 0.f, pq = 0.f;
        #pragma unroll
        for (int uu = 0; uu < 8; uu++) {
            float c = smf[(SM_CHI >> 2) + a * CHI_STR + ug * 8 + uu];
            ps += c; pq += c * c;
        }
        smf[(SM_RSS >> 2) + tid] = ps;
        smf[(SM_RSS >> 2) + 256 + tid] = pq;
    }
    __syncthreads();
    if (tid < 32) {
        const float* rp = smf + (SM_RSS >> 2);
        float s = 0.f, q = 0.f;
        #pragma unroll
        for (int j = 0; j < 8; j++) { s += rp[tid * 8 + j]; q += rp[256 + tid * 8 + j]; }
        float mu = s * (1.f / 64.f);
        float var = fmaxf(q * (1.f / 64.f) - mu * mu, 0.f);
        smf[(SM_CS >> 2) + tid] = mu;
        smf[(SM_CS >> 2) + 64 + tid] = rsqrtf(var + 1e-5f);
    }

    // ============ gate phase ============
    {   // stage inv A [32][256] hi only
        const float4* src = (const float4*)(emb + (abase + a8) * 1024 + q8 * 32);
        #pragma unroll
        for (int jj = 0; jj < 4; jj++) {
            float4 v0 = __ldg(src + 2 * jj), v1 = __ldg(src + 2 * jj + 1);
            u32 hp0 = pk2h(v0.x, v0.y), hp1 = pk2h(v0.z, v0.w);
            u32 hp2 = pk2h(v1.x, v1.y), hp3 = pk2h(v1.z, v1.w);
            *(uint4*)(smc + SM_INVA + (u32)(a8 * INVA_STR + q8 * 32 + jj * 8) * 2) =
                make_uint4(hp0, hp1, hp2, hp3);
        }
    }
    // prologue B1 copy for (hc=0,kcb=0): 128 rows x 64 k
    {
        u32 bb = sb + SM_B1;
        #pragma unroll
        for (int rr = 0; rr < 4; rr++) {
            int idx = tid + rr * 256;
            int row = idx >> 3, ch = idx & 7;
            cpa16(bb + row * 144 + ch * 16, d_G1T_h + row * 256 + ch * 8);
        }
        CP_COMMIT();
    }

    const int gmw = w >> 2, gnw = w & 3;
    float g2acc[8][4];
    #pragma unroll
    for (int nt = 0; nt < 8; nt++)
        #pragma unroll
        for (int e = 0; e < 4; e++) g2acc[nt][e] = 0.f;

    for (int hc = 0; hc < 4; hc++) {
        float g1acc[4][4];
        #pragma unroll
        for (int nt = 0; nt < 4; nt++)
            #pragma unroll
            for (int e = 0; e < 4; e++) g1acc[nt][e] = 0.f;

        for (int kcb = 0; kcb < 4; kcb++) {    // k-chunks of 64
            int g = hc * 4 + kcb;
            CP_WAIT0();
            __syncthreads();
            bool did = false;
            if (g < 15) {
                int gn = g + 1;
                int nhc = gn >> 2, nkcb = gn & 3;
                u32 bb = sb + SM_B1 + (gn & 1) * 18432;
                #pragma unroll
                for (int rr = 0; rr < 4; rr++) {
                    int idx = tid + rr * 256;
                    int row = idx >> 3, ch = idx & 7;
                    cpa16(bb + row * 144 + ch * 16,
                          d_G1T_h + (nhc * 128 + row) * 256 + nkcb * 64 + ch * 8);
                }
                did = true;
            }
            if (kcb == 3) {
                #pragma unroll
                for (int rr = 0; rr < 4; rr++) {
                    int idx = tid + rr * 256;
                    int row = idx >> 4, ch = idx & 15;
                    cpa16(sb + SM_B2 + row * 272 + ch * 16,
                          d_G2T_h + row * 512 + hc * 128 + ch * 8);
                }
                did = true;
            }
            if (did) CP_COMMIT();
            u32 bb = sb + SM_B1 + (g & 1) * 18432;
            #pragma unroll
            for (int ks = 0; ks < 4; ks++) {
                u32 A[4];
                ldsm4(A, sb + SM_INVA +
                      2 * ((gmw * 16 + arow) * INVA_STR + kcb * 64 + ks * 16 + akq));
                #pragma unroll
                for (int nt = 0; nt < 4; nt++) {
                    u32 Bh[2];
                    u32 boff = (gnw * 32 + nt * 8 + brow) * 144 + (ks * 16 + bkq) * 2;
                    ldsm2(Bh, bb + boff);
                    mma16816(g1acc[nt], A, Bh);
                }
            }
        }
        // SiLU -> fp16 gate2 A fragments (covers B2 copy latency)
        u32 a2h[2][4];
        #pragma unroll
        for (int kt = 0; kt < 2; kt++)
            #pragma unroll
            for (int half = 0; half < 2; half++) {
                int nt = kt * 2 + half;
                int hb = hc * 128 + gnw * 32 + nt * 8 + (lane & 3) * 2;
                float b0 = __ldg(d_B1f + hb), b1 = __ldg(d_B1f + hb + 1);
                float s0 = silu(g1acc[nt][0] + b0);
                float s1 = silu(g1acc[nt][1] + b1);
                float s2 = silu(g1acc[nt][2] + b0);
                float s3 = silu(g1acc[nt][3] + b1);
                a2h[kt][half * 2]     = pk2h(s0, s1);
                a2h[kt][half * 2 + 1] = pk2h(s2, s3);
            }
        CP_WAIT0();
        __syncthreads();
        #pragma unroll
        for (int kt = 0; kt < 2; kt++)
            #pragma unroll
            for (int nt = 0; nt < 8; nt++) {
                u32 Bh[2];
                u32 boff = 2 * ((nt * 8 + brow) * 136 + gnw * 32 + kt * 16 + bkq);
                ldsm2(Bh, sb + SM_B2 + boff);
                mma16816(g2acc[nt], a2h[kt], Bh);
            }
    }
    // cross-warp reduction over gnw, then epilogue (LN applied here)
    __syncthreads();
    if (gnw != 0) {
        float* rp = smf + (SM_RED >> 2) + (((gnw - 1) * 2 + gmw) * 32 + lane) * 32;
        #pragma unroll
        for (int nt = 0; nt < 8; nt++)
            #pragma unroll
            for (int e = 0; e < 4; e++)
                rp[nt * 4 + e] = g2acc[nt][e];
    }
    __syncthreads();
    if (gnw == 0) {
        #pragma unroll
        for (int p = 0; p < 3; p++) {
            const float* rp = smf + (SM_RED >> 2) + ((p * 2 + gmw) * 32 + lane) * 32;
            #pragma unroll
            for (int nt = 0; nt < 8; nt++)
                #pragma unroll
                for (int e = 0; e < 4; e++)
                    g2acc[nt][e] += rp[nt * 4 + e];
        }
        #pragma unroll
        for (int nt = 0; nt < 8; nt++) {
            int r0 = gmw * 16 + (lane >> 2);
            int c0 = nt * 8 + (lane & 3) * 2;
            float b0 = __ldg(gb2 + c0), b1 = __ldg(gb2 + c0 + 1);
            float w0 = __ldg(lnw + c0), w1 = __ldg(lnw + c0 + 1);
            float z0 = __ldg(lnb + c0), z1 = __ldg(lnb + c0 + 1);
            float mu0 = smf[(SM_CS >> 2) + r0], is0 = smf[(SM_CS >> 2) + 64 + r0];
            float g0 = sigm(g2acc[nt][0] + b0);
            float g1 = sigm(g2acc[nt][1] + b1);
            float n0 = (smf[(SM_CHI >> 2) + r0 * CHI_STR + c0]     - mu0) * is0 * w0 + z0;
            float n1 = (smf[(SM_CHI >> 2) + r0 * CHI_STR + c0 + 1] - mu0) * is0 * w1 + z1;
            *(float2*)(outp + (abase + r0) * 64 + c0) = make_float2(g0 * n0, g1 * n1);
            int r1 = r0 + 8;
            float mu1 = smf[(SM_CS >> 2) + r1], is1 = smf[(SM_CS >> 2) + 64 + r1];
            float g2 = sigm(g2acc[nt][2] + b0);
            float g3 = sigm(g2acc[nt][3] + b1);
            float n2 = (smf[(SM_CHI >> 2) + r1 * CHI_STR + c0]     - mu1) * is1 * w0 + z0;
            float n3 = (smf[(SM_CHI >> 2) + r1 * CHI_STR + c0 + 1] - mu1) * is1 * w1 + z1;
            *(float2*)(outp + (abase + r1) * 64 + c0) = make_float2(g2 * n2, g3 * n3);
        }
    }
}

extern "C" void kernel_launch(void* const* d_in, const int* in_sizes, int n_in,
                              void* d_out, int out_size) {
    const float* emb  = (const float*)d_in[0];
    const float* mean = (const float*)d_in[1];
    const float* stdv = (const float*)d_in[2];
    const float* gam  = (const float*)d_in[3];
    const float* W0   = (const float*)d_in[4];
    const float* W1   = (const float*)d_in[5];
    const float* W2   = (const float*)d_in[6];
    const float* wc   = (const float*)d_in[7];
    const float* wd   = (const float*)d_in[8];
    const float* lnw  = (const float*)d_in[9];
    const float* lnb  = (const float*)d_in[10];
    const float* gw1  = (const float*)d_in[11];
    const float* gb1  = (const float*)d_in[12];
    const float* gw2  = (const float*)d_in[13];
    const float* gb2  = (const float*)d_in[14];
    float* out = (float*)d_out;

    prep_pf<<<192, 256>>>(gam, W0, W1, W2, wc, wd);
    prep_g1<<<512, 256>>>(gw1, stdv);
    prep_g2<<<64, 512>>>(gw2);
    prep_b1<<<512, 256>>>(gw1, gb1, mean, stdv);

    cudaFuncSetAttribute(chiral_tc, cudaFuncAttributeMaxDynamicSharedMemorySize, SM_BYTES);
    chiral_tc<<<131072 / ATOMS, NT, SM_BYTES>>>(emb, lnw, lnb, gb2, out);
}

// round 17
// speedup vs baseline: 2.9186x; 1.0008x over previous
#include <cuda_runtime.h>
#include <cuda_fp16.h>

typedef unsigned long long u64;
typedef unsigned int u32;
typedef unsigned short u16;

#define NT 256
#define ATOMS 32

// ---------------- smem map (bytes) ----------------
// eq window (double-buffered):
#define SM_EQA0   0          // [3][32][40hw u16] = 7680
#define SM_EQA1   7680       // 7680
#define SM_B0     15360      // 192 rows * 80 = 15360
#define SM_B1B    30720      // 15360 -> eq window [0,46080)
// gate aliases / persistent (inside dead eq regions):
#define SM_INVA   0          // [32][264hw] u16 = 16896 (over EQA0/EQA1/B0 head)
#define INVA_STR  264
#define SM_CHI    16896      // 8448, inside B0 region (dead post-eq)
#define CHI_STR   66
#define SM_CS     25344      // 128 f32 (dead-B0 region)
#define SM_RSS    25856      // 512 f32 (dead-B0 region)
// gate-only regions:
#define SM_B1     46080      // 2 bufs * 18432 (128 rows x 144B) -> [46080,82944)
#define SM_RED    82944      // 24576 gate2 reduction
#define SM_B2     82944      // alias RED: 64*272 = 17408
#define SM_BYTES  107520

__device__ u16 d_PfT_h[192 * 256];
__device__ u16 d_G1T_h[512 * 256];
__device__ u16 d_G2T_h[64 * 512];
__device__ float d_B1f[512];

// ---------------- helpers ----------------
static __device__ __forceinline__ u32 smem_u32(const void* p) {
    u32 a;
    asm("{ .reg .u64 t; cvta.to.shared.u64 t, %1; cvt.u32.u64 %0, t; }" : "=r"(a) : "l"(p));
    return a;
}
static __device__ __forceinline__ void ldsm4(u32* r, u32 addr) {
    asm volatile("ldmatrix.sync.aligned.m8n8.x4.shared.b16 {%0,%1,%2,%3}, [%4];"
        : "=r"(r[0]), "=r"(r[1]), "=r"(r[2]), "=r"(r[3]) : "r"(addr));
}
static __device__ __forceinline__ void ldsm2(u32* r, u32 addr) {
    asm volatile("ldmatrix.sync.aligned.m8n8.x2.shared.b16 {%0,%1}, [%2];"
        : "=r"(r[0]), "=r"(r[1]) : "r"(addr));
}
static __device__ __forceinline__ void mma16816(float* d, const u32* a, const u32* b) {
    asm volatile(
        "mma.sync.aligned.m16n8k16.row.col.f32.f16.f16.f32 "
        "{%0,%1,%2,%3},{%4,%5,%6,%7},{%8,%9},{%0,%1,%2,%3};"
        : "+f"(d[0]), "+f"(d[1]), "+f"(d[2]), "+f"(d[3])
        : "r"(a[0]), "r"(a[1]), "r"(a[2]), "r"(a[3]), "r"(b[0]), "r"(b[1]));
}
static __device__ __forceinline__ void cpa16(u32 dst, const void* src) {
    asm volatile("cp.async.cg.shared.global [%0], [%1], 16;" :: "r"(dst), "l"(src));
}
#define CP_COMMIT() asm volatile("cp.async.commit_group;")
#define CP_WAIT0()  asm volatile("cp.async.wait_group 0;")

static __device__ __forceinline__ u16 cvt1(float v) {
    return __half_as_ushort(__float2half_rn(v));
}
static __device__ __forceinline__ u32 pk2h(float v0, float v1) {
    __half2 h2 = __floats2half2_rn(v0, v1);
    return *(u32*)&h2;
}
static __device__ __forceinline__ float silu(float x) { return x / (1.f + __expf(-x)); }
static __device__ __forceinline__ float sigm(float x) { return 1.f / (1.f + __expf(-x)); }

// ---------------- prep kernels ----------------
__global__ void prep_pf(const float* __restrict__ gam, const float* __restrict__ W0,
                        const float* __restrict__ W1, const float* __restrict__ W2,
                        const float* __restrict__ wc, const float* __restrict__ wd) {
    int n = blockIdx.x, m = threadIdx.x;
    int role = n >> 6, u = n & 63;
    float v;
    if (role == 0) v = W0[m * 64 + u];
    else {
        const float* Wx = (role == 1) ? W1 : W2;
        const float* wx = (role == 1) ? wc : wd;
        float s = 0.f;
        #pragma unroll 8
        for (int j = 0; j < 64; j++) s += Wx[m * 64 + j] * wx[u * 64 + j];
        v = s;
    }
    d_PfT_h[n * 256 + m] = cvt1(v * gam[m] * 0.0625f);
}
__global__ void prep_g1(const float* __restrict__ gw1, const float* __restrict__ stdv) {
    int h = blockIdx.x, v = threadIdx.x;
    d_G1T_h[h * 256 + v] = cvt1(gw1[v * 512 + h] / stdv[v]);
}
__global__ void prep_g2(const float* __restrict__ gw2) {
    int k = blockIdx.x, h = threadIdx.x;
    d_G2T_h[k * 512 + h] = cvt1(gw2[h * 64 + k]);
}
__global__ void prep_b1(const float* __restrict__ gw1, const float* __restrict__ gb1,
                        const float* __restrict__ mean, const float* __restrict__ stdv) {
    __shared__ float red[256];
    int h = blockIdx.x, v = threadIdx.x;
    red[v] = (mean[v] / stdv[v]) * gw1[v * 512 + h];
    __syncthreads();
    #pragma unroll
    for (int s = 128; s > 0; s >>= 1) {
        if (v < s) red[v] += red[v + s];
        __syncthreads();
    }
    if (v == 0) d_B1f[h] = gb1[h] - red[0];
}

// ---------------- fused main kernel ----------------
__global__ __launch_bounds__(NT, 2)
void chiral_tc(const float* __restrict__ emb,
               const float* __restrict__ lnw, const float* __restrict__ lnb,
               const float* __restrict__ gb2, float* __restrict__ outp) {
    extern __shared__ char smc[];
    float* smf = (float*)smc;
    const u32 sb = smem_u32(smc);
    const int tid = threadIdx.x, lane = tid & 31, w = tid >> 5;
    const int l15 = lane & 15;
    const long abase = (long)blockIdx.x * ATOMS;

    const int arow = (lane & 7) + ((lane >> 3) & 1) * 8;
    const int akq  = (lane >> 4) * 8;
    const int brow = l15 & 7;
    const int bkq  = ((l15 >> 3) & 1) * 8;

    const int mw = w >> 2, uw = w & 3;     // row block mw*16; u block uw*16
    const int a8 = tid >> 3, q8 = tid & 7; // staging: 8 threads per atom
    float rloc = 0.f;

    // A-staging helper: cvt 12 floats (4 m x 3 dims) to fp16, 8B stores
    auto stageA = [&](const float4* Ar, u32 eoff) {
        float val[3][4];
        #pragma unroll
        for (int j = 0; j < 3; j++) {
            float vv[4] = {Ar[j].x, Ar[j].y, Ar[j].z, Ar[j].w};
            #pragma unroll
            for (int e = 0; e < 4; e++) {
                const int je = j * 4 + e;
                val[je % 3][je / 3] = vv[e];
                rloc += vv[e] * vv[e];
            }
        }
        const u32 off = (u32)(a8 * 40 + q8 * 4) * 2;
        #pragma unroll
        for (int i = 0; i < 3; i++) {
            u32 h0 = pk2h(val[i][0], val[i][1]);
            u32 h1 = pk2h(val[i][2], val[i][3]);
            *(uint2*)(smc + eoff + i * 2560 + off) = make_uint2(h0, h1);
        }
    };

    // ============ eq GEMM: double-buffered pipeline, 1 barrier per kc ============
    float acc[3][6][4];
    #pragma unroll
    for (int i = 0; i < 3; i++)
        #pragma unroll
        for (int nt = 0; nt < 6; nt++)
            #pragma unroll
            for (int e = 0; e < 4; e++) acc[i][nt][e] = 0.f;

    {   // prologue: stage A(0), B(0) into buffer 0
        float4 Areg[3];
        #pragma unroll
        for (int j = 0; j < 3; j++)
            Areg[j] = __ldg((const float4*)(emb + (abase + a8) * 1024) + 64 + q8 * 3 + j);
        #pragma unroll
        for (int rr = 0; rr < 3; rr++) {
            int idx = tid + rr * 256;
            int row = idx >> 2, ch = idx & 3;
            cpa16(sb + SM_B0 + row * 80 + ch * 16, d_PfT_h + row * 256 + ch * 8);
        }
        CP_COMMIT();
        stageA(Areg, SM_EQA0);
    }

    for (int kc = 0; kc < 8; kc++) {
        const u32 ebuf  = (kc & 1) ? SM_EQA1 : SM_EQA0;
        const u32 bbuf  = (kc & 1) ? SM_B1B  : SM_B0;
        const u32 ebufN = (kc & 1) ? SM_EQA0 : SM_EQA1;
        const u32 bbufN = (kc & 1) ? SM_B0   : SM_B1B;
        float4 AregN[3];
        if (kc < 7) {
            #pragma unroll
            for (int j = 0; j < 3; j++)
                AregN[j] = __ldg((const float4*)(emb + (abase + a8) * 1024)
                                 + 64 + (kc + 1) * 24 + q8 * 3 + j);
        }
        CP_WAIT0();
        __syncthreads();   // B(kc)+A(kc) visible; all MMA(kc-1) done -> buffers kc+1 free
        if (kc < 7) {
            #pragma unroll
            for (int rr = 0; rr < 3; rr++) {
                int idx = tid + rr * 256;
                int row = idx >> 2, ch = idx & 3;
                cpa16(sb + bbufN + row * 80 + ch * 16,
                      d_PfT_h + row * 256 + (kc + 1) * 32 + ch * 8);
            }
            CP_COMMIT();
        }
        #pragma unroll
        for (int ks = 0; ks < 2; ks++) {
            u32 A[3][4];
            #pragma unroll
            for (int i = 0; i < 3; i++)
                ldsm4(A[i], sb + ebuf + i * 2560 +
                      2 * ((mw * 16 + arow) * 40 + ks * 16 + akq));
            #pragma unroll
            for (int nt = 0; nt < 6; nt++) {
                u32 Bh[2];
                int nbase = (nt >> 1) * 64 + uw * 16 + (nt & 1) * 8;
                u32 boff = 2 * ((nbase + brow) * 40 + ks * 16 + bkq);
                ldsm2(Bh, sb + bbuf + boff);
                #pragma unroll
                for (int i = 0; i < 3; i++)
                    mma16816(acc[i][nt], A[i], Bh);
            }
        }
        if (kc < 7) stageA(AregN, ebufN);
    }
    __syncthreads();

    // ============ rms -> cs ============
    smf[(SM_RSS >> 2) + tid] = rloc;
    __syncthreads();
    if (tid < 32) {
        const float* rp = smf + (SM_RSS >> 2);
        float s = 0.f;
        #pragma unroll
        for (int j = 0; j < 8; j++) s += rp[tid * 8 + j];
        float qr = rsqrtf(s * (1.f / 256.f) + 1e-6f);
        smf[(SM_CS >> 2) + tid] = qr * qr * qr * rsqrtf(24576.0f);
    }
    __syncthreads();

    // ============ det in registers -> raw chi to smem ============
    {
        #pragma unroll
        for (int eh = 0; eh < 2; eh++) {
            int r = mw * 16 + eh * 8 + (lane >> 2);
            float cs = smf[(SM_CS >> 2) + r];
            #pragma unroll
            for (int half = 0; half < 2; half++)
                #pragma unroll
                for (int el = 0; el < 2; el++) {
                    int e = eh * 2 + el;
                    int u = uw * 16 + half * 8 + (lane & 3) * 2 + el;
                    float ax = acc[0][half][e],     bx = acc[0][2 + half][e], cx = acc[0][4 + half][e];
                    float ay = acc[1][half][e],     by = acc[1][2 + half][e], cy = acc[1][4 + half][e];
                    float az = acc[2][half][e],     bz = acc[2][2 + half][e], cz = acc[2][4 + half][e];
                    float det = ax * (by * cz - bz * cy) + ay * (bz * cx - bx * cz)
                              + az * (bx * cy - by * cx);
                    smf[(SM_CHI >> 2) + r * CHI_STR + u] = cs * det;
                }
        }
    }
    __syncthreads();

    // ============ LN stats (apply deferred to epilogue) ============
    {
        int a = tid >> 3, ug = tid & 7;
        float ps = 0.f, pq = 0.f;
        #pragma unroll
        for (int uu = 0; uu < 8; uu++) {
            float c = smf[(SM_CHI >> 2) + a * CHI_STR + ug * 8 + uu];
            ps += c; pq += c * c;
        }
        smf[(SM_RSS >> 2) + tid] = ps;
        smf[(SM_RSS >> 2) + 256 + tid] = pq;
    }
    __syncthreads();
    if (tid < 32) {
        const float* rp = smf + (SM_RSS >> 2);
        float s = 0.f, q = 0.f;
        #pragma unroll
        for (int j = 0; j < 8; j++) { s += rp[tid * 8 + j]; q += rp[256 + tid * 8 + j]; }
        float mu = s * (1.f / 64.f);
        float var = fmaxf(q * (1.f / 64.f) - mu * mu, 0.f);
        smf[(SM_CS >> 2) + tid] = mu;
        smf[(SM_CS >> 2) + 64 + tid] = rsqrtf(var + 1e-5f);
    }

    // ============ gate phase ============
    {   // stage inv A [32][256] hi only
        const float4* src = (const float4*)(emb + (abase + a8) * 1024 + q8 * 32);
        #pragma unroll
        for (int jj = 0; jj < 4; jj++) {
            float4 v0 = __ldg(src + 2 * jj), v1 = __ldg(src + 2 * jj + 1);
            u32 hp0 = pk2h(v0.x, v0.y), hp1 = pk2h(v0.z, v0.w);
            u32 hp2 = pk2h(v1.x, v1.y), hp3 = pk2h(v1.z, v1.w);
            *(uint4*)(smc + SM_INVA + (u32)(a8 * INVA_STR + q8 * 32 + jj * 8) * 2) =
                make_uint4(hp0, hp1, hp2, hp3);
        }
    }
    // prologue B1 copy for (hc=0,kcb=0): 128 rows x 64 k
    {
        u32 bb = sb + SM_B1;
        #pragma unroll
        for (int rr = 0; rr < 4; rr++) {
            int idx = tid + rr * 256;
            int row = idx >> 3, ch = idx & 7;
            cpa16(bb + row * 144 + ch * 16, d_G1T_h + row * 256 + ch * 8);
        }
        CP_COMMIT();
    }

    const int gmw = w >> 2, gnw = w & 3;
    float g2acc[8][4];
    #pragma unroll
    for (int nt = 0; nt < 8; nt++)
        #pragma unroll
        for (int e = 0; e < 4; e++) g2acc[nt][e] = 0.f;

    for (int hc = 0; hc < 4; hc++) {
        float g1acc[4][4];
        #pragma unroll
        for (int nt = 0; nt < 4; nt++)
            #pragma unroll
            for (int e = 0; e < 4; e++) g1acc[nt][e] = 0.f;

        for (int kcb = 0; kcb < 4; kcb++) {    // k-chunks of 64
            int g = hc * 4 + kcb;
            CP_WAIT0();
            __syncthreads();
            bool did = false;
            if (g < 15) {
                int gn = g + 1;
                int nhc = gn >> 2, nkcb = gn & 3;
                u32 bb = sb + SM_B1 + (gn & 1) * 18432;
                #pragma unroll
                for (int rr = 0; rr < 4; rr++) {
                    int idx = tid + rr * 256;
                    int row = idx >> 3, ch = idx & 7;
                    cpa16(bb + row * 144 + ch * 16,
                          d_G1T_h + (nhc * 128 + row) * 256 + nkcb * 64 + ch * 8);
                }
                did = true;
            }
            if (kcb == 3) {
                #pragma unroll
                for (int rr = 0; rr < 4; rr++) {
                    int idx = tid + rr * 256;
                    int row = idx >> 4, ch = idx & 15;
                    cpa16(sb + SM_B2 + row * 272 + ch * 16,
                          d_G2T_h + row * 512 + hc * 128 + ch * 8);
                }
                did = true;
            }
            if (did) CP_COMMIT();
            u32 bb = sb + SM_B1 + (g & 1) * 18432;
            #pragma unroll
            for (int ks = 0; ks < 4; ks++) {
                u32 A[4];
                ldsm4(A, sb + SM_INVA +
                      2 * ((gmw * 16 + arow) * INVA_STR + kcb * 64 + ks * 16 + akq));
                #pragma unroll
                for (int nt = 0; nt < 4; nt++) {
                    u32 Bh[2];
                    u32 boff = (gnw * 32 + nt * 8 + brow) * 144 + (ks * 16 + bkq) * 2;
                    ldsm2(Bh, bb + boff);
                    mma16816(g1acc[nt], A, Bh);
                }
            }
        }
        // SiLU -> fp16 gate2 A fragments (covers B2 copy latency)
        u32 a2h[2][4];
        #pragma unroll
        for (int kt = 0; kt < 2; kt++)
            #pragma unroll
            for (int half = 0; half < 2; half++) {
                int nt = kt * 2 + half;
                int hb = hc * 128 + gnw * 32 + nt * 8 + (lane & 3) * 2;
                float b0 = __ldg(d_B1f + hb), b1 = __ldg(d_B1f + hb + 1);
                float s0 = silu(g1acc[nt][0] + b0);
                float s1 = silu(g1acc[nt][1] + b1);
                float s2 = silu(g1acc[nt][2] + b0);
                float s3 = silu(g1acc[nt][3] + b1);
                a2h[kt][half * 2]     = pk2h(s0, s1);
                a2h[kt][half * 2 + 1] = pk2h(s2, s3);
            }
        CP_WAIT0();
        __syncthreads();
        #pragma unroll
        for (int kt = 0; kt < 2; kt++)
            #pragma unroll
            for (int nt = 0; nt < 8; nt++) {
                u32 Bh[2];
                u32 boff = 2 * ((nt * 8 + brow) * 136 + gnw * 32 + kt * 16 + bkq);
                ldsm2(Bh, sb + SM_B2 + boff);
                mma16816(g2acc[nt], a2h[kt], Bh);
            }
    }
    // cross-warp reduction over gnw, then epilogue (LN applied here)
    __syncthreads();
    if (gnw != 0) {
        float* rp = smf + (SM_RED >> 2) + (((gnw - 1) * 2 + gmw) * 32 + lane) * 32;
        #pragma unroll
        for (int nt = 0; nt < 8; nt++)
            #pragma unroll
            for (int e = 0; e < 4; e++)
                rp[nt * 4 + e] = g2acc[nt][e];
    }
    __syncthreads();
    if (gnw == 0) {
        #pragma unroll
        for (int p = 0; p < 3; p++) {
            const float* rp = smf + (SM_RED >> 2) + ((p * 2 + gmw) * 32 + lane) * 32;
            #pragma unroll
            for (int nt = 0; nt < 8; nt++)
                #pragma unroll
                for (int e = 0; e < 4; e++)
                    g2acc[nt][e] += rp[nt * 4 + e];
        }
        #pragma unroll
        for (int nt = 0; nt < 8; nt++) {
            int r0 = gmw * 16 + (lane >> 2);
            int c0 = nt * 8 + (lane & 3) * 2;
            float b0 = __ldg(gb2 + c0), b1 = __ldg(gb2 + c0 + 1);
            float w0 = __ldg(lnw + c0), w1 = __ldg(lnw + c0 + 1);
            float z0 = __ldg(lnb + c0), z1 = __ldg(lnb + c0 + 1);
            float mu0 = smf[(SM_CS >> 2) + r0], is0 = smf[(SM_CS >> 2) + 64 + r0];
            float g0 = sigm(g2acc[nt][0] + b0);
            float g1 = sigm(g2acc[nt][1] + b1);
            float n0 = (smf[(SM_CHI >> 2) + r0 * CHI_STR + c0]     - mu0) * is0 * w0 + z0;
            float n1 = (smf[(SM_CHI >> 2) + r0 * CHI_STR + c0 + 1] - mu0) * is0 * w1 + z1;
            *(float2*)(outp + (abase + r0) * 64 + c0) = make_float2(g0 * n0, g1 * n1);
            int r1 = r0 + 8;
            float mu1 = smf[(SM_CS >> 2) + r1], is1 = smf[(SM_CS >> 2) + 64 + r1];
            float g2 = sigm(g2acc[nt][2] + b0);
            float g3 = sigm(g2acc[nt][3] + b1);
            float n2 = (smf[(SM_CHI >> 2) + r1 * CHI_STR + c0]     - mu1) * is1 * w0 + z0;
            float n3 = (smf[(SM_CHI >> 2) + r1 * CHI_STR + c0 + 1] - mu1) * is1 * w1 + z1;
            *(float2*)(outp + (abase + r1) * 64 + c0) = make_float2(g2 * n2, g3 * n3);
        }
    }
}

extern "C" void kernel_launch(void* const* d_in, const int* in_sizes, int n_in,
                              void* d_out, int out_size) {
    const float* emb  = (const float*)d_in[0];
    const float* mean = (const float*)d_in[1];
    const float* stdv = (const float*)d_in[2];
    const float* gam  = (const float*)d_in[3];
    const float* W0   = (const float*)d_in[4];
    const float* W1   = (const float*)d_in[5];
    const float* W2   = (const float*)d_in[6];
    const float* wc   = (const float*)d_in[7];
    const float* wd   = (const float*)d_in[8];
    const float* lnw  = (const float*)d_in[9];
    const float* lnb  = (const float*)d_in[10];
    const float* gw1  = (const float*)d_in[11];
    const float* gb1  = (const float*)d_in[12];
    const float* gw2  = (const float*)d_in[13];
    const float* gb2  = (const float*)d_in[14];
    float* out = (float*)d_out;

    prep_pf<<<192, 256>>>(gam, W0, W1, W2, wc, wd);
    prep_g1<<<512, 256>>>(gw1, stdv);
    prep_g2<<<64, 512>>>(gw2);
    prep_b1<<<512, 256>>>(gw1, gb1, mean, stdv);

    cudaFuncSetAttribute(chiral_tc, cudaFuncAttributeMaxDynamicSharedMemorySize, SM_BYTES);
    chiral_tc<<<131072 / ATOMS, NT, SM_BYTES>>>(emb, lnw, lnb, gb2, out);
}